// round 2
// baseline (speedup 1.0000x reference)
#include <cuda_runtime.h>
#include <cuda_bf16.h>
#include <math.h>

// Problem constants
#define BB 1
#define HH 64
#define WW 64
#define CC 256
#define HEADS 8
#define HD 32
#define KK 7
#define DIL 2
#define FF 1024
#define NTOK (HH*WW)            // 4096
#define SCALE 0.17677669529663687f  // 1/sqrt(32)

// ---------------- scratch (device globals; no runtime alloc) ----------------
__device__ float g_hs  [NTOK*CC];      // LN1(x)
__device__ float g_qkv [NTOK*3*CC];    // [tok][q|k|v] concatenated
__device__ float g_ctx [NTOK*CC];      // attention context
__device__ float g_hs2 [NTOK*CC];      // x + attn_out
__device__ float g_y   [NTOK*CC];      // LN2(hs2)
__device__ float g_t   [NTOK*FF];      // gelu(y@w1+b1)
__device__ float g_wqkv[CC*3*CC];      // packed [256][768]
__device__ float g_bqkv[3*CC];

__device__ __forceinline__ float4 ld4(const float* p) {
    return *reinterpret_cast<const float4*>(p);
}

// ---------------- weight pack: wq|wk|wv -> [256][768] ----------------
__global__ void pack_kernel(const float* __restrict__ wq, const float* __restrict__ wk,
                            const float* __restrict__ wv, const float* __restrict__ bq,
                            const float* __restrict__ bk, const float* __restrict__ bv)
{
    int idx = blockIdx.x * 256 + threadIdx.x;
    if (idx < CC*3*CC) {
        int r = idx / (3*CC), c = idx % (3*CC);
        float v;
        if      (c < CC)   v = wq[r*CC + c];
        else if (c < 2*CC) v = wk[r*CC + (c - CC)];
        else               v = wv[r*CC + (c - 2*CC)];
        g_wqkv[idx] = v;
    }
    if (idx < 3*CC) {
        float v;
        if      (idx < CC)   v = bq[idx];
        else if (idx < 2*CC) v = bk[idx - CC];
        else                 v = bv[idx - 2*CC];
        g_bqkv[idx] = v;
    }
}

// ---------------- LayerNorm: one block per row, 256 threads ----------------
__global__ void ln_kernel(const float* __restrict__ x, const float* __restrict__ g,
                          const float* __restrict__ b, float* __restrict__ out)
{
    int row = blockIdx.x;
    int c   = threadIdx.x;       // 0..255
    float v = x[row*CC + c];
    float s = v, sq = v*v;
    #pragma unroll
    for (int o = 16; o; o >>= 1) {
        s  += __shfl_xor_sync(0xffffffffu, s,  o);
        sq += __shfl_xor_sync(0xffffffffu, sq, o);
    }
    __shared__ float rs[8], rq[8];
    int w = c >> 5, l = c & 31;
    if (l == 0) { rs[w] = s; rq[w] = sq; }
    __syncthreads();
    if (w == 0) {
        float ss = (l < 8) ? rs[l] : 0.f;
        float qq = (l < 8) ? rq[l] : 0.f;
        #pragma unroll
        for (int o = 16; o; o >>= 1) {
            ss += __shfl_xor_sync(0xffffffffu, ss, o);
            qq += __shfl_xor_sync(0xffffffffu, qq, o);
        }
        if (l == 0) { rs[0] = ss; rq[0] = qq; }
    }
    __syncthreads();
    float mean = rs[0] * (1.0f/CC);
    float var  = rq[0] * (1.0f/CC) - mean*mean;
    float inv  = rsqrtf(var + 1e-5f);
    out[row*CC + c] = (v - mean) * inv * g[c] + b[c];
}

// ---------------- SGEMM: C[M,N] = A[M,K] @ W[K,N] (+ epilogue) --------------
// 128x64 block tile, BK=16, 256 threads, 8x4 microtile, double-buffered smem,
// transposed-A staging for vectorized fragment loads.
// EPI 0: +bias ; EPI 1: gelu(+bias) exact ; EPI 2: +bias + res
#define BM 128
#define BN 64
#define BKT 16
#define ASTR 132   // padded stride for As[k][m]

template<int EPI>
__global__ void __launch_bounds__(256, 2)
sgemm_kernel(const float* __restrict__ A, const float* __restrict__ W,
             const float* __restrict__ bias, const float* __restrict__ res,
             float* __restrict__ C, int M, int N, int K)
{
    __shared__ float As[2][BKT][ASTR];   // [buf][k][m]
    __shared__ float Bs[2][BKT][BN];     // [buf][k][n]

    const int tid = threadIdx.x;
    const int bm = blockIdx.y * BM, bn = blockIdx.x * BN;
    const int tm = tid & 15;             // m-group (8 rows)
    const int tn = tid >> 4;             // n-group (4 cols)

    // A tile load mapping: thread -> (row, 8 consecutive k)
    const int arow = tid >> 1;           // 0..127
    const int akq  = (tid & 1) * 8;      // k offset 0 or 8
    // B tile load mapping: thread -> (k row, 4 consecutive n)
    const int brow = tid >> 4;           // 0..15
    const int bcol = (tid & 15) * 4;

    const float* Ag = A + (size_t)(bm + arow) * K + akq;
    const float* Bg = W + (size_t)brow * N + bn + bcol;

    float acc[8][4];
    #pragma unroll
    for (int i = 0; i < 8; i++)
        #pragma unroll
        for (int j = 0; j < 4; j++) acc[i][j] = 0.f;

    // prologue: stage 0
    float4 pa0 = ld4(Ag);
    float4 pa1 = ld4(Ag + 4);
    float4 pb  = ld4(Bg);
    {
        float* a0 = (float*)&pa0; float* a1 = (float*)&pa1;
        #pragma unroll
        for (int c = 0; c < 4; c++) {
            As[0][akq + c][arow]     = a0[c];
            As[0][akq + 4 + c][arow] = a1[c];
        }
        *reinterpret_cast<float4*>(&Bs[0][brow][bcol]) = pb;
    }
    __syncthreads();

    int buf = 0;
    for (int k0 = BKT; k0 <= K; k0 += BKT) {
        if (k0 < K) {
            pa0 = ld4(Ag + k0);
            pa1 = ld4(Ag + k0 + 4);
            pb  = ld4(Bg + (size_t)k0 * N);
        }
        #pragma unroll
        for (int kk = 0; kk < BKT; kk++) {
            float4 a0 = ld4(&As[buf][kk][tm*8]);
            float4 a1 = ld4(&As[buf][kk][tm*8 + 4]);
            float4 b  = ld4(&Bs[buf][kk][tn*4]);
            float av[8] = {a0.x,a0.y,a0.z,a0.w,a1.x,a1.y,a1.z,a1.w};
            float bv[4] = {b.x,b.y,b.z,b.w};
            #pragma unroll
            for (int i = 0; i < 8; i++)
                #pragma unroll
                for (int j = 0; j < 4; j++)
                    acc[i][j] = fmaf(av[i], bv[j], acc[i][j]);
        }
        if (k0 < K) {
            int nb = buf ^ 1;
            float* a0 = (float*)&pa0; float* a1 = (float*)&pa1;
            #pragma unroll
            for (int c = 0; c < 4; c++) {
                As[nb][akq + c][arow]     = a0[c];
                As[nb][akq + 4 + c][arow] = a1[c];
            }
            *reinterpret_cast<float4*>(&Bs[nb][brow][bcol]) = pb;
            buf = nb;
        }
        __syncthreads();
    }

    // epilogue
    const int coln = bn + tn*4;
    float4 bvec = ld4(bias + coln);
    #pragma unroll
    for (int i = 0; i < 8; i++) {
        int row = bm + tm*8 + i;
        float v0 = acc[i][0] + bvec.x;
        float v1 = acc[i][1] + bvec.y;
        float v2 = acc[i][2] + bvec.z;
        float v3 = acc[i][3] + bvec.w;
        if (EPI == 1) {
            v0 *= normcdff(v0); v1 *= normcdff(v1);
            v2 *= normcdff(v2); v3 *= normcdff(v3);
        } else if (EPI == 2) {
            float4 r = ld4(res + (size_t)row * N + coln);
            v0 += r.x; v1 += r.y; v2 += r.z; v3 += r.w;
        }
        float4 o = make_float4(v0, v1, v2, v3);
        *reinterpret_cast<float4*>(C + (size_t)row * N + coln) = o;
    }
}

// ---------------- dilated neighborhood attention ----------------
// one warp per (token, head); warp split into 4 groups of 8 lanes.
// group g handles neighbor n = t*4+g; lane e within group owns channel quad e.
__global__ void attn_kernel(const float* __restrict__ qkv, const float* __restrict__ rpb,
                            float* __restrict__ ctx)
{
    __shared__ float sc[HEADS][52];
    const int tok  = blockIdx.x;
    const int head = threadIdx.y;
    const int lane = threadIdx.x;
    const int g = lane >> 3, e = lane & 7;
    const int i = tok >> 6, j = tok & 63;

    // clamped dilated-window starts (L=64, k=7, d=2 -> lg=32, max start=25)
    int gi = i >> 1, ri = i & 1;
    int si = gi - 3; si = si < 0 ? 0 : (si > 25 ? 25 : si);
    int gj = j >> 1, rj = j & 1;
    int sj = gj - 3; sj = sj < 0 ? 0 : (sj > 25 ? 25 : sj);
    const int bhi = si - gi + 6;
    const int bwj = sj - gj + 6;

    const int choff = head*HD + e*4;
    float4 q4 = ld4(qkv + (size_t)tok*(3*CC) + choff);
    q4.x *= SCALE; q4.y *= SCALE; q4.z *= SCALE; q4.w *= SCALE;
    const float* biasrow = rpb + head*169;   // 13*13

    // pass 1: scores (4 neighbors in flight per warp iteration)
    #pragma unroll
    for (int t = 0; t < 13; t++) {
        int n = t*4 + g;
        bool valid = n < 49;
        float partial = 0.f;
        int kh = 0, kw = 0;
        if (valid) {
            kh = (n*586) >> 12;      // n/7 for n<49
            kw = n - kh*7;
            int ki = (si + kh)*2 + ri;
            int kj = (sj + kw)*2 + rj;
            int nt = ki*WW + kj;
            float4 k4 = ld4(qkv + (size_t)nt*(3*CC) + CC + choff);
            partial = q4.x*k4.x + q4.y*k4.y + q4.z*k4.z + q4.w*k4.w;
        }
        partial += __shfl_xor_sync(0xffffffffu, partial, 1);
        partial += __shfl_xor_sync(0xffffffffu, partial, 2);
        partial += __shfl_xor_sync(0xffffffffu, partial, 4);
        if (valid && e == 0)
            sc[head][n] = partial + biasrow[(bhi + kh)*13 + (bwj + kw)];
    }
    __syncwarp();

    // softmax over 49 entries
    float s1 = sc[head][lane];                             // lane < 49 always
    float s2 = (lane < 17) ? sc[head][lane + 32] : -1e30f;
    float m = fmaxf(s1, s2);
    #pragma unroll
    for (int o = 16; o; o >>= 1) m = fmaxf(m, __shfl_xor_sync(0xffffffffu, m, o));
    float e1 = __expf(s1 - m);
    float e2 = (lane < 17) ? __expf(s2 - m) : 0.f;
    float ssum = e1 + e2;
    #pragma unroll
    for (int o = 16; o; o >>= 1) ssum += __shfl_xor_sync(0xffffffffu, ssum, o);
    sc[head][lane] = e1;
    if (lane < 17) sc[head][lane + 32] = e2;
    __syncwarp();
    const float inv = 1.0f / ssum;

    // pass 2: weighted V
    float4 a = make_float4(0.f, 0.f, 0.f, 0.f);
    #pragma unroll
    for (int t = 0; t < 13; t++) {
        int n = t*4 + g;
        if (n < 49) {
            int kh = (n*586) >> 12;
            int kw = n - kh*7;
            int ki = (si + kh)*2 + ri;
            int kj = (sj + kw)*2 + rj;
            int nt = ki*WW + kj;
            float w = sc[head][n];
            float4 v4 = ld4(qkv + (size_t)nt*(3*CC) + 2*CC + choff);
            a.x = fmaf(w, v4.x, a.x);
            a.y = fmaf(w, v4.y, a.y);
            a.z = fmaf(w, v4.z, a.z);
            a.w = fmaf(w, v4.w, a.w);
        }
    }
    // reduce across the 4 groups (lanes ±8, ±16 hold same channel quad)
    #pragma unroll
    for (int o = 8; o <= 16; o <<= 1) {
        a.x += __shfl_xor_sync(0xffffffffu, a.x, o);
        a.y += __shfl_xor_sync(0xffffffffu, a.y, o);
        a.z += __shfl_xor_sync(0xffffffffu, a.z, o);
        a.w += __shfl_xor_sync(0xffffffffu, a.w, o);
    }
    if (g == 0) {
        float4 o4 = make_float4(a.x*inv, a.y*inv, a.z*inv, a.w*inv);
        *reinterpret_cast<float4*>(ctx + (size_t)tok*CC + choff) = o4;
    }
}

// ---------------- launch ----------------
extern "C" void kernel_launch(void* const* d_in, const int* in_sizes, int n_in,
                              void* d_out, int out_size)
{
    const float* x     = (const float*)d_in[0];
    const float* ln1_g = (const float*)d_in[1];
    const float* ln1_b = (const float*)d_in[2];
    const float* wq    = (const float*)d_in[3];
    const float* bq    = (const float*)d_in[4];
    const float* wk    = (const float*)d_in[5];
    const float* bk    = (const float*)d_in[6];
    const float* wv    = (const float*)d_in[7];
    const float* bv    = (const float*)d_in[8];
    const float* rpb   = (const float*)d_in[9];
    const float* wo    = (const float*)d_in[10];
    const float* bo    = (const float*)d_in[11];
    const float* ln2_g = (const float*)d_in[12];
    const float* ln2_b = (const float*)d_in[13];
    const float* w1    = (const float*)d_in[14];
    const float* b1    = (const float*)d_in[15];
    const float* w2    = (const float*)d_in[16];
    const float* b2    = (const float*)d_in[17];
    float* out = (float*)d_out;

    float *hs, *qkv, *ctx, *hs2, *y, *t, *wqkv, *bqkv;
    cudaGetSymbolAddress((void**)&hs,   g_hs);
    cudaGetSymbolAddress((void**)&qkv,  g_qkv);
    cudaGetSymbolAddress((void**)&ctx,  g_ctx);
    cudaGetSymbolAddress((void**)&hs2,  g_hs2);
    cudaGetSymbolAddress((void**)&y,    g_y);
    cudaGetSymbolAddress((void**)&t,    g_t);
    cudaGetSymbolAddress((void**)&wqkv, g_wqkv);
    cudaGetSymbolAddress((void**)&bqkv, g_bqkv);

    // 1) pack qkv weights
    pack_kernel<<<(CC*3*CC + 255)/256, 256>>>(wq, wk, wv, bq, bk, bv);

    // 2) LN1
    ln_kernel<<<NTOK, CC>>>(x, ln1_g, ln1_b, hs);

    // 3) QKV GEMM: [4096,256] @ [256,768]
    {
        dim3 grid((3*CC)/BN, NTOK/BM);
        sgemm_kernel<0><<<grid, 256>>>(hs, wqkv, bqkv, nullptr, qkv, NTOK, 3*CC, CC);
    }

    // 4) attention
    {
        dim3 blk(32, HEADS);
        attn_kernel<<<NTOK, blk>>>(qkv, rpb, ctx);
    }

    // 5) wo GEMM + residual(x): hs2 = ctx@wo + bo + x
    {
        dim3 grid(CC/BN, NTOK/BM);
        sgemm_kernel<2><<<grid, 256>>>(ctx, wo, bo, x, hs2, NTOK, CC, CC);
    }

    // 6) LN2
    ln_kernel<<<NTOK, CC>>>(hs2, ln2_g, ln2_b, y);

    // 7) w1 GEMM + exact GELU: t = gelu(y@w1 + b1)
    {
        dim3 grid(FF/BN, NTOK/BM);
        sgemm_kernel<1><<<grid, 256>>>(y, w1, b1, nullptr, t, NTOK, FF, CC);
    }

    // 8) w2 GEMM + residual(hs2): out = t@w2 + b2 + hs2
    {
        dim3 grid(CC/BN, NTOK/BM);
        sgemm_kernel<2><<<grid, 256>>>(t, w2, b2, hs2, out, NTOK, CC, FF);
    }
}

// round 3
// speedup vs baseline: 2.0021x; 2.0021x over previous
#include <cuda_runtime.h>
#include <cuda_bf16.h>
#include <math.h>
#include <stdint.h>

// Problem constants
#define BB 1
#define HH 64
#define WW 64
#define CC 256
#define HEADS 8
#define HD 32
#define KK 7
#define DIL 2
#define FF 1024
#define NTOK (HH*WW)            // 4096
#define SCALE 0.17677669529663687f  // 1/sqrt(32)

// ---------------- scratch (device globals; no runtime alloc) ----------------
__device__ float g_hs  [NTOK*CC];      // LN1(x)
__device__ float g_qkv [NTOK*3*CC];    // [tok][q|k|v] concatenated
__device__ float g_ctx [NTOK*CC];      // attention context
__device__ float g_hs2 [NTOK*CC];      // x + attn_out
__device__ float g_y   [NTOK*CC];      // LN2(hs2)
__device__ float g_t   [NTOK*FF];      // gelu(y@w1+b1)
__device__ float g_wqkv[CC*3*CC];      // packed [256][768]
__device__ float g_bqkv[3*CC];

__device__ __forceinline__ float4 ld4(const float* p) {
    return *reinterpret_cast<const float4*>(p);
}

__device__ __forceinline__ uint32_t f2tf(float f) {
    uint32_t u;
    asm("cvt.rna.tf32.f32 %0, %1;" : "=r"(u) : "f"(f));
    return u;
}

__device__ __forceinline__ void mma_tf32(float (&d)[4], const uint32_t (&a)[4],
                                         const uint32_t (&b)[2]) {
    asm volatile(
        "mma.sync.aligned.m16n8k8.row.col.f32.tf32.tf32.f32 "
        "{%0,%1,%2,%3}, {%4,%5,%6,%7}, {%8,%9}, {%0,%1,%2,%3};\n"
        : "+f"(d[0]), "+f"(d[1]), "+f"(d[2]), "+f"(d[3])
        : "r"(a[0]), "r"(a[1]), "r"(a[2]), "r"(a[3]),
          "r"(b[0]), "r"(b[1]));
}

// ---------------- weight pack: wq|wk|wv -> [256][768] ----------------
__global__ void pack_kernel(const float* __restrict__ wq, const float* __restrict__ wk,
                            const float* __restrict__ wv, const float* __restrict__ bq,
                            const float* __restrict__ bk, const float* __restrict__ bv)
{
    int idx = blockIdx.x * 256 + threadIdx.x;
    if (idx < CC*3*CC) {
        int r = idx / (3*CC), c = idx % (3*CC);
        float v;
        if      (c < CC)   v = wq[r*CC + c];
        else if (c < 2*CC) v = wk[r*CC + (c - CC)];
        else               v = wv[r*CC + (c - 2*CC)];
        g_wqkv[idx] = v;
    }
    if (idx < 3*CC) {
        float v;
        if      (idx < CC)   v = bq[idx];
        else if (idx < 2*CC) v = bk[idx - CC];
        else                 v = bv[idx - 2*CC];
        g_bqkv[idx] = v;
    }
}

// ---------------- LayerNorm: one block per row, 256 threads ----------------
__global__ void ln_kernel(const float* __restrict__ x, const float* __restrict__ g,
                          const float* __restrict__ b, float* __restrict__ out)
{
    int row = blockIdx.x;
    int c   = threadIdx.x;       // 0..255
    float v = x[row*CC + c];
    float s = v, sq = v*v;
    #pragma unroll
    for (int o = 16; o; o >>= 1) {
        s  += __shfl_xor_sync(0xffffffffu, s,  o);
        sq += __shfl_xor_sync(0xffffffffu, sq, o);
    }
    __shared__ float rs[8], rq[8];
    int w = c >> 5, l = c & 31;
    if (l == 0) { rs[w] = s; rq[w] = sq; }
    __syncthreads();
    if (w == 0) {
        float ss = (l < 8) ? rs[l] : 0.f;
        float qq = (l < 8) ? rq[l] : 0.f;
        #pragma unroll
        for (int o = 16; o; o >>= 1) {
            ss += __shfl_xor_sync(0xffffffffu, ss, o);
            qq += __shfl_xor_sync(0xffffffffu, qq, o);
        }
        if (l == 0) { rs[0] = ss; rq[0] = qq; }
    }
    __syncthreads();
    float mean = rs[0] * (1.0f/CC);
    float var  = rq[0] * (1.0f/CC) - mean*mean;
    float inv  = rsqrtf(var + 1e-5f);
    out[row*CC + c] = (v - mean) * inv * g[c] + b[c];
}

// ---------------- TF32 tensor-core GEMM ----------------
// C[M,N] = A[M,K] @ W[K,N] (+ epilogue), A/W fp32 in, tf32(rna) in smem.
// Block 128x64, BK=16, 256 thr = 8 warps (4 M x 2 N), warp tile 32x32
// (2x4 m16n8k8 frags). Double-buffered smem, register-staged global loads.
// Smem strides: A=20 (bank 20g+c distinct), B=72 (bank 8c+g distinct).
// EPI 0: +bias ; EPI 1: gelu(+bias) exact ; EPI 2: +bias + res
#define ASTR 20
#define BSTR 72

template<int EPI>
__global__ void __launch_bounds__(256, 2)
tgemm_kernel(const float* __restrict__ A, const float* __restrict__ W,
             const float* __restrict__ bias, const float* __restrict__ res,
             float* __restrict__ C, int M, int N, int K)
{
    __shared__ uint32_t As[2][128][ASTR];   // [buf][m][k]
    __shared__ uint32_t Bs[2][16][BSTR];    // [buf][k][n]

    const int tid  = threadIdx.x;
    const int lane = tid & 31, warp = tid >> 5;
    const int wm = warp & 3, wn = warp >> 2;       // warp tile origin
    const int g = lane >> 2, c = lane & 3;         // mma lane decomposition
    const int bm = blockIdx.y * 128, bn = blockIdx.x * 64;

    // global load mapping
    const int arow = tid >> 1, akq = (tid & 1) * 8;    // A: 8 floats/thread
    const int brow = tid >> 4, bcol = (tid & 15) * 4;  // B: 4 floats/thread
    const float* Ag = A + (size_t)(bm + arow) * K + akq;
    const float* Bg = W + (size_t)brow * N + bn + bcol;

    float acc[2][4][4];
    #pragma unroll
    for (int mf = 0; mf < 2; mf++)
        #pragma unroll
        for (int nf = 0; nf < 4; nf++)
            #pragma unroll
            for (int e = 0; e < 4; e++) acc[mf][nf][e] = 0.f;

    // prologue: stage tile 0
    float4 pa0 = ld4(Ag);
    float4 pa1 = ld4(Ag + 4);
    float4 pb  = ld4(Bg);
    {
        uint4 ua = make_uint4(f2tf(pa0.x), f2tf(pa0.y), f2tf(pa0.z), f2tf(pa0.w));
        uint4 ub = make_uint4(f2tf(pa1.x), f2tf(pa1.y), f2tf(pa1.z), f2tf(pa1.w));
        *reinterpret_cast<uint4*>(&As[0][arow][akq])     = ua;
        *reinterpret_cast<uint4*>(&As[0][arow][akq + 4]) = ub;
        uint4 uc = make_uint4(f2tf(pb.x), f2tf(pb.y), f2tf(pb.z), f2tf(pb.w));
        *reinterpret_cast<uint4*>(&Bs[0][brow][bcol]) = uc;
    }
    __syncthreads();

    const int NT = K / 16;
    int buf = 0;
    for (int kt = 0; kt < NT; kt++) {
        if (kt + 1 < NT) {
            pa0 = ld4(Ag + (kt + 1) * 16);
            pa1 = ld4(Ag + (kt + 1) * 16 + 4);
            pb  = ld4(Bg + (size_t)(kt + 1) * 16 * N);
        }
        #pragma unroll
        for (int ks = 0; ks < 16; ks += 8) {
            uint32_t af[2][4], bf[4][2];
            #pragma unroll
            for (int mf = 0; mf < 2; mf++) {
                int rb = wm * 32 + mf * 16;
                af[mf][0] = As[buf][rb + g][ks + c];
                af[mf][1] = As[buf][rb + g + 8][ks + c];
                af[mf][2] = As[buf][rb + g][ks + c + 4];
                af[mf][3] = As[buf][rb + g + 8][ks + c + 4];
            }
            #pragma unroll
            for (int nf = 0; nf < 4; nf++) {
                int nb = wn * 32 + nf * 8 + g;
                bf[nf][0] = Bs[buf][ks + c][nb];
                bf[nf][1] = Bs[buf][ks + c + 4][nb];
            }
            #pragma unroll
            for (int mf = 0; mf < 2; mf++)
                #pragma unroll
                for (int nf = 0; nf < 4; nf++)
                    mma_tf32(acc[mf][nf], af[mf], bf[nf]);
        }
        if (kt + 1 < NT) {
            int nb = buf ^ 1;
            uint4 ua = make_uint4(f2tf(pa0.x), f2tf(pa0.y), f2tf(pa0.z), f2tf(pa0.w));
            uint4 ub = make_uint4(f2tf(pa1.x), f2tf(pa1.y), f2tf(pa1.z), f2tf(pa1.w));
            *reinterpret_cast<uint4*>(&As[nb][arow][akq])     = ua;
            *reinterpret_cast<uint4*>(&As[nb][arow][akq + 4]) = ub;
            uint4 uc = make_uint4(f2tf(pb.x), f2tf(pb.y), f2tf(pb.z), f2tf(pb.w));
            *reinterpret_cast<uint4*>(&Bs[nb][brow][bcol]) = uc;
        }
        __syncthreads();
        buf ^= 1;
    }

    // epilogue: each (mf,nf) frag -> two float2 stores (rows g and g+8)
    #pragma unroll
    for (int mf = 0; mf < 2; mf++) {
        #pragma unroll
        for (int nf = 0; nf < 4; nf++) {
            int row0 = bm + wm * 32 + mf * 16 + g;
            int col  = bn + wn * 32 + nf * 8 + c * 2;
            float bx = bias[col], by = bias[col + 1];
            #pragma unroll
            for (int h = 0; h < 2; h++) {
                int row = row0 + h * 8;
                float v0 = acc[mf][nf][h * 2 + 0] + bx;
                float v1 = acc[mf][nf][h * 2 + 1] + by;
                if (EPI == 1) {
                    v0 *= normcdff(v0);
                    v1 *= normcdff(v1);
                } else if (EPI == 2) {
                    float2 r = *reinterpret_cast<const float2*>(res + (size_t)row * N + col);
                    v0 += r.x; v1 += r.y;
                }
                *reinterpret_cast<float2*>(C + (size_t)row * N + col) = make_float2(v0, v1);
            }
        }
    }
}

// ---------------- dilated neighborhood attention ----------------
// one warp per (token, head); warp split into 4 groups of 8 lanes.
__global__ void attn_kernel(const float* __restrict__ qkv, const float* __restrict__ rpb,
                            float* __restrict__ ctx)
{
    __shared__ float sc[HEADS][52];
    const int tok  = blockIdx.x;
    const int head = threadIdx.y;
    const int lane = threadIdx.x;
    const int g = lane >> 3, e = lane & 7;
    const int i = tok >> 6, j = tok & 63;

    int gi = i >> 1, ri = i & 1;
    int si = gi - 3; si = si < 0 ? 0 : (si > 25 ? 25 : si);
    int gj = j >> 1, rj = j & 1;
    int sj = gj - 3; sj = sj < 0 ? 0 : (sj > 25 ? 25 : sj);
    const int bhi = si - gi + 6;
    const int bwj = sj - gj + 6;

    const int choff = head*HD + e*4;
    float4 q4 = ld4(qkv + (size_t)tok*(3*CC) + choff);
    q4.x *= SCALE; q4.y *= SCALE; q4.z *= SCALE; q4.w *= SCALE;
    const float* biasrow = rpb + head*169;   // 13*13

    #pragma unroll
    for (int t = 0; t < 13; t++) {
        int n = t*4 + g;
        bool valid = n < 49;
        float partial = 0.f;
        int kh = 0, kw = 0;
        if (valid) {
            kh = (n*586) >> 12;      // n/7 for n<49
            kw = n - kh*7;
            int ki = (si + kh)*2 + ri;
            int kj = (sj + kw)*2 + rj;
            int nt = ki*WW + kj;
            float4 k4 = ld4(qkv + (size_t)nt*(3*CC) + CC + choff);
            partial = q4.x*k4.x + q4.y*k4.y + q4.z*k4.z + q4.w*k4.w;
        }
        partial += __shfl_xor_sync(0xffffffffu, partial, 1);
        partial += __shfl_xor_sync(0xffffffffu, partial, 2);
        partial += __shfl_xor_sync(0xffffffffu, partial, 4);
        if (valid && e == 0)
            sc[head][n] = partial + biasrow[(bhi + kh)*13 + (bwj + kw)];
    }
    __syncwarp();

    float s1 = sc[head][lane];
    float s2 = (lane < 17) ? sc[head][lane + 32] : -1e30f;
    float m = fmaxf(s1, s2);
    #pragma unroll
    for (int o = 16; o; o >>= 1) m = fmaxf(m, __shfl_xor_sync(0xffffffffu, m, o));
    float e1 = __expf(s1 - m);
    float e2 = (lane < 17) ? __expf(s2 - m) : 0.f;
    float ssum = e1 + e2;
    #pragma unroll
    for (int o = 16; o; o >>= 1) ssum += __shfl_xor_sync(0xffffffffu, ssum, o);
    sc[head][lane] = e1;
    if (lane < 17) sc[head][lane + 32] = e2;
    __syncwarp();
    const float inv = 1.0f / ssum;

    float4 a = make_float4(0.f, 0.f, 0.f, 0.f);
    #pragma unroll
    for (int t = 0; t < 13; t++) {
        int n = t*4 + g;
        if (n < 49) {
            int kh = (n*586) >> 12;
            int kw = n - kh*7;
            int ki = (si + kh)*2 + ri;
            int kj = (sj + kw)*2 + rj;
            int nt = ki*WW + kj;
            float w = sc[head][n];
            float4 v4 = ld4(qkv + (size_t)nt*(3*CC) + 2*CC + choff);
            a.x = fmaf(w, v4.x, a.x);
            a.y = fmaf(w, v4.y, a.y);
            a.z = fmaf(w, v4.z, a.z);
            a.w = fmaf(w, v4.w, a.w);
        }
    }
    #pragma unroll
    for (int o = 8; o <= 16; o <<= 1) {
        a.x += __shfl_xor_sync(0xffffffffu, a.x, o);
        a.y += __shfl_xor_sync(0xffffffffu, a.y, o);
        a.z += __shfl_xor_sync(0xffffffffu, a.z, o);
        a.w += __shfl_xor_sync(0xffffffffu, a.w, o);
    }
    if (g == 0) {
        float4 o4 = make_float4(a.x*inv, a.y*inv, a.z*inv, a.w*inv);
        *reinterpret_cast<float4*>(ctx + (size_t)tok*CC + choff) = o4;
    }
}

// ---------------- launch ----------------
extern "C" void kernel_launch(void* const* d_in, const int* in_sizes, int n_in,
                              void* d_out, int out_size)
{
    const float* x     = (const float*)d_in[0];
    const float* ln1_g = (const float*)d_in[1];
    const float* ln1_b = (const float*)d_in[2];
    const float* wq    = (const float*)d_in[3];
    const float* bq    = (const float*)d_in[4];
    const float* wk    = (const float*)d_in[5];
    const float* bk    = (const float*)d_in[6];
    const float* wv    = (const float*)d_in[7];
    const float* bv    = (const float*)d_in[8];
    const float* rpb   = (const float*)d_in[9];
    const float* wo    = (const float*)d_in[10];
    const float* bo    = (const float*)d_in[11];
    const float* ln2_g = (const float*)d_in[12];
    const float* ln2_b = (const float*)d_in[13];
    const float* w1    = (const float*)d_in[14];
    const float* b1    = (const float*)d_in[15];
    const float* w2    = (const float*)d_in[16];
    const float* b2    = (const float*)d_in[17];
    float* out = (float*)d_out;

    float *hs, *qkv, *ctx, *hs2, *y, *t, *wqkv, *bqkv;
    cudaGetSymbolAddress((void**)&hs,   g_hs);
    cudaGetSymbolAddress((void**)&qkv,  g_qkv);
    cudaGetSymbolAddress((void**)&ctx,  g_ctx);
    cudaGetSymbolAddress((void**)&hs2,  g_hs2);
    cudaGetSymbolAddress((void**)&y,    g_y);
    cudaGetSymbolAddress((void**)&t,    g_t);
    cudaGetSymbolAddress((void**)&wqkv, g_wqkv);
    cudaGetSymbolAddress((void**)&bqkv, g_bqkv);

    // 1) pack qkv weights
    pack_kernel<<<(CC*3*CC + 255)/256, 256>>>(wq, wk, wv, bq, bk, bv);

    // 2) LN1
    ln_kernel<<<NTOK, CC>>>(x, ln1_g, ln1_b, hs);

    // 3) QKV GEMM: [4096,256] @ [256,768]
    {
        dim3 grid((3*CC)/64, NTOK/128);
        tgemm_kernel<0><<<grid, 256>>>(hs, wqkv, bqkv, nullptr, qkv, NTOK, 3*CC, CC);
    }

    // 4) attention
    {
        dim3 blk(32, HEADS);
        attn_kernel<<<NTOK, blk>>>(qkv, rpb, ctx);
    }

    // 5) wo GEMM + residual(x): hs2 = ctx@wo + bo + x
    {
        dim3 grid(CC/64, NTOK/128);
        tgemm_kernel<2><<<grid, 256>>>(ctx, wo, bo, x, hs2, NTOK, CC, CC);
    }

    // 6) LN2
    ln_kernel<<<NTOK, CC>>>(hs2, ln2_g, ln2_b, y);

    // 7) w1 GEMM + exact GELU: t = gelu(y@w1 + b1)
    {
        dim3 grid(FF/64, NTOK/128);
        tgemm_kernel<1><<<grid, 256>>>(y, w1, b1, nullptr, t, NTOK, FF, CC);
    }

    // 8) w2 GEMM + residual(hs2): out = t@w2 + b2 + hs2
    {
        dim3 grid(CC/64, NTOK/128);
        tgemm_kernel<2><<<grid, 256>>>(t, w2, b2, hs2, out, NTOK, CC, FF);
    }
}

// round 4
// speedup vs baseline: 2.8734x; 1.4352x over previous
#include <cuda_runtime.h>
#include <cuda_bf16.h>
#include <math.h>
#include <stdint.h>

// Problem constants
#define BB 1
#define HH 64
#define WW 64
#define CC 256
#define HEADS 8
#define HD 32
#define KK 7
#define DIL 2
#define FF 1024
#define NTOK (HH*WW)            // 4096
#define SCALE 0.17677669529663687f  // 1/sqrt(32)

// ---------------- scratch (device globals; no runtime alloc) ----------------
__device__ __nv_bfloat16 g_hs [NTOK*CC];     // LN1(x), bf16 (GEMM A)
__device__ float         g_qkv[NTOK*3*CC];   // q|k|v fp32 (attn input)
__device__ __nv_bfloat16 g_ctx[NTOK*CC];     // attention context, bf16
__device__ float         g_hs2[NTOK*CC];     // x + attn_out, fp32
__device__ __nv_bfloat16 g_y  [NTOK*CC];     // LN2(hs2), bf16
__device__ __nv_bfloat16 g_t  [NTOK*FF];     // gelu(y@w1+b1), bf16
// packed weights: P[k2][n] = bf16x2( W[2*k2][n], W[2*k2+1][n] )
__device__ uint32_t g_wqkv_p[128*768];
__device__ uint32_t g_wo_p  [128*256];
__device__ uint32_t g_w1_p  [128*1024];
__device__ uint32_t g_w2_p  [512*256];
__device__ float    g_bqkv  [768];

__device__ __forceinline__ float4 ld4(const float* p) {
    return *reinterpret_cast<const float4*>(p);
}

__device__ __forceinline__ void mma_bf16(float (&d)[4], const uint32_t (&a)[4],
                                         const uint32_t (&b)[2]) {
    asm volatile(
        "mma.sync.aligned.m16n8k16.row.col.f32.bf16.bf16.f32 "
        "{%0,%1,%2,%3}, {%4,%5,%6,%7}, {%8,%9}, {%0,%1,%2,%3};\n"
        : "+f"(d[0]), "+f"(d[1]), "+f"(d[2]), "+f"(d[3])
        : "r"(a[0]), "r"(a[1]), "r"(a[2]), "r"(a[3]),
          "r"(b[0]), "r"(b[1]));
}

__device__ __forceinline__ uint32_t pack2(const float* W, int N, int k2, int n) {
    __nv_bfloat162 h = __floats2bfloat162_rn(W[(size_t)(2*k2)*N + n],
                                             W[(size_t)(2*k2+1)*N + n]);
    return *reinterpret_cast<uint32_t*>(&h);
}

// ---------------- weight pack (bf16 k-pair interleaved) ----------------
__global__ void pack_kernel(const float* __restrict__ wq, const float* __restrict__ wk,
                            const float* __restrict__ wv, const float* __restrict__ wo,
                            const float* __restrict__ w1, const float* __restrict__ w2,
                            const float* __restrict__ bq, const float* __restrict__ bk,
                            const float* __restrict__ bv)
{
    int idx = blockIdx.x * 256 + threadIdx.x;
    if (idx < 98304) {                       // wqkv: 128 x 768
        int k2 = idx / 768, n = idx % 768;
        const float* W; int nn;
        if      (n < 256) { W = wq; nn = n; }
        else if (n < 512) { W = wk; nn = n - 256; }
        else              { W = wv; nn = n - 512; }
        g_wqkv_p[idx] = pack2(W, 256, k2, nn);
    } else if (idx < 131072) {               // wo: 128 x 256
        int t = idx - 98304;
        g_wo_p[t] = pack2(wo, 256, t / 256, t % 256);
    } else if (idx < 262144) {               // w1: 128 x 1024
        int t = idx - 131072;
        g_w1_p[t] = pack2(w1, 1024, t / 1024, t % 1024);
    } else if (idx < 393216) {               // w2: 512 x 256
        int t = idx - 262144;
        g_w2_p[t] = pack2(w2, 256, t / 256, t % 256);
    }
    if (idx < 768) {
        float v;
        if      (idx < 256) v = bq[idx];
        else if (idx < 512) v = bk[idx - 256];
        else                v = bv[idx - 512];
        g_bqkv[idx] = v;
    }
}

// ---------------- LayerNorm: one block per row, 256 threads, bf16 out -------
__global__ void ln_kernel(const float* __restrict__ x, const float* __restrict__ g,
                          const float* __restrict__ b, __nv_bfloat16* __restrict__ out)
{
    int row = blockIdx.x;
    int c   = threadIdx.x;
    float v = x[row*CC + c];
    float s = v, sq = v*v;
    #pragma unroll
    for (int o = 16; o; o >>= 1) {
        s  += __shfl_xor_sync(0xffffffffu, s,  o);
        sq += __shfl_xor_sync(0xffffffffu, sq, o);
    }
    __shared__ float rs[8], rq[8];
    int w = c >> 5, l = c & 31;
    if (l == 0) { rs[w] = s; rq[w] = sq; }
    __syncthreads();
    if (w == 0) {
        float ss = (l < 8) ? rs[l] : 0.f;
        float qq = (l < 8) ? rq[l] : 0.f;
        #pragma unroll
        for (int o = 16; o; o >>= 1) {
            ss += __shfl_xor_sync(0xffffffffu, ss, o);
            qq += __shfl_xor_sync(0xffffffffu, qq, o);
        }
        if (l == 0) { rs[0] = ss; rq[0] = qq; }
    }
    __syncthreads();
    float mean = rs[0] * (1.0f/CC);
    float var  = rq[0] * (1.0f/CC) - mean*mean;
    float inv  = rsqrtf(var + 1e-5f);
    out[row*CC + c] = __float2bfloat16((v - mean) * inv * g[c] + b[c]);
}

// ---------------- bf16 tensor-core GEMM ----------------
// C[M,N] = A[M,K] @ W[K,N] (+ epilogue). A bf16 row-major, W packed uint32
// [K/2][N] (bf16x2 k-pairs). fp32 accum. Block 128x64, BK=32, 8 warps (4Mx2N),
// warp tile 32x32 (2x4 m16n8k16). Double-buffered smem.
// Smem strides (uint32 units): A=20, B=72 -> conflict-free fragment reads.
// EPI 0: +bias ; EPI 1: gelu(+bias) ; EPI 2: +bias + res
#define ASTR 20
#define BSTR 72

__device__ __forceinline__ void store2(float* p, float v0, float v1) {
    *reinterpret_cast<float2*>(p) = make_float2(v0, v1);
}
__device__ __forceinline__ void store2(__nv_bfloat16* p, float v0, float v1) {
    *reinterpret_cast<__nv_bfloat162*>(p) = __floats2bfloat162_rn(v0, v1);
}

template<int EPI, typename OutT>
__global__ void __launch_bounds__(256, 2)
bgemm_kernel(const __nv_bfloat16* __restrict__ A, const uint32_t* __restrict__ P,
             const float* __restrict__ bias, const float* __restrict__ res,
             OutT* __restrict__ C, int M, int N, int K)
{
    __shared__ uint32_t As[2][128][ASTR];   // [buf][m][k2], k2 = 0..15
    __shared__ uint32_t Bs[2][16][BSTR];    // [buf][k2][n]

    const int tid  = threadIdx.x;
    const int lane = tid & 31, warp = tid >> 5;
    const int wm = warp & 3, wn = warp >> 2;
    const int g = lane >> 2, c = lane & 3;
    const int bm = blockIdx.y * 128, bn = blockIdx.x * 64;

    // global load mapping
    const int arow = tid >> 1, akq = (tid & 1) * 16;   // A: 16 bf16 per thread
    const int brow = tid >> 4, bcol = (tid & 15) * 4;  // B: 4 uint32 per thread
    const __nv_bfloat16* Ag = A + (size_t)(bm + arow) * K + akq;
    const uint32_t* Pg = P + (size_t)brow * N + bn + bcol;

    float acc[2][4][4];
    #pragma unroll
    for (int mf = 0; mf < 2; mf++)
        #pragma unroll
        for (int nf = 0; nf < 4; nf++)
            #pragma unroll
            for (int e = 0; e < 4; e++) acc[mf][nf][e] = 0.f;

    // prologue
    uint4 pa0 = *reinterpret_cast<const uint4*>(Ag);
    uint4 pa1 = *reinterpret_cast<const uint4*>(Ag + 8);
    uint4 pb  = *reinterpret_cast<const uint4*>(Pg);
    *reinterpret_cast<uint4*>(&As[0][arow][akq >> 1])       = pa0;
    *reinterpret_cast<uint4*>(&As[0][arow][(akq >> 1) + 4]) = pa1;
    *reinterpret_cast<uint4*>(&Bs[0][brow][bcol])           = pb;
    __syncthreads();

    const int NT = K / 32;
    int buf = 0;
    for (int kt = 0; kt < NT; kt++) {
        if (kt + 1 < NT) {
            pa0 = *reinterpret_cast<const uint4*>(Ag + (kt + 1) * 32);
            pa1 = *reinterpret_cast<const uint4*>(Ag + (kt + 1) * 32 + 8);
            pb  = *reinterpret_cast<const uint4*>(Pg + (size_t)(kt + 1) * 16 * N);
        }
        #pragma unroll
        for (int ks = 0; ks < 16; ks += 8) {
            uint32_t af[2][4], bf[4][2];
            #pragma unroll
            for (int mf = 0; mf < 2; mf++) {
                int rb = wm * 32 + mf * 16;
                af[mf][0] = As[buf][rb + g][ks + c];
                af[mf][1] = As[buf][rb + g + 8][ks + c];
                af[mf][2] = As[buf][rb + g][ks + c + 4];
                af[mf][3] = As[buf][rb + g + 8][ks + c + 4];
            }
            #pragma unroll
            for (int nf = 0; nf < 4; nf++) {
                int nb = wn * 32 + nf * 8 + g;
                bf[nf][0] = Bs[buf][ks + c][nb];
                bf[nf][1] = Bs[buf][ks + c + 4][nb];
            }
            #pragma unroll
            for (int mf = 0; mf < 2; mf++)
                #pragma unroll
                for (int nf = 0; nf < 4; nf++)
                    mma_bf16(acc[mf][nf], af[mf], bf[nf]);
        }
        if (kt + 1 < NT) {
            int nb = buf ^ 1;
            *reinterpret_cast<uint4*>(&As[nb][arow][akq >> 1])       = pa0;
            *reinterpret_cast<uint4*>(&As[nb][arow][(akq >> 1) + 4]) = pa1;
            *reinterpret_cast<uint4*>(&Bs[nb][brow][bcol])           = pb;
        }
        __syncthreads();
        buf ^= 1;
    }

    // epilogue
    #pragma unroll
    for (int mf = 0; mf < 2; mf++) {
        #pragma unroll
        for (int nf = 0; nf < 4; nf++) {
            int row0 = bm + wm * 32 + mf * 16 + g;
            int col  = bn + wn * 32 + nf * 8 + c * 2;
            float bx = bias[col], by = bias[col + 1];
            #pragma unroll
            for (int h = 0; h < 2; h++) {
                int row = row0 + h * 8;
                float v0 = acc[mf][nf][h * 2 + 0] + bx;
                float v1 = acc[mf][nf][h * 2 + 1] + by;
                if (EPI == 1) {
                    v0 *= normcdff(v0);
                    v1 *= normcdff(v1);
                } else if (EPI == 2) {
                    float2 r = *reinterpret_cast<const float2*>(res + (size_t)row * N + col);
                    v0 += r.x; v1 += r.y;
                }
                store2(C + (size_t)row * N + col, v0, v1);
            }
        }
    }
}

// ---------------- dilated neighborhood attention ----------------
// one block per token; 8 head-warps; neighbor index/bias tables precomputed
// once per block into shared (removes 8x-redundant integer work).
__global__ void attn_kernel(const float* __restrict__ qkv, const float* __restrict__ rpb,
                            __nv_bfloat16* __restrict__ ctx)
{
    __shared__ float sc[HEADS][52];
    __shared__ int snt[49];   // qkv element offset: neighbor_tok * 768
    __shared__ int sbi[49];   // rpb index within a head's 13x13 table

    const int tok  = blockIdx.x;
    const int head = threadIdx.y;
    const int lane = threadIdx.x;
    const int tid  = head * 32 + lane;
    const int g = lane >> 3, e = lane & 7;

    if (tid < 49) {
        const int i = tok >> 6, j = tok & 63;
        int gi = i >> 1, ri = i & 1;
        int si = gi - 3; si = si < 0 ? 0 : (si > 25 ? 25 : si);
        int gj = j >> 1, rj = j & 1;
        int sj = gj - 3; sj = sj < 0 ? 0 : (sj > 25 ? 25 : sj);
        int kh = tid / 7, kw = tid - kh * 7;
        int ki = (si + kh) * 2 + ri;
        int kj = (sj + kw) * 2 + rj;
        snt[tid] = (ki * WW + kj) * (3*CC);
        sbi[tid] = (si - gi + 6 + kh) * 13 + (sj - gj + 6 + kw);
    }
    __syncthreads();

    const int choff = head*HD + e*4;
    float4 q4 = ld4(qkv + (size_t)tok*(3*CC) + choff);
    q4.x *= SCALE; q4.y *= SCALE; q4.z *= SCALE; q4.w *= SCALE;
    const float* biasrow = rpb + head*169;

    // pass 1: scores (4 neighbors in flight per warp iteration)
    #pragma unroll
    for (int t = 0; t < 13; t++) {
        int n = t*4 + g;
        bool valid = n < 49;
        float partial = 0.f;
        if (valid) {
            float4 k4 = ld4(qkv + snt[n] + CC + choff);
            partial = q4.x*k4.x + q4.y*k4.y + q4.z*k4.z + q4.w*k4.w;
        }
        partial += __shfl_xor_sync(0xffffffffu, partial, 1);
        partial += __shfl_xor_sync(0xffffffffu, partial, 2);
        partial += __shfl_xor_sync(0xffffffffu, partial, 4);
        if (valid && e == 0)
            sc[head][n] = partial + biasrow[sbi[n]];
    }
    __syncwarp();

    // softmax over 49 entries
    float s1 = sc[head][lane];
    float s2 = (lane < 17) ? sc[head][lane + 32] : -1e30f;
    float m = fmaxf(s1, s2);
    #pragma unroll
    for (int o = 16; o; o >>= 1) m = fmaxf(m, __shfl_xor_sync(0xffffffffu, m, o));
    float e1 = __expf(s1 - m);
    float e2 = (lane < 17) ? __expf(s2 - m) : 0.f;
    float ssum = e1 + e2;
    #pragma unroll
    for (int o = 16; o; o >>= 1) ssum += __shfl_xor_sync(0xffffffffu, ssum, o);
    sc[head][lane] = e1;
    if (lane < 17) sc[head][lane + 32] = e2;
    __syncwarp();
    const float inv = 1.0f / ssum;

    // pass 2: weighted V
    float4 a = make_float4(0.f, 0.f, 0.f, 0.f);
    #pragma unroll
    for (int t = 0; t < 13; t++) {
        int n = t*4 + g;
        if (n < 49) {
            float w = sc[head][n];
            float4 v4 = ld4(qkv + snt[n] + 2*CC + choff);
            a.x = fmaf(w, v4.x, a.x);
            a.y = fmaf(w, v4.y, a.y);
            a.z = fmaf(w, v4.z, a.z);
            a.w = fmaf(w, v4.w, a.w);
        }
    }
    #pragma unroll
    for (int o = 8; o <= 16; o <<= 1) {
        a.x += __shfl_xor_sync(0xffffffffu, a.x, o);
        a.y += __shfl_xor_sync(0xffffffffu, a.y, o);
        a.z += __shfl_xor_sync(0xffffffffu, a.z, o);
        a.w += __shfl_xor_sync(0xffffffffu, a.w, o);
    }
    if (g == 0) {
        __nv_bfloat162 o0 = __floats2bfloat162_rn(a.x*inv, a.y*inv);
        __nv_bfloat162 o1 = __floats2bfloat162_rn(a.z*inv, a.w*inv);
        uint2 pk = make_uint2(*reinterpret_cast<uint32_t*>(&o0),
                              *reinterpret_cast<uint32_t*>(&o1));
        *reinterpret_cast<uint2*>(ctx + (size_t)tok*CC + choff) = pk;
    }
}

// ---------------- launch ----------------
extern "C" void kernel_launch(void* const* d_in, const int* in_sizes, int n_in,
                              void* d_out, int out_size)
{
    const float* x     = (const float*)d_in[0];
    const float* ln1_g = (const float*)d_in[1];
    const float* ln1_b = (const float*)d_in[2];
    const float* wq    = (const float*)d_in[3];
    const float* bq    = (const float*)d_in[4];
    const float* wk    = (const float*)d_in[5];
    const float* bk    = (const float*)d_in[6];
    const float* wv    = (const float*)d_in[7];
    const float* bv    = (const float*)d_in[8];
    const float* rpb   = (const float*)d_in[9];
    const float* wo    = (const float*)d_in[10];
    const float* bo    = (const float*)d_in[11];
    const float* ln2_g = (const float*)d_in[12];
    const float* ln2_b = (const float*)d_in[13];
    const float* w1    = (const float*)d_in[14];
    const float* b1    = (const float*)d_in[15];
    const float* w2    = (const float*)d_in[16];
    const float* b2    = (const float*)d_in[17];
    float* out = (float*)d_out;

    __nv_bfloat16 *hs, *ctxp, *y, *t;
    float *qkv, *hs2, *bqkv;
    uint32_t *wqkv_p, *wo_p, *w1_p, *w2_p;
    cudaGetSymbolAddress((void**)&hs,     g_hs);
    cudaGetSymbolAddress((void**)&qkv,    g_qkv);
    cudaGetSymbolAddress((void**)&ctxp,   g_ctx);
    cudaGetSymbolAddress((void**)&hs2,    g_hs2);
    cudaGetSymbolAddress((void**)&y,      g_y);
    cudaGetSymbolAddress((void**)&t,      g_t);
    cudaGetSymbolAddress((void**)&wqkv_p, g_wqkv_p);
    cudaGetSymbolAddress((void**)&wo_p,   g_wo_p);
    cudaGetSymbolAddress((void**)&w1_p,   g_w1_p);
    cudaGetSymbolAddress((void**)&w2_p,   g_w2_p);
    cudaGetSymbolAddress((void**)&bqkv,   g_bqkv);

    // 1) pack weights to bf16 k-pair layout
    pack_kernel<<<1536, 256>>>(wq, wk, wv, wo, w1, w2, bq, bk, bv);

    // 2) LN1 -> bf16
    ln_kernel<<<NTOK, CC>>>(x, ln1_g, ln1_b, hs);

    // 3) QKV GEMM: [4096,256] @ [256,768] -> fp32
    {
        dim3 grid(768/64, NTOK/128);
        bgemm_kernel<0, float><<<grid, 256>>>(hs, wqkv_p, bqkv, nullptr, qkv,
                                              NTOK, 768, CC);
    }

    // 4) attention -> bf16 ctx
    {
        dim3 blk(32, HEADS);
        attn_kernel<<<NTOK, blk>>>(qkv, rpb, ctxp);
    }

    // 5) wo GEMM + residual(x): hs2 = ctx@wo + bo + x  (fp32)
    {
        dim3 grid(CC/64, NTOK/128);
        bgemm_kernel<2, float><<<grid, 256>>>(ctxp, wo_p, bo, x, hs2,
                                              NTOK, CC, CC);
    }

    // 6) LN2 -> bf16
    ln_kernel<<<NTOK, CC>>>(hs2, ln2_g, ln2_b, y);

    // 7) w1 GEMM + exact GELU -> bf16 t
    {
        dim3 grid(FF/64, NTOK/128);
        bgemm_kernel<1, __nv_bfloat16><<<grid, 256>>>(y, w1_p, b1, nullptr, t,
                                                      NTOK, FF, CC);
    }

    // 8) w2 GEMM + residual(hs2): out = t@w2 + b2 + hs2  (fp32)
    {
        dim3 grid(CC/64, NTOK/128);
        bgemm_kernel<2, float><<<grid, 256>>>(t, w2_p, b2, hs2, out,
                                              NTOK, CC, FF);
    }
}

// round 5
// speedup vs baseline: 2.9667x; 1.0325x over previous
#include <cuda_runtime.h>
#include <cuda_bf16.h>
#include <math.h>
#include <stdint.h>

// Problem constants
#define BB 1
#define HH 64
#define WW 64
#define CC 256
#define HEADS 8
#define HD 32
#define KK 7
#define DIL 2
#define FF 1024
#define NTOK (HH*WW)            // 4096
#define SCALE 0.17677669529663687f  // 1/sqrt(32)

// ---------------- scratch (device globals; no runtime alloc) ----------------
__device__ __nv_bfloat16 g_hs [NTOK*CC];     // LN1(x), bf16 (GEMM A)
__device__ float         g_q  [NTOK*CC];     // q fp32, pre-scaled
__device__ __nv_bfloat16 g_k  [NTOK*CC];     // k bf16
__device__ __nv_bfloat16 g_v  [NTOK*CC];     // v bf16
__device__ __nv_bfloat16 g_ctx[NTOK*CC];     // attention context, bf16
__device__ float         g_hs2[NTOK*CC];     // x + attn_out, fp32
__device__ __nv_bfloat16 g_y  [NTOK*CC];     // LN2(hs2), bf16
__device__ __nv_bfloat16 g_t  [NTOK*FF];     // gelu(y@w1+b1), bf16
// packed weights: P[k2][n] = bf16x2( W[2*k2][n], W[2*k2+1][n] )
__device__ uint32_t g_wqkv_p[128*768];
__device__ uint32_t g_wo_p  [128*256];
__device__ uint32_t g_w1_p  [128*1024];
__device__ uint32_t g_w2_p  [512*256];
__device__ float    g_bqkv  [768];

__device__ __forceinline__ float4 ld4(const float* p) {
    return *reinterpret_cast<const float4*>(p);
}
__device__ __forceinline__ float2 bf2f(uint32_t u) {
    __nv_bfloat162 h = *reinterpret_cast<__nv_bfloat162*>(&u);
    return __bfloat1622float2(h);
}

__device__ __forceinline__ void mma_bf16(float (&d)[4], const uint32_t (&a)[4],
                                         const uint32_t (&b)[2]) {
    asm volatile(
        "mma.sync.aligned.m16n8k16.row.col.f32.bf16.bf16.f32 "
        "{%0,%1,%2,%3}, {%4,%5,%6,%7}, {%8,%9}, {%0,%1,%2,%3};\n"
        : "+f"(d[0]), "+f"(d[1]), "+f"(d[2]), "+f"(d[3])
        : "r"(a[0]), "r"(a[1]), "r"(a[2]), "r"(a[3]),
          "r"(b[0]), "r"(b[1]));
}

__device__ __forceinline__ uint32_t pack2(const float* W, int N, int k2, int n) {
    __nv_bfloat162 h = __floats2bfloat162_rn(W[(size_t)(2*k2)*N + n],
                                             W[(size_t)(2*k2+1)*N + n]);
    return *reinterpret_cast<uint32_t*>(&h);
}

// ---------------- weight pack (bf16 k-pair interleaved) ----------------
__global__ void pack_kernel(const float* __restrict__ wq, const float* __restrict__ wk,
                            const float* __restrict__ wv, const float* __restrict__ wo,
                            const float* __restrict__ w1, const float* __restrict__ w2,
                            const float* __restrict__ bq, const float* __restrict__ bk,
                            const float* __restrict__ bv)
{
    int idx = blockIdx.x * 256 + threadIdx.x;
    if (idx < 98304) {                       // wqkv: 128 x 768
        int k2 = idx / 768, n = idx % 768;
        const float* W; int nn;
        if      (n < 256) { W = wq; nn = n; }
        else if (n < 512) { W = wk; nn = n - 256; }
        else              { W = wv; nn = n - 512; }
        g_wqkv_p[idx] = pack2(W, 256, k2, nn);
    } else if (idx < 131072) {               // wo: 128 x 256
        int t = idx - 98304;
        g_wo_p[t] = pack2(wo, 256, t / 256, t % 256);
    } else if (idx < 262144) {               // w1: 128 x 1024
        int t = idx - 131072;
        g_w1_p[t] = pack2(w1, 1024, t / 1024, t % 1024);
    } else if (idx < 393216) {               // w2: 512 x 256
        int t = idx - 262144;
        g_w2_p[t] = pack2(w2, 256, t / 256, t % 256);
    }
    if (idx < 768) {
        float v;
        if      (idx < 256) v = bq[idx];
        else if (idx < 512) v = bk[idx - 256];
        else                v = bv[idx - 512];
        g_bqkv[idx] = v;
    }
}

// ---------------- LayerNorm: one block per row, 256 threads, bf16 out -------
__global__ void ln_kernel(const float* __restrict__ x, const float* __restrict__ g,
                          const float* __restrict__ b, __nv_bfloat16* __restrict__ out)
{
    int row = blockIdx.x;
    int c   = threadIdx.x;
    float v = x[row*CC + c];
    float s = v, sq = v*v;
    #pragma unroll
    for (int o = 16; o; o >>= 1) {
        s  += __shfl_xor_sync(0xffffffffu, s,  o);
        sq += __shfl_xor_sync(0xffffffffu, sq, o);
    }
    __shared__ float rs[8], rq[8];
    int w = c >> 5, l = c & 31;
    if (l == 0) { rs[w] = s; rq[w] = sq; }
    __syncthreads();
    if (w == 0) {
        float ss = (l < 8) ? rs[l] : 0.f;
        float qq = (l < 8) ? rq[l] : 0.f;
        #pragma unroll
        for (int o = 16; o; o >>= 1) {
            ss += __shfl_xor_sync(0xffffffffu, ss, o);
            qq += __shfl_xor_sync(0xffffffffu, qq, o);
        }
        if (l == 0) { rs[0] = ss; rq[0] = qq; }
    }
    __syncthreads();
    float mean = rs[0] * (1.0f/CC);
    float var  = rq[0] * (1.0f/CC) - mean*mean;
    float inv  = rsqrtf(var + 1e-5f);
    out[row*CC + c] = __float2bfloat16((v - mean) * inv * g[c] + b[c]);
}

// ---------------- bf16 tensor-core GEMM ----------------
// C[M,N] = A[M,K] @ W[K,N] (+ epilogue). A bf16 row-major, W packed uint32
// [K/2][N] (bf16x2 k-pairs). fp32 accum. Block 128x64, BK=32, 8 warps (4Mx2N),
// warp tile 32x32 (2x4 m16n8k16). Double-buffered smem.
// A smem is k2-interleaved within 8-k2 blocks (logical p -> phys 2*(p&3)+(p>>2))
// so A fragments load as LDS.64. ASTR=24: frag chunk = 12g+c distinct mod 16.
// EPI 0: +bias ; EPI 1: gelu(+bias) ; EPI 2: +bias + res ; EPI 3: qkv split
#define ASTR 24
#define BSTR 72

__device__ __forceinline__ void store2(float* p, float v0, float v1) {
    *reinterpret_cast<float2*>(p) = make_float2(v0, v1);
}
__device__ __forceinline__ void store2(__nv_bfloat16* p, float v0, float v1) {
    *reinterpret_cast<__nv_bfloat162*>(p) = __floats2bfloat162_rn(v0, v1);
}

template<int EPI, typename OutT>
__global__ void __launch_bounds__(256, 2)
bgemm_kernel(const __nv_bfloat16* __restrict__ A, const uint32_t* __restrict__ P,
             const float* __restrict__ bias, const float* __restrict__ res,
             OutT* __restrict__ C, __nv_bfloat16* __restrict__ kout,
             __nv_bfloat16* __restrict__ vout, int M, int N, int K)
{
    __shared__ uint32_t As[2][128][ASTR];   // [buf][m][k2 phys]
    __shared__ uint32_t Bs[2][16][BSTR];    // [buf][k2][n]

    const int tid  = threadIdx.x;
    const int lane = tid & 31, warp = tid >> 5;
    const int wm = warp & 3, wn = warp >> 2;
    const int g = lane >> 2, c = lane & 3;
    const int bm = blockIdx.y * 128, bn = blockIdx.x * 64;

    const int arow = tid >> 1, ablk = (tid & 1);       // A: one 8-k2 block
    const int brow = tid >> 4, bcol = (tid & 15) * 4;  // B: 4 uint32
    const __nv_bfloat16* Ag = A + (size_t)(bm + arow) * K + ablk * 16;
    const uint32_t* Pg = P + (size_t)brow * N + bn + bcol;

    float acc[2][4][4];
    #pragma unroll
    for (int mf = 0; mf < 2; mf++)
        #pragma unroll
        for (int nf = 0; nf < 4; nf++)
            #pragma unroll
            for (int e = 0; e < 4; e++) acc[mf][nf][e] = 0.f;

    // prologue
    uint4 pa0 = *reinterpret_cast<const uint4*>(Ag);       // k2 0..3 of block
    uint4 pa1 = *reinterpret_cast<const uint4*>(Ag + 8);   // k2 4..7 of block
    uint4 pb  = *reinterpret_cast<const uint4*>(Pg);
    {
        uint4 s0 = make_uint4(pa0.x, pa1.x, pa0.y, pa1.y);
        uint4 s1 = make_uint4(pa0.z, pa1.z, pa0.w, pa1.w);
        *reinterpret_cast<uint4*>(&As[0][arow][ablk*8])     = s0;
        *reinterpret_cast<uint4*>(&As[0][arow][ablk*8 + 4]) = s1;
        *reinterpret_cast<uint4*>(&Bs[0][brow][bcol])       = pb;
    }
    __syncthreads();

    const int NT = K / 32;
    int buf = 0;
    for (int kt = 0; kt < NT; kt++) {
        if (kt + 1 < NT) {
            pa0 = *reinterpret_cast<const uint4*>(Ag + (kt + 1) * 32);
            pa1 = *reinterpret_cast<const uint4*>(Ag + (kt + 1) * 32 + 8);
            pb  = *reinterpret_cast<const uint4*>(Pg + (size_t)(kt + 1) * 16 * N);
        }
        #pragma unroll
        for (int ks = 0; ks < 16; ks += 8) {
            uint32_t af[2][4], bf[4][2];
            #pragma unroll
            for (int mf = 0; mf < 2; mf++) {
                int rb = wm * 32 + mf * 16;
                uint2 u1 = *reinterpret_cast<const uint2*>(&As[buf][rb + g][ks + 2*c]);
                uint2 u2 = *reinterpret_cast<const uint2*>(&As[buf][rb + g + 8][ks + 2*c]);
                af[mf][0] = u1.x; af[mf][2] = u1.y;
                af[mf][1] = u2.x; af[mf][3] = u2.y;
            }
            #pragma unroll
            for (int nf = 0; nf < 4; nf++) {
                int nb = wn * 32 + nf * 8 + g;
                bf[nf][0] = Bs[buf][ks + c][nb];
                bf[nf][1] = Bs[buf][ks + c + 4][nb];
            }
            #pragma unroll
            for (int mf = 0; mf < 2; mf++)
                #pragma unroll
                for (int nf = 0; nf < 4; nf++)
                    mma_bf16(acc[mf][nf], af[mf], bf[nf]);
        }
        if (kt + 1 < NT) {
            int nb = buf ^ 1;
            uint4 s0 = make_uint4(pa0.x, pa1.x, pa0.y, pa1.y);
            uint4 s1 = make_uint4(pa0.z, pa1.z, pa0.w, pa1.w);
            *reinterpret_cast<uint4*>(&As[nb][arow][ablk*8])     = s0;
            *reinterpret_cast<uint4*>(&As[nb][arow][ablk*8 + 4]) = s1;
            *reinterpret_cast<uint4*>(&Bs[nb][brow][bcol])       = pb;
        }
        __syncthreads();
        buf ^= 1;
    }

    // epilogue
    #pragma unroll
    for (int mf = 0; mf < 2; mf++) {
        #pragma unroll
        for (int nf = 0; nf < 4; nf++) {
            int row0 = bm + wm * 32 + mf * 16 + g;
            int col  = bn + wn * 32 + nf * 8 + c * 2;
            float bx = bias[col], by = bias[col + 1];
            #pragma unroll
            for (int h = 0; h < 2; h++) {
                int row = row0 + h * 8;
                float v0 = acc[mf][nf][h * 2 + 0] + bx;
                float v1 = acc[mf][nf][h * 2 + 1] + by;
                if (EPI == 1) {
                    v0 *= normcdff(v0);
                    v1 *= normcdff(v1);
                } else if (EPI == 2) {
                    float2 r = *reinterpret_cast<const float2*>(res + (size_t)row * N + col);
                    v0 += r.x; v1 += r.y;
                }
                if (EPI == 3) {
                    // qkv split: q fp32 pre-scaled, k/v bf16
                    if (col < 256) {
                        store2((float*)C + (size_t)row * 256 + col, v0 * SCALE, v1 * SCALE);
                    } else if (col < 512) {
                        store2(kout + (size_t)row * 256 + (col - 256), v0, v1);
                    } else {
                        store2(vout + (size_t)row * 256 + (col - 512), v0, v1);
                    }
                } else {
                    store2(C + (size_t)row * N + col, v0, v1);
                }
            }
        }
    }
}

// ---------------- dilated neighborhood attention ----------------
// one block per token; 8 head-warps; q fp32 (pre-scaled), k/v bf16.
// warp split into 4 groups of 8 lanes; neighbor tables in shared.
__global__ void attn_kernel(const float* __restrict__ q, const __nv_bfloat16* __restrict__ k,
                            const __nv_bfloat16* __restrict__ v, const float* __restrict__ rpb,
                            __nv_bfloat16* __restrict__ ctx)
{
    __shared__ float sc[HEADS][52];
    __shared__ int snt[49];   // neighbor_tok * 256
    __shared__ int sbi[49];   // rpb index within a head's 13x13 table

    const int tok  = blockIdx.x;
    const int head = threadIdx.y;
    const int lane = threadIdx.x;
    const int tid  = head * 32 + lane;
    const int gg = lane >> 3, e = lane & 7;

    if (tid < 49) {
        const int i = tok >> 6, j = tok & 63;
        int gi = i >> 1, ri = i & 1;
        int si = gi - 3; si = si < 0 ? 0 : (si > 25 ? 25 : si);
        int gj = j >> 1, rj = j & 1;
        int sj = gj - 3; sj = sj < 0 ? 0 : (sj > 25 ? 25 : sj);
        int kh = tid / 7, kw = tid - kh * 7;
        int ki = (si + kh) * 2 + ri;
        int kj = (sj + kw) * 2 + rj;
        snt[tid] = (ki * WW + kj) * CC;
        sbi[tid] = (si - gi + 6 + kh) * 13 + (sj - gj + 6 + kw);
    }
    __syncthreads();

    const int choff = head*HD + e*4;
    float4 q4 = ld4(q + (size_t)tok*CC + choff);       // pre-scaled
    const float* biasrow = rpb + head*169;

    // pass 1: scores (4 neighbors in flight per warp iteration)
    #pragma unroll
    for (int t = 0; t < 13; t++) {
        int n = t*4 + gg;
        bool valid = n < 49;
        float partial = 0.f;
        if (valid) {
            uint2 u = *reinterpret_cast<const uint2*>(k + snt[n] + choff);
            float2 k01 = bf2f(u.x), k23 = bf2f(u.y);
            partial = q4.x*k01.x + q4.y*k01.y + q4.z*k23.x + q4.w*k23.y;
        }
        partial += __shfl_xor_sync(0xffffffffu, partial, 1);
        partial += __shfl_xor_sync(0xffffffffu, partial, 2);
        partial += __shfl_xor_sync(0xffffffffu, partial, 4);
        if (valid && e == 0)
            sc[head][n] = partial + biasrow[sbi[n]];
    }
    __syncwarp();

    // softmax over 49 entries
    float s1 = sc[head][lane];
    float s2 = (lane < 17) ? sc[head][lane + 32] : -1e30f;
    float m = fmaxf(s1, s2);
    #pragma unroll
    for (int o = 16; o; o >>= 1) m = fmaxf(m, __shfl_xor_sync(0xffffffffu, m, o));
    float e1 = __expf(s1 - m);
    float e2 = (lane < 17) ? __expf(s2 - m) : 0.f;
    float ssum = e1 + e2;
    #pragma unroll
    for (int o = 16; o; o >>= 1) ssum += __shfl_xor_sync(0xffffffffu, ssum, o);
    sc[head][lane] = e1;
    if (lane < 17) sc[head][lane + 32] = e2;
    __syncwarp();
    const float inv = 1.0f / ssum;

    // pass 2: weighted V
    float4 a = make_float4(0.f, 0.f, 0.f, 0.f);
    #pragma unroll
    for (int t = 0; t < 13; t++) {
        int n = t*4 + gg;
        if (n < 49) {
            float w = sc[head][n];
            uint2 u = *reinterpret_cast<const uint2*>(v + snt[n] + choff);
            float2 v01 = bf2f(u.x), v23 = bf2f(u.y);
            a.x = fmaf(w, v01.x, a.x);
            a.y = fmaf(w, v01.y, a.y);
            a.z = fmaf(w, v23.x, a.z);
            a.w = fmaf(w, v23.y, a.w);
        }
    }
    #pragma unroll
    for (int o = 8; o <= 16; o <<= 1) {
        a.x += __shfl_xor_sync(0xffffffffu, a.x, o);
        a.y += __shfl_xor_sync(0xffffffffu, a.y, o);
        a.z += __shfl_xor_sync(0xffffffffu, a.z, o);
        a.w += __shfl_xor_sync(0xffffffffu, a.w, o);
    }
    if (gg == 0) {
        __nv_bfloat162 o0 = __floats2bfloat162_rn(a.x*inv, a.y*inv);
        __nv_bfloat162 o1 = __floats2bfloat162_rn(a.z*inv, a.w*inv);
        uint2 pk = make_uint2(*reinterpret_cast<uint32_t*>(&o0),
                              *reinterpret_cast<uint32_t*>(&o1));
        *reinterpret_cast<uint2*>(ctx + (size_t)tok*CC + choff) = pk;
    }
}

// ---------------- launch ----------------
extern "C" void kernel_launch(void* const* d_in, const int* in_sizes, int n_in,
                              void* d_out, int out_size)
{
    const float* x     = (const float*)d_in[0];
    const float* ln1_g = (const float*)d_in[1];
    const float* ln1_b = (const float*)d_in[2];
    const float* wq    = (const float*)d_in[3];
    const float* bq    = (const float*)d_in[4];
    const float* wk    = (const float*)d_in[5];
    const float* bk    = (const float*)d_in[6];
    const float* wv    = (const float*)d_in[7];
    const float* bv    = (const float*)d_in[8];
    const float* rpb   = (const float*)d_in[9];
    const float* wo    = (const float*)d_in[10];
    const float* bo    = (const float*)d_in[11];
    const float* ln2_g = (const float*)d_in[12];
    const float* ln2_b = (const float*)d_in[13];
    const float* w1    = (const float*)d_in[14];
    const float* b1    = (const float*)d_in[15];
    const float* w2    = (const float*)d_in[16];
    const float* b2    = (const float*)d_in[17];
    float* out = (float*)d_out;

    __nv_bfloat16 *hs, *kq, *vq, *ctxp, *y, *t;
    float *qq, *hs2, *bqkv;
    uint32_t *wqkv_p, *wo_p, *w1_p, *w2_p;
    cudaGetSymbolAddress((void**)&hs,     g_hs);
    cudaGetSymbolAddress((void**)&qq,     g_q);
    cudaGetSymbolAddress((void**)&kq,     g_k);
    cudaGetSymbolAddress((void**)&vq,     g_v);
    cudaGetSymbolAddress((void**)&ctxp,   g_ctx);
    cudaGetSymbolAddress((void**)&hs2,    g_hs2);
    cudaGetSymbolAddress((void**)&y,      g_y);
    cudaGetSymbolAddress((void**)&t,      g_t);
    cudaGetSymbolAddress((void**)&wqkv_p, g_wqkv_p);
    cudaGetSymbolAddress((void**)&wo_p,   g_wo_p);
    cudaGetSymbolAddress((void**)&w1_p,   g_w1_p);
    cudaGetSymbolAddress((void**)&w2_p,   g_w2_p);
    cudaGetSymbolAddress((void**)&bqkv,   g_bqkv);

    // 1) pack weights to bf16 k-pair layout
    pack_kernel<<<1536, 256>>>(wq, wk, wv, wo, w1, w2, bq, bk, bv);

    // 2) LN1 -> bf16
    ln_kernel<<<NTOK, CC>>>(x, ln1_g, ln1_b, hs);

    // 3) QKV GEMM: [4096,256] @ [256,768] -> q fp32(scaled) | k bf16 | v bf16
    {
        dim3 grid(768/64, NTOK/128);
        bgemm_kernel<3, float><<<grid, 256>>>(hs, wqkv_p, bqkv, nullptr, qq,
                                              kq, vq, NTOK, 768, CC);
    }

    // 4) attention -> bf16 ctx
    {
        dim3 blk(32, HEADS);
        attn_kernel<<<NTOK, blk>>>(qq, kq, vq, rpb, ctxp);
    }

    // 5) wo GEMM + residual(x): hs2 = ctx@wo + bo + x  (fp32)
    {
        dim3 grid(CC/64, NTOK/128);
        bgemm_kernel<2, float><<<grid, 256>>>(ctxp, wo_p, bo, x, hs2,
                                              nullptr, nullptr, NTOK, CC, CC);
    }

    // 6) LN2 -> bf16
    ln_kernel<<<NTOK, CC>>>(hs2, ln2_g, ln2_b, y);

    // 7) w1 GEMM + exact GELU -> bf16 t
    {
        dim3 grid(FF/64, NTOK/128);
        bgemm_kernel<1, __nv_bfloat16><<<grid, 256>>>(y, w1_p, b1, nullptr, t,
                                                      nullptr, nullptr, NTOK, FF, CC);
    }

    // 8) w2 GEMM + residual(hs2): out = t@w2 + b2 + hs2  (fp32)
    {
        dim3 grid(CC/64, NTOK/128);
        bgemm_kernel<2, float><<<grid, 256>>>(t, w2_p, b2, hs2, out,
                                              nullptr, nullptr, NTOK, CC, FF);
    }
}

// round 6
// speedup vs baseline: 3.0282x; 1.0207x over previous
#include <cuda_runtime.h>
#include <cuda_bf16.h>
#include <math.h>
#include <stdint.h>

// Problem constants
#define BB 1
#define HH 64
#define WW 64
#define CC 256
#define HEADS 8
#define HD 32
#define KK 7
#define DIL 2
#define FF 1024
#define NTOK (HH*WW)            // 4096
#define SCALE 0.17677669529663687f  // 1/sqrt(32)

// ---------------- scratch (device globals; no runtime alloc) ----------------
__device__ __nv_bfloat16 g_hs [NTOK*CC];     // LN1(x), bf16 (GEMM A)
__device__ float         g_q  [NTOK*CC];     // q fp32, pre-scaled
__device__ __nv_bfloat16 g_k  [NTOK*CC];     // k bf16
__device__ __nv_bfloat16 g_v  [NTOK*CC];     // v bf16
__device__ __nv_bfloat16 g_ctx[NTOK*CC];     // attention context, bf16
__device__ float         g_hs2[NTOK*CC];     // x + attn_out, fp32
__device__ __nv_bfloat16 g_y  [NTOK*CC];     // LN2(hs2), bf16
__device__ __nv_bfloat16 g_t  [NTOK*FF];     // gelu(y@w1+b1), bf16
// packed weights: P[k2][n] = bf16x2( W[2*k2][n], W[2*k2+1][n] )
__device__ uint32_t g_wqkv_p[128*768];
__device__ uint32_t g_wo_p  [128*256];
__device__ uint32_t g_w1_p  [128*1024];
__device__ uint32_t g_w2_p  [512*256];
__device__ float    g_bqkv  [768];

__device__ __forceinline__ float4 ld4(const float* p) {
    return *reinterpret_cast<const float4*>(p);
}
__device__ __forceinline__ float2 bf2f(uint32_t u) {
    __nv_bfloat162 h = *reinterpret_cast<__nv_bfloat162*>(&u);
    return __bfloat1622float2(h);
}

// packed f32x2 fma (sm_103a; PTX-only, ptxas won't auto-fuse)
__device__ __forceinline__ float2 ffma2(float2 a, float2 b, float2 c) {
    float2 d;
    asm("fma.rn.f32x2 %0, %1, %2, %3;"
        : "=l"(*reinterpret_cast<uint64_t*>(&d))
        : "l"(*reinterpret_cast<const uint64_t*>(&a)),
          "l"(*reinterpret_cast<const uint64_t*>(&b)),
          "l"(*reinterpret_cast<const uint64_t*>(&c)));
    return d;
}
__device__ __forceinline__ float2 fmul2(float2 a, float2 b) {
    float2 d;
    asm("mul.rn.f32x2 %0, %1, %2;"
        : "=l"(*reinterpret_cast<uint64_t*>(&d))
        : "l"(*reinterpret_cast<const uint64_t*>(&a)),
          "l"(*reinterpret_cast<const uint64_t*>(&b)));
    return d;
}

__device__ __forceinline__ void mma_bf16(float (&d)[4], const uint32_t (&a)[4],
                                         const uint32_t (&b)[2]) {
    asm volatile(
        "mma.sync.aligned.m16n8k16.row.col.f32.bf16.bf16.f32 "
        "{%0,%1,%2,%3}, {%4,%5,%6,%7}, {%8,%9}, {%0,%1,%2,%3};\n"
        : "+f"(d[0]), "+f"(d[1]), "+f"(d[2]), "+f"(d[3])
        : "r"(a[0]), "r"(a[1]), "r"(a[2]), "r"(a[3]),
          "r"(b[0]), "r"(b[1]));
}

__device__ __forceinline__ uint32_t pack2(const float* W, int N, int k2, int n) {
    __nv_bfloat162 h = __floats2bfloat162_rn(W[(size_t)(2*k2)*N + n],
                                             W[(size_t)(2*k2+1)*N + n]);
    return *reinterpret_cast<uint32_t*>(&h);
}

// ---------------- weight pack (bf16 k-pair interleaved) ----------------
__global__ void pack_kernel(const float* __restrict__ wq, const float* __restrict__ wk,
                            const float* __restrict__ wv, const float* __restrict__ wo,
                            const float* __restrict__ w1, const float* __restrict__ w2,
                            const float* __restrict__ bq, const float* __restrict__ bk,
                            const float* __restrict__ bv)
{
    int idx = blockIdx.x * 256 + threadIdx.x;
    if (idx < 98304) {                       // wqkv: 128 x 768
        int k2 = idx / 768, n = idx % 768;
        const float* W; int nn;
        if      (n < 256) { W = wq; nn = n; }
        else if (n < 512) { W = wk; nn = n - 256; }
        else              { W = wv; nn = n - 512; }
        g_wqkv_p[idx] = pack2(W, 256, k2, nn);
    } else if (idx < 131072) {               // wo: 128 x 256
        int t = idx - 98304;
        g_wo_p[t] = pack2(wo, 256, t / 256, t % 256);
    } else if (idx < 262144) {               // w1: 128 x 1024
        int t = idx - 131072;
        g_w1_p[t] = pack2(w1, 1024, t / 1024, t % 1024);
    } else if (idx < 393216) {               // w2: 512 x 256
        int t = idx - 262144;
        g_w2_p[t] = pack2(w2, 256, t / 256, t % 256);
    }
    if (idx < 768) {
        float v;
        if      (idx < 256) v = bq[idx];
        else if (idx < 512) v = bk[idx - 256];
        else                v = bv[idx - 512];
        g_bqkv[idx] = v;
    }
}

// ---------------- LayerNorm: one warp per row, 8 rows/block ----------------
__global__ void ln_kernel(const float* __restrict__ x, const float* __restrict__ g,
                          const float* __restrict__ b, __nv_bfloat16* __restrict__ out)
{
    const int row  = blockIdx.x * 8 + (threadIdx.x >> 5);
    const int lane = threadIdx.x & 31;
    const float* xr = x + (size_t)row * CC + lane * 8;
    float4 v0 = ld4(xr), v1 = ld4(xr + 4);
    float s  = v0.x + v0.y + v0.z + v0.w + v1.x + v1.y + v1.z + v1.w;
    float sq = v0.x*v0.x + v0.y*v0.y + v0.z*v0.z + v0.w*v0.w
             + v1.x*v1.x + v1.y*v1.y + v1.z*v1.z + v1.w*v1.w;
    #pragma unroll
    for (int o = 16; o; o >>= 1) {
        s  += __shfl_xor_sync(0xffffffffu, s,  o);
        sq += __shfl_xor_sync(0xffffffffu, sq, o);
    }
    float mean = s * (1.0f/CC);
    float var  = sq * (1.0f/CC) - mean*mean;
    float inv  = rsqrtf(var + 1e-5f);
    float4 g0 = ld4(g + lane*8), g1 = ld4(g + lane*8 + 4);
    float4 b0 = ld4(b + lane*8), b1 = ld4(b + lane*8 + 4);
    __nv_bfloat162 o0 = __floats2bfloat162_rn((v0.x-mean)*inv*g0.x + b0.x,
                                              (v0.y-mean)*inv*g0.y + b0.y);
    __nv_bfloat162 o1 = __floats2bfloat162_rn((v0.z-mean)*inv*g0.z + b0.z,
                                              (v0.w-mean)*inv*g0.w + b0.w);
    __nv_bfloat162 o2 = __floats2bfloat162_rn((v1.x-mean)*inv*g1.x + b1.x,
                                              (v1.y-mean)*inv*g1.y + b1.y);
    __nv_bfloat162 o3 = __floats2bfloat162_rn((v1.z-mean)*inv*g1.z + b1.z,
                                              (v1.w-mean)*inv*g1.w + b1.w);
    uint4 pk = make_uint4(*reinterpret_cast<uint32_t*>(&o0),
                          *reinterpret_cast<uint32_t*>(&o1),
                          *reinterpret_cast<uint32_t*>(&o2),
                          *reinterpret_cast<uint32_t*>(&o3));
    *reinterpret_cast<uint4*>(out + (size_t)row * CC + lane * 8) = pk;
}

// ---------------- bf16 tensor-core GEMM ----------------
// C[M,N] = A[M,K] @ W[K,N] (+ epilogue). A bf16 row-major, W packed uint32
// [K/2][N] (bf16x2 k-pairs). fp32 accum. BM_ in {128, 64}, BN=64, BK=32,
// 8 warps. BM128: 4Mx2N warps, warp 32x32 (2x4 frags). BM64: 2Mx4N warps,
// warp 32x16 (2x2 frags). Double-buffered smem, A k2-interleaved for LDS.64.
// EPI 0: +bias ; EPI 1: gelu(+bias) ; EPI 2: +bias + res ; EPI 3: qkv split
#define ASTR 24
#define BSTR 72

__device__ __forceinline__ void store2(float* p, float v0, float v1) {
    *reinterpret_cast<float2*>(p) = make_float2(v0, v1);
}
__device__ __forceinline__ void store2(__nv_bfloat16* p, float v0, float v1) {
    *reinterpret_cast<__nv_bfloat162*>(p) = __floats2bfloat162_rn(v0, v1);
}

template<int EPI, typename OutT, int BM_>
__global__ void __launch_bounds__(256, 2)
bgemm_kernel(const __nv_bfloat16* __restrict__ A, const uint32_t* __restrict__ P,
             const float* __restrict__ bias, const float* __restrict__ res,
             OutT* __restrict__ C, __nv_bfloat16* __restrict__ kout,
             __nv_bfloat16* __restrict__ vout, int M, int N, int K)
{
    constexpr int WM = (BM_ == 128) ? 4 : 2;   // warps along M
    constexpr int WN = 8 / WM;                 // warps along N
    constexpr int NF = 64 / (WN * 8);          // n-frags per warp (4 or 2)

    __shared__ uint32_t As[2][BM_][ASTR];   // [buf][m][k2 phys]
    __shared__ uint32_t Bs[2][16][BSTR];    // [buf][k2][n]

    const int tid  = threadIdx.x;
    const int lane = tid & 31, warp = tid >> 5;
    const int wm = warp % WM, wn = warp / WM;
    const int g = lane >> 2, c = lane & 3;
    const int bm = blockIdx.y * BM_, bn = blockIdx.x * 64;

    const int arow = (tid >> 1) % BM_, ablk = (tid & 1);
    const bool aload = (BM_ == 128) || (tid < 128);
    const int brow = tid >> 4, bcol = (tid & 15) * 4;
    const __nv_bfloat16* Ag = A + (size_t)(bm + arow) * K + ablk * 16;
    const uint32_t* Pg = P + (size_t)brow * N + bn + bcol;

    float acc[2][NF][4];
    #pragma unroll
    for (int mf = 0; mf < 2; mf++)
        #pragma unroll
        for (int nf = 0; nf < NF; nf++)
            #pragma unroll
            for (int e = 0; e < 4; e++) acc[mf][nf][e] = 0.f;

    // prologue
    uint4 pa0, pa1, pb;
    if (aload) {
        pa0 = *reinterpret_cast<const uint4*>(Ag);       // k2 0..3 of block
        pa1 = *reinterpret_cast<const uint4*>(Ag + 8);   // k2 4..7 of block
        uint4 s0 = make_uint4(pa0.x, pa1.x, pa0.y, pa1.y);
        uint4 s1 = make_uint4(pa0.z, pa1.z, pa0.w, pa1.w);
        *reinterpret_cast<uint4*>(&As[0][arow][ablk*8])     = s0;
        *reinterpret_cast<uint4*>(&As[0][arow][ablk*8 + 4]) = s1;
    }
    pb = *reinterpret_cast<const uint4*>(Pg);
    *reinterpret_cast<uint4*>(&Bs[0][brow][bcol]) = pb;
    __syncthreads();

    const int NT = K / 32;
    int buf = 0;
    for (int kt = 0; kt < NT; kt++) {
        if (kt + 1 < NT) {
            if (aload) {
                pa0 = *reinterpret_cast<const uint4*>(Ag + (kt + 1) * 32);
                pa1 = *reinterpret_cast<const uint4*>(Ag + (kt + 1) * 32 + 8);
            }
            pb = *reinterpret_cast<const uint4*>(Pg + (size_t)(kt + 1) * 16 * N);
        }
        #pragma unroll
        for (int ks = 0; ks < 16; ks += 8) {
            uint32_t af[2][4], bf[NF][2];
            #pragma unroll
            for (int mf = 0; mf < 2; mf++) {
                int rb = wm * 32 + mf * 16;
                uint2 u1 = *reinterpret_cast<const uint2*>(&As[buf][rb + g][ks + 2*c]);
                uint2 u2 = *reinterpret_cast<const uint2*>(&As[buf][rb + g + 8][ks + 2*c]);
                af[mf][0] = u1.x; af[mf][2] = u1.y;
                af[mf][1] = u2.x; af[mf][3] = u2.y;
            }
            #pragma unroll
            for (int nf = 0; nf < NF; nf++) {
                int nb = wn * (NF*8) + nf * 8 + g;
                bf[nf][0] = Bs[buf][ks + c][nb];
                bf[nf][1] = Bs[buf][ks + c + 4][nb];
            }
            #pragma unroll
            for (int mf = 0; mf < 2; mf++)
                #pragma unroll
                for (int nf = 0; nf < NF; nf++)
                    mma_bf16(acc[mf][nf], af[mf], bf[nf]);
        }
        if (kt + 1 < NT) {
            int nb = buf ^ 1;
            if (aload) {
                uint4 s0 = make_uint4(pa0.x, pa1.x, pa0.y, pa1.y);
                uint4 s1 = make_uint4(pa0.z, pa1.z, pa0.w, pa1.w);
                *reinterpret_cast<uint4*>(&As[nb][arow][ablk*8])     = s0;
                *reinterpret_cast<uint4*>(&As[nb][arow][ablk*8 + 4]) = s1;
            }
            *reinterpret_cast<uint4*>(&Bs[nb][brow][bcol]) = pb;
        }
        __syncthreads();
        buf ^= 1;
    }

    // epilogue
    #pragma unroll
    for (int mf = 0; mf < 2; mf++) {
        #pragma unroll
        for (int nf = 0; nf < NF; nf++) {
            int row0 = bm + wm * 32 + mf * 16 + g;
            int col  = bn + wn * (NF*8) + nf * 8 + c * 2;
            float bx = bias[col], by = bias[col + 1];
            #pragma unroll
            for (int h = 0; h < 2; h++) {
                int row = row0 + h * 8;
                float v0 = acc[mf][nf][h * 2 + 0] + bx;
                float v1 = acc[mf][nf][h * 2 + 1] + by;
                if (EPI == 1) {
                    v0 *= normcdff(v0);
                    v1 *= normcdff(v1);
                } else if (EPI == 2) {
                    float2 r = *reinterpret_cast<const float2*>(res + (size_t)row * N + col);
                    v0 += r.x; v1 += r.y;
                }
                if (EPI == 3) {
                    // qkv split: q fp32 pre-scaled, k/v bf16
                    if (col < 256) {
                        store2((float*)C + (size_t)row * 256 + col, v0 * SCALE, v1 * SCALE);
                    } else if (col < 512) {
                        store2(kout + (size_t)row * 256 + (col - 256), v0, v1);
                    } else {
                        store2(vout + (size_t)row * 256 + (col - 512), v0, v1);
                    }
                } else {
                    store2(C + (size_t)row * N + col, v0, v1);
                }
            }
        }
    }
}

// ---------------- dilated neighborhood attention ----------------
// one block per token; 8 head-warps; q fp32 (pre-scaled), k/v bf16.
// warp split into 4 groups of 8 lanes; neighbor tables in shared.
// dot products / PV accumulation use packed f32x2 fma.
__global__ void attn_kernel(const float* __restrict__ q, const __nv_bfloat16* __restrict__ k,
                            const __nv_bfloat16* __restrict__ v, const float* __restrict__ rpb,
                            __nv_bfloat16* __restrict__ ctx)
{
    __shared__ float sc[HEADS][52];
    __shared__ int snt[49];   // neighbor_tok * 256
    __shared__ int sbi[49];   // rpb index within a head's 13x13 table

    const int tok  = blockIdx.x;
    const int head = threadIdx.y;
    const int lane = threadIdx.x;
    const int tid  = head * 32 + lane;
    const int gg = lane >> 3, e = lane & 7;

    if (tid < 49) {
        const int i = tok >> 6, j = tok & 63;
        int gi = i >> 1, ri = i & 1;
        int si = gi - 3; si = si < 0 ? 0 : (si > 25 ? 25 : si);
        int gj = j >> 1, rj = j & 1;
        int sj = gj - 3; sj = sj < 0 ? 0 : (sj > 25 ? 25 : sj);
        int kh = tid / 7, kw = tid - kh * 7;
        int ki = (si + kh) * 2 + ri;
        int kj = (sj + kw) * 2 + rj;
        snt[tid] = (ki * WW + kj) * CC;
        sbi[tid] = (si - gi + 6 + kh) * 13 + (sj - gj + 6 + kw);
    }
    __syncthreads();

    const int choff = head*HD + e*4;
    float4 q4 = ld4(q + (size_t)tok*CC + choff);       // pre-scaled
    float2 q01 = make_float2(q4.x, q4.y), q23 = make_float2(q4.z, q4.w);
    const float* biasrow = rpb + head*169;

    // pass 1: scores (4 neighbors in flight per warp iteration)
    #pragma unroll
    for (int t = 0; t < 13; t++) {
        int n = t*4 + gg;
        bool valid = n < 49;
        float partial = 0.f;
        if (valid) {
            uint2 u = *reinterpret_cast<const uint2*>(k + snt[n] + choff);
            float2 p2 = fmul2(q01, bf2f(u.x));
            p2 = ffma2(q23, bf2f(u.y), p2);
            partial = p2.x + p2.y;
        }
        partial += __shfl_xor_sync(0xffffffffu, partial, 1);
        partial += __shfl_xor_sync(0xffffffffu, partial, 2);
        partial += __shfl_xor_sync(0xffffffffu, partial, 4);
        if (valid && e == 0)
            sc[head][n] = partial + biasrow[sbi[n]];
    }
    __syncwarp();

    // softmax over 49 entries
    float s1 = sc[head][lane];
    float s2 = (lane < 17) ? sc[head][lane + 32] : -1e30f;
    float m = fmaxf(s1, s2);
    #pragma unroll
    for (int o = 16; o; o >>= 1) m = fmaxf(m, __shfl_xor_sync(0xffffffffu, m, o));
    float e1 = __expf(s1 - m);
    float e2 = (lane < 17) ? __expf(s2 - m) : 0.f;
    float ssum = e1 + e2;
    #pragma unroll
    for (int o = 16; o; o >>= 1) ssum += __shfl_xor_sync(0xffffffffu, ssum, o);
    sc[head][lane] = e1;
    if (lane < 17) sc[head][lane + 32] = e2;
    __syncwarp();
    const float inv = 1.0f / ssum;

    // pass 2: weighted V (packed f32x2)
    float2 a01 = make_float2(0.f, 0.f), a23 = make_float2(0.f, 0.f);
    #pragma unroll
    for (int t = 0; t < 13; t++) {
        int n = t*4 + gg;
        if (n < 49) {
            float w = sc[head][n];
            float2 w2 = make_float2(w, w);
            uint2 u = *reinterpret_cast<const uint2*>(v + snt[n] + choff);
            a01 = ffma2(w2, bf2f(u.x), a01);
            a23 = ffma2(w2, bf2f(u.y), a23);
        }
    }
    #pragma unroll
    for (int o = 8; o <= 16; o <<= 1) {
        a01.x += __shfl_xor_sync(0xffffffffu, a01.x, o);
        a01.y += __shfl_xor_sync(0xffffffffu, a01.y, o);
        a23.x += __shfl_xor_sync(0xffffffffu, a23.x, o);
        a23.y += __shfl_xor_sync(0xffffffffu, a23.y, o);
    }
    if (gg == 0) {
        __nv_bfloat162 o0 = __floats2bfloat162_rn(a01.x*inv, a01.y*inv);
        __nv_bfloat162 o1 = __floats2bfloat162_rn(a23.x*inv, a23.y*inv);
        uint2 pk = make_uint2(*reinterpret_cast<uint32_t*>(&o0),
                              *reinterpret_cast<uint32_t*>(&o1));
        *reinterpret_cast<uint2*>(ctx + (size_t)tok*CC + choff) = pk;
    }
}

// ---------------- launch ----------------
extern "C" void kernel_launch(void* const* d_in, const int* in_sizes, int n_in,
                              void* d_out, int out_size)
{
    const float* x     = (const float*)d_in[0];
    const float* ln1_g = (const float*)d_in[1];
    const float* ln1_b = (const float*)d_in[2];
    const float* wq    = (const float*)d_in[3];
    const float* bq    = (const float*)d_in[4];
    const float* wk    = (const float*)d_in[5];
    const float* bk    = (const float*)d_in[6];
    const float* wv    = (const float*)d_in[7];
    const float* bv    = (const float*)d_in[8];
    const float* rpb   = (const float*)d_in[9];
    const float* wo    = (const float*)d_in[10];
    const float* bo    = (const float*)d_in[11];
    const float* ln2_g = (const float*)d_in[12];
    const float* ln2_b = (const float*)d_in[13];
    const float* w1    = (const float*)d_in[14];
    const float* b1    = (const float*)d_in[15];
    const float* w2    = (const float*)d_in[16];
    const float* b2    = (const float*)d_in[17];
    float* out = (float*)d_out;

    __nv_bfloat16 *hs, *kq, *vq, *ctxp, *y, *t;
    float *qq, *hs2, *bqkv;
    uint32_t *wqkv_p, *wo_p, *w1_p, *w2_p;
    cudaGetSymbolAddress((void**)&hs,     g_hs);
    cudaGetSymbolAddress((void**)&qq,     g_q);
    cudaGetSymbolAddress((void**)&kq,     g_k);
    cudaGetSymbolAddress((void**)&vq,     g_v);
    cudaGetSymbolAddress((void**)&ctxp,   g_ctx);
    cudaGetSymbolAddress((void**)&hs2,    g_hs2);
    cudaGetSymbolAddress((void**)&y,      g_y);
    cudaGetSymbolAddress((void**)&t,      g_t);
    cudaGetSymbolAddress((void**)&wqkv_p, g_wqkv_p);
    cudaGetSymbolAddress((void**)&wo_p,   g_wo_p);
    cudaGetSymbolAddress((void**)&w1_p,   g_w1_p);
    cudaGetSymbolAddress((void**)&w2_p,   g_w2_p);
    cudaGetSymbolAddress((void**)&bqkv,   g_bqkv);

    // 1) pack weights to bf16 k-pair layout
    pack_kernel<<<1536, 256>>>(wq, wk, wv, wo, w1, w2, bq, bk, bv);

    // 2) LN1 -> bf16
    ln_kernel<<<NTOK/8, 256>>>(x, ln1_g, ln1_b, hs);

    // 3) QKV GEMM: [4096,256] @ [256,768] -> q fp32(scaled) | k bf16 | v bf16
    {
        dim3 grid(768/64, NTOK/128);
        bgemm_kernel<3, float, 128><<<grid, 256>>>(hs, wqkv_p, bqkv, nullptr, qq,
                                                   kq, vq, NTOK, 768, CC);
    }

    // 4) attention -> bf16 ctx
    {
        dim3 blk(32, HEADS);
        attn_kernel<<<NTOK, blk>>>(qq, kq, vq, rpb, ctxp);
    }

    // 5) wo GEMM + residual(x): hs2 = ctx@wo + bo + x  (fp32), BM=64
    {
        dim3 grid(CC/64, NTOK/64);
        bgemm_kernel<2, float, 64><<<grid, 256>>>(ctxp, wo_p, bo, x, hs2,
                                                  nullptr, nullptr, NTOK, CC, CC);
    }

    // 6) LN2 -> bf16
    ln_kernel<<<NTOK/8, 256>>>(hs2, ln2_g, ln2_b, y);

    // 7) w1 GEMM + exact GELU -> bf16 t
    {
        dim3 grid(FF/64, NTOK/128);
        bgemm_kernel<1, __nv_bfloat16, 128><<<grid, 256>>>(y, w1_p, b1, nullptr, t,
                                                           nullptr, nullptr, NTOK, FF, CC);
    }

    // 8) w2 GEMM + residual(hs2): out = t@w2 + b2 + hs2  (fp32), BM=64
    {
        dim3 grid(CC/64, NTOK/64);
        bgemm_kernel<2, float, 64><<<grid, 256>>>(t, w2_p, b2, hs2, out,
                                                  nullptr, nullptr, NTOK, CC, FF);
    }
}

// round 7
// speedup vs baseline: 3.2046x; 1.0582x over previous
#include <cuda_runtime.h>
#include <cuda_bf16.h>
#include <math.h>
#include <stdint.h>

// Problem constants
#define BB 1
#define HH 64
#define WW 64
#define CC 256
#define HEADS 8
#define HD 32
#define KK 7
#define DIL 2
#define FF 1024
#define NTOK (HH*WW)            // 4096
#define SCALE 0.17677669529663687f  // 1/sqrt(32)

// ---------------- scratch (device globals; no runtime alloc) ----------------
__device__ __nv_bfloat16 g_hs [NTOK*CC];     // LN1(x), bf16 (GEMM A)
__device__ float         g_q  [NTOK*CC];     // q fp32, pre-scaled
__device__ __nv_bfloat16 g_k  [NTOK*CC];     // k bf16
__device__ __nv_bfloat16 g_v  [NTOK*CC];     // v bf16
__device__ __nv_bfloat16 g_ctx[NTOK*CC];     // attention context, bf16
__device__ float         g_hs2[NTOK*CC];     // x + attn_out, fp32
__device__ __nv_bfloat16 g_y  [NTOK*CC];     // LN2(hs2), bf16
__device__ __nv_bfloat16 g_t  [NTOK*FF];     // gelu(y@w1+b1), bf16
// bf16 weights, plain [k][n] layout
__device__ __nv_bfloat16 g_wqkv_b[256*768];
__device__ __nv_bfloat16 g_wo_b  [256*256];
__device__ __nv_bfloat16 g_w1_b  [256*1024];
__device__ __nv_bfloat16 g_w2_b  [1024*256];
__device__ float         g_bqkv  [768];

__device__ __forceinline__ float4 ld4(const float* p) {
    return *reinterpret_cast<const float4*>(p);
}
__device__ __forceinline__ float2 bf2f(uint32_t u) {
    __nv_bfloat162 h = *reinterpret_cast<__nv_bfloat162*>(&u);
    return __bfloat1622float2(h);
}
__device__ __forceinline__ float2 ffma2(float2 a, float2 b, float2 c) {
    float2 d;
    asm("fma.rn.f32x2 %0, %1, %2, %3;"
        : "=l"(*reinterpret_cast<uint64_t*>(&d))
        : "l"(*reinterpret_cast<const uint64_t*>(&a)),
          "l"(*reinterpret_cast<const uint64_t*>(&b)),
          "l"(*reinterpret_cast<const uint64_t*>(&c)));
    return d;
}
__device__ __forceinline__ float2 fmul2(float2 a, float2 b) {
    float2 d;
    asm("mul.rn.f32x2 %0, %1, %2;"
        : "=l"(*reinterpret_cast<uint64_t*>(&d))
        : "l"(*reinterpret_cast<const uint64_t*>(&a)),
          "l"(*reinterpret_cast<const uint64_t*>(&b)));
    return d;
}
__device__ __forceinline__ uint32_t smem_u32(const void* p) {
    uint32_t a;
    asm("{ .reg .u64 t; cvta.to.shared.u64 t, %1; cvt.u32.u64 %0, t; }"
        : "=r"(a) : "l"(p));
    return a;
}
__device__ __forceinline__ void ldsm_x4(uint32_t (&r)[4], uint32_t addr) {
    asm volatile("ldmatrix.sync.aligned.m8n8.x4.shared.b16 {%0,%1,%2,%3}, [%4];"
        : "=r"(r[0]), "=r"(r[1]), "=r"(r[2]), "=r"(r[3]) : "r"(addr));
}
__device__ __forceinline__ void ldsm_x4_t(uint32_t (&r)[4], uint32_t addr) {
    asm volatile("ldmatrix.sync.aligned.m8n8.x4.trans.shared.b16 {%0,%1,%2,%3}, [%4];"
        : "=r"(r[0]), "=r"(r[1]), "=r"(r[2]), "=r"(r[3]) : "r"(addr));
}
__device__ __forceinline__ void mma_bf16(float (&d)[4], const uint32_t (&a)[4],
                                         const uint32_t (&b)[2]) {
    asm volatile(
        "mma.sync.aligned.m16n8k16.row.col.f32.bf16.bf16.f32 "
        "{%0,%1,%2,%3}, {%4,%5,%6,%7}, {%8,%9}, {%0,%1,%2,%3};\n"
        : "+f"(d[0]), "+f"(d[1]), "+f"(d[2]), "+f"(d[3])
        : "r"(a[0]), "r"(a[1]), "r"(a[2]), "r"(a[3]),
          "r"(b[0]), "r"(b[1]));
}

// ---------------- weight pack: fp32 -> bf16 plain [k][n] ----------------
__global__ void pack_kernel(const float* __restrict__ wq, const float* __restrict__ wk,
                            const float* __restrict__ wv, const float* __restrict__ wo,
                            const float* __restrict__ w1, const float* __restrict__ w2,
                            const float* __restrict__ bq, const float* __restrict__ bk,
                            const float* __restrict__ bv)
{
    int idx = blockIdx.x * 256 + threadIdx.x;
    if (idx < 196608) {                      // wqkv: 256 x 768
        int k = idx / 768, n = idx % 768;
        float v;
        if      (n < 256) v = wq[k*256 + n];
        else if (n < 512) v = wk[k*256 + (n-256)];
        else              v = wv[k*256 + (n-512)];
        g_wqkv_b[idx] = __float2bfloat16(v);
    } else if (idx < 262144) {               // wo: 256 x 256
        int t = idx - 196608;
        g_wo_b[t] = __float2bfloat16(wo[t]);
    } else if (idx < 524288) {               // w1: 256 x 1024
        int t = idx - 262144;
        g_w1_b[t] = __float2bfloat16(w1[t]);
    } else if (idx < 786432) {               // w2: 1024 x 256
        int t = idx - 524288;
        g_w2_b[t] = __float2bfloat16(w2[t]);
    }
    if (idx < 768) {
        float v;
        if      (idx < 256) v = bq[idx];
        else if (idx < 512) v = bk[idx - 256];
        else                v = bv[idx - 512];
        g_bqkv[idx] = v;
    }
}

// ---------------- LayerNorm: one warp per row, 8 rows/block ----------------
__global__ void ln_kernel(const float* __restrict__ x, const float* __restrict__ g,
                          const float* __restrict__ b, __nv_bfloat16* __restrict__ out)
{
    const int row  = blockIdx.x * 8 + (threadIdx.x >> 5);
    const int lane = threadIdx.x & 31;
    const float* xr = x + (size_t)row * CC + lane * 8;
    float4 v0 = ld4(xr), v1 = ld4(xr + 4);
    float s  = v0.x + v0.y + v0.z + v0.w + v1.x + v1.y + v1.z + v1.w;
    float sq = v0.x*v0.x + v0.y*v0.y + v0.z*v0.z + v0.w*v0.w
             + v1.x*v1.x + v1.y*v1.y + v1.z*v1.z + v1.w*v1.w;
    #pragma unroll
    for (int o = 16; o; o >>= 1) {
        s  += __shfl_xor_sync(0xffffffffu, s,  o);
        sq += __shfl_xor_sync(0xffffffffu, sq, o);
    }
    float mean = s * (1.0f/CC);
    float var  = sq * (1.0f/CC) - mean*mean;
    float inv  = rsqrtf(var + 1e-5f);
    float4 g0 = ld4(g + lane*8), g1 = ld4(g + lane*8 + 4);
    float4 b0 = ld4(b + lane*8), b1 = ld4(b + lane*8 + 4);
    __nv_bfloat162 o0 = __floats2bfloat162_rn((v0.x-mean)*inv*g0.x + b0.x,
                                              (v0.y-mean)*inv*g0.y + b0.y);
    __nv_bfloat162 o1 = __floats2bfloat162_rn((v0.z-mean)*inv*g0.z + b0.z,
                                              (v0.w-mean)*inv*g0.w + b0.w);
    __nv_bfloat162 o2 = __floats2bfloat162_rn((v1.x-mean)*inv*g1.x + b1.x,
                                              (v1.y-mean)*inv*g1.y + b1.y);
    __nv_bfloat162 o3 = __floats2bfloat162_rn((v1.z-mean)*inv*g1.z + b1.z,
                                              (v1.w-mean)*inv*g1.w + b1.w);
    uint4 pk = make_uint4(*reinterpret_cast<uint32_t*>(&o0),
                          *reinterpret_cast<uint32_t*>(&o1),
                          *reinterpret_cast<uint32_t*>(&o2),
                          *reinterpret_cast<uint32_t*>(&o3));
    *reinterpret_cast<uint4*>(out + (size_t)row * CC + lane * 8) = pk;
}

// ---------------- bf16 tensor-core GEMM with ldmatrix ----------------
// C[M,N] = A[M,K] @ W[K,N] (+ epilogue). A,W bf16 row-major. fp32 accum.
// BM_ in {128,64}, BN=64, BK=32, 8 warps. BM128: 4Mx2N warps, warp 32x32.
// BM64: 2Mx4N warps, warp 32x16. Double-buffered smem.
// A smem: rows of 32 bf16, stride 80B (r*80 mod 128 distinct -> LDSM clean).
// B smem: [k][n] rows of 64 bf16, stride 144B (r*144 mod 128 = r*16 distinct).
// EPI 0: +bias ; EPI 1: gelu(+bias) ; EPI 2: +bias + res ; EPI 3: qkv split
#define A_STR 20   // uint32 per A row (80B)
#define B_STR 36   // uint32 per B row (144B)

__device__ __forceinline__ void store2(float* p, float v0, float v1) {
    *reinterpret_cast<float2*>(p) = make_float2(v0, v1);
}
__device__ __forceinline__ void store2(__nv_bfloat16* p, float v0, float v1) {
    *reinterpret_cast<__nv_bfloat162*>(p) = __floats2bfloat162_rn(v0, v1);
}

template<int EPI, typename OutT, int BM_>
__global__ void __launch_bounds__(256, 2)
bgemm_kernel(const __nv_bfloat16* __restrict__ A, const __nv_bfloat16* __restrict__ W,
             const float* __restrict__ bias, const float* __restrict__ res,
             OutT* __restrict__ C, __nv_bfloat16* __restrict__ kout,
             __nv_bfloat16* __restrict__ vout, int M, int N, int K)
{
    constexpr int WM = (BM_ == 128) ? 4 : 2;
    constexpr int WN = 8 / WM;
    constexpr int NF = 64 / (WN * 8);          // 4 (BM128) or 2 (BM64)

    __shared__ __align__(16) uint32_t As[2][BM_ * A_STR];
    __shared__ __align__(16) uint32_t Bs[2][32 * B_STR];

    const int tid  = threadIdx.x;
    const int lane = tid & 31, warp = tid >> 5;
    const int wm = warp % WM, wn = warp / WM;
    const int g = lane >> 2, c = lane & 3;
    const int bm = blockIdx.y * BM_, bn = blockIdx.x * 64;

    // global load mapping
    const int arow = (tid >> 1) % BM_, ahalf = (tid & 1);   // 32B of one A row
    const bool aload = (BM_ == 128) || (tid < 128);
    const int bkrow = tid >> 3, bnch = (tid & 7) * 8;       // 16B of one B row
    const __nv_bfloat16* Ag = A + (size_t)(bm + arow) * K + ahalf * 16;
    const __nv_bfloat16* Wg = W + (size_t)bkrow * N + bn + bnch;

    // smem store offsets (uint32 units)
    const int asto = arow * A_STR + ahalf * 8;
    const int bsto = bkrow * B_STR + (tid & 7) * 4;

    // ldmatrix byte addresses (per buffer base added later)
    const uint32_t aBase = smem_u32(As);
    const uint32_t bBase = smem_u32(Bs);
    // A: row = wm*32 + mf*16 + (lane&15), col byte = ks*2 + (lane>>4)*16
    const uint32_t aoff = (uint32_t)(wm*32 + (lane & 15)) * 80 + (lane >> 4) * 16;
    // B: k row = ks + (lane&15), n = wn*(NF*8) + p*16 + (lane>>4)*8
    const uint32_t boff = (uint32_t)(lane & 15) * 144 +
                          (uint32_t)(wn*(NF*8) + (lane >> 4)*8) * 2;

    float acc[2][NF][4];
    #pragma unroll
    for (int mf = 0; mf < 2; mf++)
        #pragma unroll
        for (int nf = 0; nf < NF; nf++)
            #pragma unroll
            for (int e = 0; e < 4; e++) acc[mf][nf][e] = 0.f;

    // prologue
    uint4 pa0, pa1, pb;
    if (aload) {
        pa0 = *reinterpret_cast<const uint4*>(Ag);
        pa1 = *reinterpret_cast<const uint4*>(Ag + 8);
        *reinterpret_cast<uint4*>(&As[0][asto])     = pa0;
        *reinterpret_cast<uint4*>(&As[0][asto + 4]) = pa1;
    }
    pb = *reinterpret_cast<const uint4*>(Wg);
    *reinterpret_cast<uint4*>(&Bs[0][bsto]) = pb;
    __syncthreads();

    const int NT = K / 32;
    int buf = 0;
    for (int kt = 0; kt < NT; kt++) {
        if (kt + 1 < NT) {
            if (aload) {
                pa0 = *reinterpret_cast<const uint4*>(Ag + (kt + 1) * 32);
                pa1 = *reinterpret_cast<const uint4*>(Ag + (kt + 1) * 32 + 8);
            }
            pb = *reinterpret_cast<const uint4*>(Wg + (size_t)(kt + 1) * 32 * N);
        }
        const uint32_t ab = aBase + (uint32_t)(buf * BM_ * A_STR * 4);
        const uint32_t bb = bBase + (uint32_t)(buf * 32 * B_STR * 4);
        #pragma unroll
        for (int ks = 0; ks < 32; ks += 16) {
            uint32_t af[2][4], bf[NF][2];
            #pragma unroll
            for (int mf = 0; mf < 2; mf++)
                ldsm_x4(af[mf], ab + aoff + (uint32_t)(mf * 16 * 80 + ks * 2));
            #pragma unroll
            for (int p = 0; p < NF/2; p++) {
                uint32_t br[4];
                ldsm_x4_t(br, bb + boff + (uint32_t)(ks * 144 + p * 32));
                bf[2*p][0]   = br[0]; bf[2*p][1]   = br[1];
                bf[2*p+1][0] = br[2]; bf[2*p+1][1] = br[3];
            }
            #pragma unroll
            for (int mf = 0; mf < 2; mf++)
                #pragma unroll
                for (int nf = 0; nf < NF; nf++)
                    mma_bf16(acc[mf][nf], af[mf], bf[nf]);
        }
        if (kt + 1 < NT) {
            int nb = buf ^ 1;
            if (aload) {
                *reinterpret_cast<uint4*>(&As[nb][asto])     = pa0;
                *reinterpret_cast<uint4*>(&As[nb][asto + 4]) = pa1;
            }
            *reinterpret_cast<uint4*>(&Bs[nb][bsto]) = pb;
        }
        __syncthreads();
        buf ^= 1;
    }

    // epilogue
    #pragma unroll
    for (int mf = 0; mf < 2; mf++) {
        #pragma unroll
        for (int nf = 0; nf < NF; nf++) {
            int row0 = bm + wm * 32 + mf * 16 + g;
            int col  = bn + wn * (NF*8) + nf * 8 + c * 2;
            float bx = bias[col], by = bias[col + 1];
            #pragma unroll
            for (int h = 0; h < 2; h++) {
                int row = row0 + h * 8;
                float v0 = acc[mf][nf][h * 2 + 0] + bx;
                float v1 = acc[mf][nf][h * 2 + 1] + by;
                if (EPI == 1) {
                    v0 *= normcdff(v0);
                    v1 *= normcdff(v1);
                } else if (EPI == 2) {
                    float2 r = *reinterpret_cast<const float2*>(res + (size_t)row * N + col);
                    v0 += r.x; v1 += r.y;
                }
                if (EPI == 3) {
                    if (col < 256) {
                        store2((float*)C + (size_t)row * 256 + col, v0 * SCALE, v1 * SCALE);
                    } else if (col < 512) {
                        store2(kout + (size_t)row * 256 + (col - 256), v0, v1);
                    } else {
                        store2(vout + (size_t)row * 256 + (col - 512), v0, v1);
                    }
                } else {
                    store2(C + (size_t)row * N + col, v0, v1);
                }
            }
        }
    }
}

// ---------------- dilated neighborhood attention ----------------
// one block per token; 8 head-warps; q fp32 (pre-scaled), k/v bf16.
// warp split into 8 groups of 4 lanes; each lane owns 8 channels (uint4 loads).
__global__ void attn_kernel(const float* __restrict__ q, const __nv_bfloat16* __restrict__ k,
                            const __nv_bfloat16* __restrict__ v, const float* __restrict__ rpb,
                            __nv_bfloat16* __restrict__ ctx)
{
    __shared__ float sc[HEADS][52];
    __shared__ int snt[49];   // neighbor_tok * 256
    __shared__ int sbi[49];   // rpb index within a head's 13x13 table

    const int tok  = blockIdx.x;
    const int head = threadIdx.y;
    const int lane = threadIdx.x;
    const int tid  = head * 32 + lane;
    const int gg = lane >> 2, e = lane & 3;

    if (tid < 49) {
        const int i = tok >> 6, j = tok & 63;
        int gi = i >> 1, ri = i & 1;
        int si = gi - 3; si = si < 0 ? 0 : (si > 25 ? 25 : si);
        int gj = j >> 1, rj = j & 1;
        int sj = gj - 3; sj = sj < 0 ? 0 : (sj > 25 ? 25 : sj);
        int kh = tid / 7, kw = tid - kh * 7;
        int ki = (si + kh) * 2 + ri;
        int kj = (sj + kw) * 2 + rj;
        snt[tid] = (ki * WW + kj) * CC;
        sbi[tid] = (si - gi + 6 + kh) * 13 + (sj - gj + 6 + kw);
    }
    __syncthreads();

    const int choff = head*HD + e*8;
    float4 qa = ld4(q + (size_t)tok*CC + choff);       // pre-scaled
    float4 qb = ld4(q + (size_t)tok*CC + choff + 4);
    float2 q0 = make_float2(qa.x, qa.y), q1 = make_float2(qa.z, qa.w);
    float2 q2 = make_float2(qb.x, qb.y), q3 = make_float2(qb.z, qb.w);
    const float* biasrow = rpb + head*169;

    // pass 1: scores (8 neighbors in flight per warp iteration)
    #pragma unroll
    for (int t = 0; t < 7; t++) {
        int n = t*8 + gg;
        bool valid = n < 49;
        float partial = 0.f;
        if (valid) {
            uint4 u = *reinterpret_cast<const uint4*>(k + snt[n] + choff);
            float2 p2 = fmul2(q0, bf2f(u.x));
            p2 = ffma2(q1, bf2f(u.y), p2);
            p2 = ffma2(q2, bf2f(u.z), p2);
            p2 = ffma2(q3, bf2f(u.w), p2);
            partial = p2.x + p2.y;
        }
        partial += __shfl_xor_sync(0xffffffffu, partial, 1);
        partial += __shfl_xor_sync(0xffffffffu, partial, 2);
        if (valid && e == 0)
            sc[head][n] = partial + biasrow[sbi[n]];
    }
    __syncwarp();

    // softmax over 49 entries
    float s1 = sc[head][lane];
    float s2 = (lane < 17) ? sc[head][lane + 32] : -1e30f;
    float m = fmaxf(s1, s2);
    #pragma unroll
    for (int o = 16; o; o >>= 1) m = fmaxf(m, __shfl_xor_sync(0xffffffffu, m, o));
    float e1 = __expf(s1 - m);
    float e2 = (lane < 17) ? __expf(s2 - m) : 0.f;
    float ssum = e1 + e2;
    #pragma unroll
    for (int o = 16; o; o >>= 1) ssum += __shfl_xor_sync(0xffffffffu, ssum, o);
    sc[head][lane] = e1;
    if (lane < 17) sc[head][lane + 32] = e2;
    __syncwarp();
    const float inv = 1.0f / ssum;

    // pass 2: weighted V (packed f32x2, 8 ch per lane)
    float2 a0 = make_float2(0.f,0.f), a1 = a0, a2 = a0, a3 = a0;
    #pragma unroll
    for (int t = 0; t < 7; t++) {
        int n = t*8 + gg;
        if (n < 49) {
            float w = sc[head][n];
            float2 w2 = make_float2(w, w);
            uint4 u = *reinterpret_cast<const uint4*>(v + snt[n] + choff);
            a0 = ffma2(w2, bf2f(u.x), a0);
            a1 = ffma2(w2, bf2f(u.y), a1);
            a2 = ffma2(w2, bf2f(u.z), a2);
            a3 = ffma2(w2, bf2f(u.w), a3);
        }
    }
    // reduce across the 8 groups (lanes ±4, ±8, ±16 hold same channel set)
    #pragma unroll
    for (int o = 4; o <= 16; o <<= 1) {
        a0.x += __shfl_xor_sync(0xffffffffu, a0.x, o);
        a0.y += __shfl_xor_sync(0xffffffffu, a0.y, o);
        a1.x += __shfl_xor_sync(0xffffffffu, a1.x, o);
        a1.y += __shfl_xor_sync(0xffffffffu, a1.y, o);
        a2.x += __shfl_xor_sync(0xffffffffu, a2.x, o);
        a2.y += __shfl_xor_sync(0xffffffffu, a2.y, o);
        a3.x += __shfl_xor_sync(0xffffffffu, a3.x, o);
        a3.y += __shfl_xor_sync(0xffffffffu, a3.y, o);
    }
    if (gg == 0) {
        __nv_bfloat162 o0 = __floats2bfloat162_rn(a0.x*inv, a0.y*inv);
        __nv_bfloat162 o1 = __floats2bfloat162_rn(a1.x*inv, a1.y*inv);
        __nv_bfloat162 o2 = __floats2bfloat162_rn(a2.x*inv, a2.y*inv);
        __nv_bfloat162 o3 = __floats2bfloat162_rn(a3.x*inv, a3.y*inv);
        uint4 pk = make_uint4(*reinterpret_cast<uint32_t*>(&o0),
                              *reinterpret_cast<uint32_t*>(&o1),
                              *reinterpret_cast<uint32_t*>(&o2),
                              *reinterpret_cast<uint32_t*>(&o3));
        *reinterpret_cast<uint4*>(ctx + (size_t)tok*CC + choff) = pk;
    }
}

// ---------------- launch ----------------
extern "C" void kernel_launch(void* const* d_in, const int* in_sizes, int n_in,
                              void* d_out, int out_size)
{
    const float* x     = (const float*)d_in[0];
    const float* ln1_g = (const float*)d_in[1];
    const float* ln1_b = (const float*)d_in[2];
    const float* wq    = (const float*)d_in[3];
    const float* bq    = (const float*)d_in[4];
    const float* wk    = (const float*)d_in[5];
    const float* bk    = (const float*)d_in[6];
    const float* wv    = (const float*)d_in[7];
    const float* bv    = (const float*)d_in[8];
    const float* rpb   = (const float*)d_in[9];
    const float* wo    = (const float*)d_in[10];
    const float* bo    = (const float*)d_in[11];
    const float* ln2_g = (const float*)d_in[12];
    const float* ln2_b = (const float*)d_in[13];
    const float* w1    = (const float*)d_in[14];
    const float* b1    = (const float*)d_in[15];
    const float* w2    = (const float*)d_in[16];
    const float* b2    = (const float*)d_in[17];
    float* out = (float*)d_out;

    __nv_bfloat16 *hs, *kq, *vq, *ctxp, *y, *t;
    __nv_bfloat16 *wqkv_b, *wo_b, *w1_b, *w2_b;
    float *qq, *hs2, *bqkv;
    cudaGetSymbolAddress((void**)&hs,     g_hs);
    cudaGetSymbolAddress((void**)&qq,     g_q);
    cudaGetSymbolAddress((void**)&kq,     g_k);
    cudaGetSymbolAddress((void**)&vq,     g_v);
    cudaGetSymbolAddress((void**)&ctxp,   g_ctx);
    cudaGetSymbolAddress((void**)&hs2,    g_hs2);
    cudaGetSymbolAddress((void**)&y,      g_y);
    cudaGetSymbolAddress((void**)&t,      g_t);
    cudaGetSymbolAddress((void**)&wqkv_b, g_wqkv_b);
    cudaGetSymbolAddress((void**)&wo_b,   g_wo_b);
    cudaGetSymbolAddress((void**)&w1_b,   g_w1_b);
    cudaGetSymbolAddress((void**)&w2_b,   g_w2_b);
    cudaGetSymbolAddress((void**)&bqkv,   g_bqkv);

    // 1) pack weights to bf16
    pack_kernel<<<3072, 256>>>(wq, wk, wv, wo, w1, w2, bq, bk, bv);

    // 2) LN1 -> bf16
    ln_kernel<<<NTOK/8, 256>>>(x, ln1_g, ln1_b, hs);

    // 3) QKV GEMM: [4096,256] @ [256,768] -> q fp32(scaled) | k bf16 | v bf16
    {
        dim3 grid(768/64, NTOK/128);
        bgemm_kernel<3, float, 128><<<grid, 256>>>(hs, wqkv_b, bqkv, nullptr, qq,
                                                   kq, vq, NTOK, 768, CC);
    }

    // 4) attention -> bf16 ctx
    {
        dim3 blk(32, HEADS);
        attn_kernel<<<NTOK, blk>>>(qq, kq, vq, rpb, ctxp);
    }

    // 5) wo GEMM + residual(x): hs2 = ctx@wo + bo + x  (fp32), BM=64
    {
        dim3 grid(CC/64, NTOK/64);
        bgemm_kernel<2, float, 64><<<grid, 256>>>(ctxp, wo_b, bo, x, hs2,
                                                  nullptr, nullptr, NTOK, CC, CC);
    }

    // 6) LN2 -> bf16
    ln_kernel<<<NTOK/8, 256>>>(hs2, ln2_g, ln2_b, y);

    // 7) w1 GEMM + exact GELU -> bf16 t
    {
        dim3 grid(FF/64, NTOK/128);
        bgemm_kernel<1, __nv_bfloat16, 128><<<grid, 256>>>(y, w1_b, b1, nullptr, t,
                                                           nullptr, nullptr, NTOK, FF, CC);
    }

    // 8) w2 GEMM + residual(hs2): out = t@w2 + b2 + hs2  (fp32), BM=64
    {
        dim3 grid(CC/64, NTOK/64);
        bgemm_kernel<2, float, 64><<<grid, 256>>>(t, w2_b, b2, hs2, out,
                                                  nullptr, nullptr, NTOK, CC, FF);
    }
}

// round 8
// speedup vs baseline: 3.4793x; 1.0857x over previous
#include <cuda_runtime.h>
#include <cuda_bf16.h>
#include <math.h>
#include <stdint.h>

// Problem constants
#define BB 1
#define HH 64
#define WW 64
#define CC 256
#define HEADS 8
#define HD 32
#define KK 7
#define DIL 2
#define FF 1024
#define NTOK (HH*WW)            // 4096
#define SCALE 0.17677669529663687f  // 1/sqrt(32)

// ---------------- scratch (device globals; no runtime alloc) ----------------
__device__ __nv_bfloat16 g_hs [NTOK*CC];     // LN1(x), bf16 (GEMM A)
__device__ float         g_q  [NTOK*CC];     // q fp32, pre-scaled
__device__ __nv_bfloat16 g_k  [NTOK*CC];     // k bf16
__device__ __nv_bfloat16 g_v  [NTOK*CC];     // v bf16
__device__ __nv_bfloat16 g_ctx[NTOK*CC];     // attention context, bf16
__device__ float         g_hs2[NTOK*CC];     // x + attn_out, fp32
__device__ __nv_bfloat16 g_y  [NTOK*CC];     // LN2(hs2), bf16
__device__ __nv_bfloat16 g_t  [NTOK*FF];     // gelu(y@w1+b1), bf16
// bf16 weights, plain [k][n] layout
__device__ __nv_bfloat16 g_wqkv_b[256*768];
__device__ __nv_bfloat16 g_wo_b  [256*256];
__device__ __nv_bfloat16 g_w1_b  [256*1024];
__device__ __nv_bfloat16 g_w2_b  [1024*256];
__device__ float         g_bqkv  [768];

__device__ __forceinline__ float4 ld4(const float* p) {
    return *reinterpret_cast<const float4*>(p);
}
__device__ __forceinline__ float2 bf2f(uint32_t u) {
    __nv_bfloat162 h = *reinterpret_cast<__nv_bfloat162*>(&u);
    return __bfloat1622float2(h);
}
__device__ __forceinline__ float2 ffma2(float2 a, float2 b, float2 c) {
    float2 d;
    asm("fma.rn.f32x2 %0, %1, %2, %3;"
        : "=l"(*reinterpret_cast<uint64_t*>(&d))
        : "l"(*reinterpret_cast<const uint64_t*>(&a)),
          "l"(*reinterpret_cast<const uint64_t*>(&b)),
          "l"(*reinterpret_cast<const uint64_t*>(&c)));
    return d;
}
__device__ __forceinline__ float2 fmul2(float2 a, float2 b) {
    float2 d;
    asm("mul.rn.f32x2 %0, %1, %2;"
        : "=l"(*reinterpret_cast<uint64_t*>(&d))
        : "l"(*reinterpret_cast<const uint64_t*>(&a)),
          "l"(*reinterpret_cast<const uint64_t*>(&b)));
    return d;
}
__device__ __forceinline__ uint32_t smem_u32(const void* p) {
    uint32_t a;
    asm("{ .reg .u64 t; cvta.to.shared.u64 t, %1; cvt.u32.u64 %0, t; }"
        : "=r"(a) : "l"(p));
    return a;
}
__device__ __forceinline__ void ldsm_x4(uint32_t (&r)[4], uint32_t addr) {
    asm volatile("ldmatrix.sync.aligned.m8n8.x4.shared.b16 {%0,%1,%2,%3}, [%4];"
        : "=r"(r[0]), "=r"(r[1]), "=r"(r[2]), "=r"(r[3]) : "r"(addr));
}
__device__ __forceinline__ void ldsm_x4_t(uint32_t (&r)[4], uint32_t addr) {
    asm volatile("ldmatrix.sync.aligned.m8n8.x4.trans.shared.b16 {%0,%1,%2,%3}, [%4];"
        : "=r"(r[0]), "=r"(r[1]), "=r"(r[2]), "=r"(r[3]) : "r"(addr));
}
__device__ __forceinline__ void mma_bf16(float (&d)[4], const uint32_t (&a)[4],
                                         const uint32_t (&b)[2]) {
    asm volatile(
        "mma.sync.aligned.m16n8k16.row.col.f32.bf16.bf16.f32 "
        "{%0,%1,%2,%3}, {%4,%5,%6,%7}, {%8,%9}, {%0,%1,%2,%3};\n"
        : "+f"(d[0]), "+f"(d[1]), "+f"(d[2]), "+f"(d[3])
        : "r"(a[0]), "r"(a[1]), "r"(a[2]), "r"(a[3]),
          "r"(b[0]), "r"(b[1]));
}

// ---------------- weight pack: fp32 -> bf16 plain [k][n] ----------------
__global__ void pack_kernel(const float* __restrict__ wq, const float* __restrict__ wk,
                            const float* __restrict__ wv, const float* __restrict__ wo,
                            const float* __restrict__ w1, const float* __restrict__ w2,
                            const float* __restrict__ bq, const float* __restrict__ bk,
                            const float* __restrict__ bv)
{
    int idx = blockIdx.x * 256 + threadIdx.x;
    if (idx < 196608) {                      // wqkv: 256 x 768
        int k = idx / 768, n = idx % 768;
        float v;
        if      (n < 256) v = wq[k*256 + n];
        else if (n < 512) v = wk[k*256 + (n-256)];
        else              v = wv[k*256 + (n-512)];
        g_wqkv_b[idx] = __float2bfloat16(v);
    } else if (idx < 262144) {               // wo: 256 x 256
        int t = idx - 196608;
        g_wo_b[t] = __float2bfloat16(wo[t]);
    } else if (idx < 524288) {               // w1: 256 x 1024
        int t = idx - 262144;
        g_w1_b[t] = __float2bfloat16(w1[t]);
    } else if (idx < 786432) {               // w2: 1024 x 256
        int t = idx - 524288;
        g_w2_b[t] = __float2bfloat16(w2[t]);
    }
    if (idx < 768) {
        float v;
        if      (idx < 256) v = bq[idx];
        else if (idx < 512) v = bk[idx - 256];
        else                v = bv[idx - 512];
        g_bqkv[idx] = v;
    }
}

// ---------------- LayerNorm: one warp per row, 8 rows/block ----------------
__global__ void ln_kernel(const float* __restrict__ x, const float* __restrict__ g,
                          const float* __restrict__ b, __nv_bfloat16* __restrict__ out)
{
    const int row  = blockIdx.x * 8 + (threadIdx.x >> 5);
    const int lane = threadIdx.x & 31;
    const float* xr = x + (size_t)row * CC + lane * 8;
    float4 v0 = ld4(xr), v1 = ld4(xr + 4);
    float s  = v0.x + v0.y + v0.z + v0.w + v1.x + v1.y + v1.z + v1.w;
    float sq = v0.x*v0.x + v0.y*v0.y + v0.z*v0.z + v0.w*v0.w
             + v1.x*v1.x + v1.y*v1.y + v1.z*v1.z + v1.w*v1.w;
    #pragma unroll
    for (int o = 16; o; o >>= 1) {
        s  += __shfl_xor_sync(0xffffffffu, s,  o);
        sq += __shfl_xor_sync(0xffffffffu, sq, o);
    }
    float mean = s * (1.0f/CC);
    float var  = sq * (1.0f/CC) - mean*mean;
    float inv  = rsqrtf(var + 1e-5f);
    float4 g0 = ld4(g + lane*8), g1 = ld4(g + lane*8 + 4);
    float4 b0 = ld4(b + lane*8), b1 = ld4(b + lane*8 + 4);
    __nv_bfloat162 o0 = __floats2bfloat162_rn((v0.x-mean)*inv*g0.x + b0.x,
                                              (v0.y-mean)*inv*g0.y + b0.y);
    __nv_bfloat162 o1 = __floats2bfloat162_rn((v0.z-mean)*inv*g0.z + b0.z,
                                              (v0.w-mean)*inv*g0.w + b0.w);
    __nv_bfloat162 o2 = __floats2bfloat162_rn((v1.x-mean)*inv*g1.x + b1.x,
                                              (v1.y-mean)*inv*g1.y + b1.y);
    __nv_bfloat162 o3 = __floats2bfloat162_rn((v1.z-mean)*inv*g1.z + b1.z,
                                              (v1.w-mean)*inv*g1.w + b1.w);
    uint4 pk = make_uint4(*reinterpret_cast<uint32_t*>(&o0),
                          *reinterpret_cast<uint32_t*>(&o1),
                          *reinterpret_cast<uint32_t*>(&o2),
                          *reinterpret_cast<uint32_t*>(&o3));
    *reinterpret_cast<uint4*>(out + (size_t)row * CC + lane * 8) = pk;
}

// ---------------- bf16 tensor-core GEMM with ldmatrix ----------------
#define A_STR 20   // uint32 per A row (80B)
#define B_STR 36   // uint32 per B row (144B)

__device__ __forceinline__ void store2(float* p, float v0, float v1) {
    *reinterpret_cast<float2*>(p) = make_float2(v0, v1);
}
__device__ __forceinline__ void store2(__nv_bfloat16* p, float v0, float v1) {
    *reinterpret_cast<__nv_bfloat162*>(p) = __floats2bfloat162_rn(v0, v1);
}

template<int EPI, typename OutT, int BM_>
__global__ void __launch_bounds__(256, 2)
bgemm_kernel(const __nv_bfloat16* __restrict__ A, const __nv_bfloat16* __restrict__ W,
             const float* __restrict__ bias, const float* __restrict__ res,
             OutT* __restrict__ C, __nv_bfloat16* __restrict__ kout,
             __nv_bfloat16* __restrict__ vout, int M, int N, int K)
{
    constexpr int WM = (BM_ == 128) ? 4 : 2;
    constexpr int WN = 8 / WM;
    constexpr int NF = 64 / (WN * 8);

    __shared__ __align__(16) uint32_t As[2][BM_ * A_STR];
    __shared__ __align__(16) uint32_t Bs[2][32 * B_STR];

    const int tid  = threadIdx.x;
    const int lane = tid & 31, warp = tid >> 5;
    const int wm = warp % WM, wn = warp / WM;
    const int g = lane >> 2, c = lane & 3;
    const int bm = blockIdx.y * BM_, bn = blockIdx.x * 64;

    const int arow = (tid >> 1) % BM_, ahalf = (tid & 1);
    const bool aload = (BM_ == 128) || (tid < 128);
    const int bkrow = tid >> 3, bnch = (tid & 7) * 8;
    const __nv_bfloat16* Ag = A + (size_t)(bm + arow) * K + ahalf * 16;
    const __nv_bfloat16* Wg = W + (size_t)bkrow * N + bn + bnch;

    const int asto = arow * A_STR + ahalf * 8;
    const int bsto = bkrow * B_STR + (tid & 7) * 4;

    const uint32_t aBase = smem_u32(As);
    const uint32_t bBase = smem_u32(Bs);
    const uint32_t aoff = (uint32_t)(wm*32 + (lane & 15)) * 80 + (lane >> 4) * 16;
    const uint32_t boff = (uint32_t)(lane & 15) * 144 +
                          (uint32_t)(wn*(NF*8) + (lane >> 4)*8) * 2;

    float acc[2][NF][4];
    #pragma unroll
    for (int mf = 0; mf < 2; mf++)
        #pragma unroll
        for (int nf = 0; nf < NF; nf++)
            #pragma unroll
            for (int e = 0; e < 4; e++) acc[mf][nf][e] = 0.f;

    uint4 pa0, pa1, pb;
    if (aload) {
        pa0 = *reinterpret_cast<const uint4*>(Ag);
        pa1 = *reinterpret_cast<const uint4*>(Ag + 8);
        *reinterpret_cast<uint4*>(&As[0][asto])     = pa0;
        *reinterpret_cast<uint4*>(&As[0][asto + 4]) = pa1;
    }
    pb = *reinterpret_cast<const uint4*>(Wg);
    *reinterpret_cast<uint4*>(&Bs[0][bsto]) = pb;
    __syncthreads();

    const int NT = K / 32;
    int buf = 0;
    for (int kt = 0; kt < NT; kt++) {
        if (kt + 1 < NT) {
            if (aload) {
                pa0 = *reinterpret_cast<const uint4*>(Ag + (kt + 1) * 32);
                pa1 = *reinterpret_cast<const uint4*>(Ag + (kt + 1) * 32 + 8);
            }
            pb = *reinterpret_cast<const uint4*>(Wg + (size_t)(kt + 1) * 32 * N);
        }
        const uint32_t ab = aBase + (uint32_t)(buf * BM_ * A_STR * 4);
        const uint32_t bb = bBase + (uint32_t)(buf * 32 * B_STR * 4);
        #pragma unroll
        for (int ks = 0; ks < 32; ks += 16) {
            uint32_t af[2][4], bf[NF][2];
            #pragma unroll
            for (int mf = 0; mf < 2; mf++)
                ldsm_x4(af[mf], ab + aoff + (uint32_t)(mf * 16 * 80 + ks * 2));
            #pragma unroll
            for (int p = 0; p < NF/2; p++) {
                uint32_t br[4];
                ldsm_x4_t(br, bb + boff + (uint32_t)(ks * 144 + p * 32));
                bf[2*p][0]   = br[0]; bf[2*p][1]   = br[1];
                bf[2*p+1][0] = br[2]; bf[2*p+1][1] = br[3];
            }
            #pragma unroll
            for (int mf = 0; mf < 2; mf++)
                #pragma unroll
                for (int nf = 0; nf < NF; nf++)
                    mma_bf16(acc[mf][nf], af[mf], bf[nf]);
        }
        if (kt + 1 < NT) {
            int nb = buf ^ 1;
            if (aload) {
                *reinterpret_cast<uint4*>(&As[nb][asto])     = pa0;
                *reinterpret_cast<uint4*>(&As[nb][asto + 4]) = pa1;
            }
            *reinterpret_cast<uint4*>(&Bs[nb][bsto]) = pb;
        }
        __syncthreads();
        buf ^= 1;
    }

    #pragma unroll
    for (int mf = 0; mf < 2; mf++) {
        #pragma unroll
        for (int nf = 0; nf < NF; nf++) {
            int row0 = bm + wm * 32 + mf * 16 + g;
            int col  = bn + wn * (NF*8) + nf * 8 + c * 2;
            float bx = bias[col], by = bias[col + 1];
            #pragma unroll
            for (int h = 0; h < 2; h++) {
                int row = row0 + h * 8;
                float v0 = acc[mf][nf][h * 2 + 0] + bx;
                float v1 = acc[mf][nf][h * 2 + 1] + by;
                if (EPI == 1) {
                    v0 *= normcdff(v0);
                    v1 *= normcdff(v1);
                } else if (EPI == 2) {
                    float2 r = *reinterpret_cast<const float2*>(res + (size_t)row * N + col);
                    v0 += r.x; v1 += r.y;
                }
                if (EPI == 3) {
                    if (col < 256) {
                        store2((float*)C + (size_t)row * 256 + col, v0 * SCALE, v1 * SCALE);
                    } else if (col < 512) {
                        store2(kout + (size_t)row * 256 + (col - 256), v0, v1);
                    } else {
                        store2(vout + (size_t)row * 256 + (col - 512), v0, v1);
                    }
                } else {
                    store2(C + (size_t)row * N + col, v0, v1);
                }
            }
        }
    }
}

// ---------------- dilated neighborhood attention: quad-token sharing --------
// Block = 2x2 same-parity token quad; warp = one head, all 4 tokens.
// Union window is 8x8 positions; iteration t = row, 4-lane group gg = column.
// Each K/V load (64B/lane-group) feeds 4 query dot/accumulates.
// Scores stored raw; bias + validity mask applied during softmax
// (invalid -> -1e30 -> exp 0, exactly matching the 49-way softmax).
__global__ void __launch_bounds__(256)
attn_kernel(const float* __restrict__ q, const __nv_bfloat16* __restrict__ k,
            const __nv_bfloat16* __restrict__ v, const float* __restrict__ rpb,
            __nv_bfloat16* __restrict__ ctx)
{
    __shared__ float sc[HEADS][4][64];

    const int head = threadIdx.y;
    const int lane = threadIdx.x;
    const int gg = lane >> 2, e = lane & 3;

    const int b   = blockIdx.x;
    const int bi  = b & 15, bj = (b >> 4) & 15, par = b >> 8;
    const int ri  = par & 1, rj = par >> 1;
    const int gi0 = bi * 2, gj0 = bj * 2;

    // clamped starts for the two group rows/cols
    int si0 = gi0 - 3; si0 = si0 < 0 ? 0 : (si0 > 25 ? 25 : si0);
    int si1 = gi0 - 2; si1 = si1 < 0 ? 0 : (si1 > 25 ? 25 : si1);
    int sj0 = gj0 - 3; sj0 = sj0 < 0 ? 0 : (sj0 > 25 ? 25 : sj0);
    int sj1 = gj0 - 2; sj1 = sj1 < 0 ? 0 : (sj1 > 25 ? 25 : sj1);
    const int dr1 = si1 - si0, dc1 = sj1 - sj0;   // 0 or 1

    // per-lane column constant (union column gg)
    int sjg = sj0 + gg; sjg = sjg > 31 ? 31 : sjg;
    const int kj = sjg * 2 + rj;
    const int choff = head * HD + e * 8;
    const int kcoff = kj * CC + choff;

    // load q for the 4 tokens (pre-scaled fp32)
    float2 qv[4][4];
    int toks[4];
    #pragma unroll
    for (int a = 0; a < 2; a++) {
        #pragma unroll
        for (int c = 0; c < 2; c++) {
            int tok = (2*(gi0 + a) + ri) * WW + 2*(gj0 + c) + rj;
            int qq_ = a*2 + c;
            toks[qq_] = tok;
            const float* qp = q + (size_t)tok * CC + choff;
            float4 qa = ld4(qp), qb = ld4(qp + 4);
            qv[qq_][0] = make_float2(qa.x, qa.y);
            qv[qq_][1] = make_float2(qa.z, qa.w);
            qv[qq_][2] = make_float2(qb.x, qb.y);
            qv[qq_][3] = make_float2(qb.z, qb.w);
        }
    }

    // pass 1: raw scores over the 8x8 union
    #pragma unroll
    for (int t = 0; t < 8; t++) {
        int sit = si0 + t; sit = sit > 31 ? 31 : sit;
        const int ki = sit * 2 + ri;
        uint4 u = *reinterpret_cast<const uint4*>(k + ki * (WW*CC) + kcoff);
        float2 k0 = bf2f(u.x), k1 = bf2f(u.y), k2 = bf2f(u.z), k3 = bf2f(u.w);
        #pragma unroll
        for (int qq_ = 0; qq_ < 4; qq_++) {
            float2 p2 = fmul2(qv[qq_][0], k0);
            p2 = ffma2(qv[qq_][1], k1, p2);
            p2 = ffma2(qv[qq_][2], k2, p2);
            p2 = ffma2(qv[qq_][3], k3, p2);
            float pt = p2.x + p2.y;
            pt += __shfl_xor_sync(0xffffffffu, pt, 1);
            pt += __shfl_xor_sync(0xffffffffu, pt, 2);
            if (e == 0) sc[head][qq_][t*8 + gg] = pt;
        }
    }
    __syncwarp();

    // softmax per query: add bias, mask invalid, normalize
    const float* br = rpb + head * 169;
    float inv[4];
    #pragma unroll
    for (int qq_ = 0; qq_ < 4; qq_++) {
        const int a = qq_ >> 1, c = qq_ & 1;
        const int dra = a ? dr1 : 0, dcc = c ? dc1 : 0;
        const int Bq = (si0 - gi0 - a + 6) * 13 + (sj0 - gj0 - c + 6);
        float s1, s2;
        {
            int p = lane, pr = p >> 3, pc = p & 7;
            bool val = (pr >= dra) && (pr < dra + 7) && (pc >= dcc) && (pc < dcc + 7);
            s1 = val ? sc[head][qq_][p] + br[Bq + pr*13 + pc] : -1e30f;
        }
        {
            int p = lane + 32, pr = p >> 3, pc = p & 7;
            bool val = (pr >= dra) && (pr < dra + 7) && (pc >= dcc) && (pc < dcc + 7);
            s2 = val ? sc[head][qq_][p] + br[Bq + pr*13 + pc] : -1e30f;
        }
        float m = fmaxf(s1, s2);
        #pragma unroll
        for (int o = 16; o; o >>= 1) m = fmaxf(m, __shfl_xor_sync(0xffffffffu, m, o));
        float e1 = __expf(s1 - m), e2 = __expf(s2 - m);
        float ss = e1 + e2;
        #pragma unroll
        for (int o = 16; o; o >>= 1) ss += __shfl_xor_sync(0xffffffffu, ss, o);
        sc[head][qq_][lane]      = e1;
        sc[head][qq_][lane + 32] = e2;
        inv[qq_] = 1.0f / ss;
    }
    __syncwarp();

    // pass 2: weighted V over the union
    float2 acc[4][4];
    #pragma unroll
    for (int qq_ = 0; qq_ < 4; qq_++)
        #pragma unroll
        for (int i = 0; i < 4; i++) acc[qq_][i] = make_float2(0.f, 0.f);

    #pragma unroll
    for (int t = 0; t < 8; t++) {
        int sit = si0 + t; sit = sit > 31 ? 31 : sit;
        const int ki = sit * 2 + ri;
        uint4 u = *reinterpret_cast<const uint4*>(v + ki * (WW*CC) + kcoff);
        float2 v0 = bf2f(u.x), v1 = bf2f(u.y), v2 = bf2f(u.z), v3 = bf2f(u.w);
        #pragma unroll
        for (int qq_ = 0; qq_ < 4; qq_++) {
            float w = sc[head][qq_][t*8 + gg];
            float2 w2 = make_float2(w, w);
            acc[qq_][0] = ffma2(w2, v0, acc[qq_][0]);
            acc[qq_][1] = ffma2(w2, v1, acc[qq_][1]);
            acc[qq_][2] = ffma2(w2, v2, acc[qq_][2]);
            acc[qq_][3] = ffma2(w2, v3, acc[qq_][3]);
        }
    }

    // reduce across the 8 column-groups (lanes xor 4,8,16 keep same e)
    #pragma unroll
    for (int o = 4; o <= 16; o <<= 1) {
        #pragma unroll
        for (int qq_ = 0; qq_ < 4; qq_++) {
            #pragma unroll
            for (int i = 0; i < 4; i++) {
                acc[qq_][i].x += __shfl_xor_sync(0xffffffffu, acc[qq_][i].x, o);
                acc[qq_][i].y += __shfl_xor_sync(0xffffffffu, acc[qq_][i].y, o);
            }
        }
    }
    if (gg == 0) {
        #pragma unroll
        for (int qq_ = 0; qq_ < 4; qq_++) {
            float iv = inv[qq_];
            __nv_bfloat162 o0 = __floats2bfloat162_rn(acc[qq_][0].x*iv, acc[qq_][0].y*iv);
            __nv_bfloat162 o1 = __floats2bfloat162_rn(acc[qq_][1].x*iv, acc[qq_][1].y*iv);
            __nv_bfloat162 o2 = __floats2bfloat162_rn(acc[qq_][2].x*iv, acc[qq_][2].y*iv);
            __nv_bfloat162 o3 = __floats2bfloat162_rn(acc[qq_][3].x*iv, acc[qq_][3].y*iv);
            uint4 pk = make_uint4(*reinterpret_cast<uint32_t*>(&o0),
                                  *reinterpret_cast<uint32_t*>(&o1),
                                  *reinterpret_cast<uint32_t*>(&o2),
                                  *reinterpret_cast<uint32_t*>(&o3));
            *reinterpret_cast<uint4*>(ctx + (size_t)toks[qq_]*CC + choff) = pk;
        }
    }
}

// ---------------- launch ----------------
extern "C" void kernel_launch(void* const* d_in, const int* in_sizes, int n_in,
                              void* d_out, int out_size)
{
    const float* x     = (const float*)d_in[0];
    const float* ln1_g = (const float*)d_in[1];
    const float* ln1_b = (const float*)d_in[2];
    const float* wq    = (const float*)d_in[3];
    const float* bq    = (const float*)d_in[4];
    const float* wk    = (const float*)d_in[5];
    const float* bk    = (const float*)d_in[6];
    const float* wv    = (const float*)d_in[7];
    const float* bv    = (const float*)d_in[8];
    const float* rpb   = (const float*)d_in[9];
    const float* wo    = (const float*)d_in[10];
    const float* bo    = (const float*)d_in[11];
    const float* ln2_g = (const float*)d_in[12];
    const float* ln2_b = (const float*)d_in[13];
    const float* w1    = (const float*)d_in[14];
    const float* b1    = (const float*)d_in[15];
    const float* w2    = (const float*)d_in[16];
    const float* b2    = (const float*)d_in[17];
    float* out = (float*)d_out;

    __nv_bfloat16 *hs, *kq, *vq, *ctxp, *y, *t;
    __nv_bfloat16 *wqkv_b, *wo_b, *w1_b, *w2_b;
    float *qq, *hs2, *bqkv;
    cudaGetSymbolAddress((void**)&hs,     g_hs);
    cudaGetSymbolAddress((void**)&qq,     g_q);
    cudaGetSymbolAddress((void**)&kq,     g_k);
    cudaGetSymbolAddress((void**)&vq,     g_v);
    cudaGetSymbolAddress((void**)&ctxp,   g_ctx);
    cudaGetSymbolAddress((void**)&hs2,    g_hs2);
    cudaGetSymbolAddress((void**)&y,      g_y);
    cudaGetSymbolAddress((void**)&t,      g_t);
    cudaGetSymbolAddress((void**)&wqkv_b, g_wqkv_b);
    cudaGetSymbolAddress((void**)&wo_b,   g_wo_b);
    cudaGetSymbolAddress((void**)&w1_b,   g_w1_b);
    cudaGetSymbolAddress((void**)&w2_b,   g_w2_b);
    cudaGetSymbolAddress((void**)&bqkv,   g_bqkv);

    // 1) pack weights to bf16
    pack_kernel<<<3072, 256>>>(wq, wk, wv, wo, w1, w2, bq, bk, bv);

    // 2) LN1 -> bf16
    ln_kernel<<<NTOK/8, 256>>>(x, ln1_g, ln1_b, hs);

    // 3) QKV GEMM: [4096,256] @ [256,768] -> q fp32(scaled) | k bf16 | v bf16
    {
        dim3 grid(768/64, NTOK/128);
        bgemm_kernel<3, float, 128><<<grid, 256>>>(hs, wqkv_b, bqkv, nullptr, qq,
                                                   kq, vq, NTOK, 768, CC);
    }

    // 4) attention -> bf16 ctx (quad-token blocks: 16x16 group tiles x 4 parities)
    {
        dim3 blk(32, HEADS);
        attn_kernel<<<1024, blk>>>(qq, kq, vq, rpb, ctxp);
    }

    // 5) wo GEMM + residual(x): hs2 = ctx@wo + bo + x  (fp32), BM=64
    {
        dim3 grid(CC/64, NTOK/64);
        bgemm_kernel<2, float, 64><<<grid, 256>>>(ctxp, wo_b, bo, x, hs2,
                                                  nullptr, nullptr, NTOK, CC, CC);
    }

    // 6) LN2 -> bf16
    ln_kernel<<<NTOK/8, 256>>>(hs2, ln2_g, ln2_b, y);

    // 7) w1 GEMM + exact GELU -> bf16 t
    {
        dim3 grid(FF/64, NTOK/128);
        bgemm_kernel<1, __nv_bfloat16, 128><<<grid, 256>>>(y, w1_b, b1, nullptr, t,
                                                           nullptr, nullptr, NTOK, FF, CC);
    }

    // 8) w2 GEMM + residual(hs2): out = t@w2 + b2 + hs2  (fp32), BM=64
    {
        dim3 grid(CC/64, NTOK/64);
        bgemm_kernel<2, float, 64><<<grid, 256>>>(t, w2_b, b2, hs2, out,
                                                  nullptr, nullptr, NTOK, CC, FF);
    }
}

// round 11
// speedup vs baseline: 3.7960x; 1.0910x over previous
#include <cuda_runtime.h>
#include <cuda_bf16.h>
#include <math.h>
#include <stdint.h>

// Problem constants
#define BB 1
#define HH 64
#define WW 64
#define CC 256
#define HEADS 8
#define HD 32
#define KK 7
#define DIL 2
#define FF 1024
#define NTOK (HH*WW)            // 4096
#define SCALE 0.17677669529663687f  // 1/sqrt(32)

// ---------------- scratch (device globals; no runtime alloc) ----------------
__device__ __nv_bfloat16 g_hs [NTOK*CC];     // LN1(x), bf16 (GEMM A)
__device__ float         g_q  [NTOK*CC];     // q fp32, pre-scaled
__device__ __nv_bfloat16 g_k  [NTOK*CC];     // k bf16
__device__ __nv_bfloat16 g_v  [NTOK*CC];     // v bf16
__device__ __nv_bfloat16 g_ctx[NTOK*CC];     // attention context, bf16
__device__ float         g_hs2[NTOK*CC];     // x + attn_out, fp32
__device__ __nv_bfloat16 g_y  [NTOK*CC];     // LN2(hs2), bf16
__device__ __nv_bfloat16 g_t  [NTOK*FF];     // gelu(y@w1+b1), bf16
// bf16 weights, plain [k][n] layout
__device__ __nv_bfloat16 g_wqkv_b[256*768];
__device__ __nv_bfloat16 g_wo_b  [256*256];
__device__ __nv_bfloat16 g_w1_b  [256*1024];
__device__ __nv_bfloat16 g_w2_b  [1024*256];
__device__ float         g_bqkv  [768];

__device__ __forceinline__ float4 ld4(const float* p) {
    return *reinterpret_cast<const float4*>(p);
}
__device__ __forceinline__ float2 bf2f(uint32_t u) {
    __nv_bfloat162 h = *reinterpret_cast<__nv_bfloat162*>(&u);
    return __bfloat1622float2(h);
}
__device__ __forceinline__ float2 ffma2(float2 a, float2 b, float2 c) {
    float2 d;
    asm("fma.rn.f32x2 %0, %1, %2, %3;"
        : "=l"(*reinterpret_cast<uint64_t*>(&d))
        : "l"(*reinterpret_cast<const uint64_t*>(&a)),
          "l"(*reinterpret_cast<const uint64_t*>(&b)),
          "l"(*reinterpret_cast<const uint64_t*>(&c)));
    return d;
}
__device__ __forceinline__ float2 fmul2(float2 a, float2 b) {
    float2 d;
    asm("mul.rn.f32x2 %0, %1, %2;"
        : "=l"(*reinterpret_cast<uint64_t*>(&d))
        : "l"(*reinterpret_cast<const uint64_t*>(&a)),
          "l"(*reinterpret_cast<const uint64_t*>(&b)));
    return d;
}
__device__ __forceinline__ uint32_t smem_u32(const void* p) {
    uint32_t a;
    asm("{ .reg .u64 t; cvta.to.shared.u64 t, %1; cvt.u32.u64 %0, t; }"
        : "=r"(a) : "l"(p));
    return a;
}
__device__ __forceinline__ void ldsm_x4(uint32_t (&r)[4], uint32_t addr) {
    asm volatile("ldmatrix.sync.aligned.m8n8.x4.shared.b16 {%0,%1,%2,%3}, [%4];"
        : "=r"(r[0]), "=r"(r[1]), "=r"(r[2]), "=r"(r[3]) : "r"(addr));
}
__device__ __forceinline__ void ldsm_x4_t(uint32_t (&r)[4], uint32_t addr) {
    asm volatile("ldmatrix.sync.aligned.m8n8.x4.trans.shared.b16 {%0,%1,%2,%3}, [%4];"
        : "=r"(r[0]), "=r"(r[1]), "=r"(r[2]), "=r"(r[3]) : "r"(addr));
}
__device__ __forceinline__ void mma_bf16(float (&d)[4], const uint32_t (&a)[4],
                                         const uint32_t (&b)[2]) {
    asm volatile(
        "mma.sync.aligned.m16n8k16.row.col.f32.bf16.bf16.f32 "
        "{%0,%1,%2,%3}, {%4,%5,%6,%7}, {%8,%9}, {%0,%1,%2,%3};\n"
        : "+f"(d[0]), "+f"(d[1]), "+f"(d[2]), "+f"(d[3])
        : "r"(a[0]), "r"(a[1]), "r"(a[2]), "r"(a[3]),
          "r"(b[0]), "r"(b[1]));
}
__device__ __forceinline__ void cpa16(uint32_t dst, const void* src) {
    asm volatile("cp.async.cg.shared.global [%0], [%1], 16;"
        :: "r"(dst), "l"(src) : "memory");
}
#define CP_COMMIT() asm volatile("cp.async.commit_group;" ::: "memory")
#define CP_WAIT(n)  asm volatile("cp.async.wait_group %0;" :: "n"(n) : "memory")

// ---------------- weight pack: fp32 -> bf16 plain [k][n] ----------------
__global__ void pack_kernel(const float* __restrict__ wq, const float* __restrict__ wk,
                            const float* __restrict__ wv, const float* __restrict__ wo,
                            const float* __restrict__ w1, const float* __restrict__ w2,
                            const float* __restrict__ bq, const float* __restrict__ bk,
                            const float* __restrict__ bv)
{
    int idx = blockIdx.x * 256 + threadIdx.x;
    if (idx < 196608) {                      // wqkv: 256 x 768
        int k = idx / 768, n = idx % 768;
        float v;
        if      (n < 256) v = wq[k*256 + n];
        else if (n < 512) v = wk[k*256 + (n-256)];
        else              v = wv[k*256 + (n-512)];
        g_wqkv_b[idx] = __float2bfloat16(v);
    } else if (idx < 262144) {               // wo: 256 x 256
        int t = idx - 196608;
        g_wo_b[t] = __float2bfloat16(wo[t]);
    } else if (idx < 524288) {               // w1: 256 x 1024
        int t = idx - 262144;
        g_w1_b[t] = __float2bfloat16(w1[t]);
    } else if (idx < 786432) {               // w2: 1024 x 256
        int t = idx - 524288;
        g_w2_b[t] = __float2bfloat16(w2[t]);
    }
    if (idx < 768) {
        float v;
        if      (idx < 256) v = bq[idx];
        else if (idx < 512) v = bk[idx - 256];
        else                v = bv[idx - 512];
        g_bqkv[idx] = v;
    }
}

// ---------------- LayerNorm: one warp per row, 8 rows/block ----------------
__global__ void ln_kernel(const float* __restrict__ x, const float* __restrict__ g,
                          const float* __restrict__ b, __nv_bfloat16* __restrict__ out)
{
    const int row  = blockIdx.x * 8 + (threadIdx.x >> 5);
    const int lane = threadIdx.x & 31;
    const float* xr = x + (size_t)row * CC + lane * 8;
    float4 v0 = ld4(xr), v1 = ld4(xr + 4);
    float s  = v0.x + v0.y + v0.z + v0.w + v1.x + v1.y + v1.z + v1.w;
    float sq = v0.x*v0.x + v0.y*v0.y + v0.z*v0.z + v0.w*v0.w
             + v1.x*v1.x + v1.y*v1.y + v1.z*v1.z + v1.w*v1.w;
    #pragma unroll
    for (int o = 16; o; o >>= 1) {
        s  += __shfl_xor_sync(0xffffffffu, s,  o);
        sq += __shfl_xor_sync(0xffffffffu, sq, o);
    }
    float mean = s * (1.0f/CC);
    float var  = sq * (1.0f/CC) - mean*mean;
    float inv  = rsqrtf(var + 1e-5f);
    float4 g0 = ld4(g + lane*8), g1 = ld4(g + lane*8 + 4);
    float4 b0 = ld4(b + lane*8), b1 = ld4(b + lane*8 + 4);
    __nv_bfloat162 o0 = __floats2bfloat162_rn((v0.x-mean)*inv*g0.x + b0.x,
                                              (v0.y-mean)*inv*g0.y + b0.y);
    __nv_bfloat162 o1 = __floats2bfloat162_rn((v0.z-mean)*inv*g0.z + b0.z,
                                              (v0.w-mean)*inv*g0.w + b0.w);
    __nv_bfloat162 o2 = __floats2bfloat162_rn((v1.x-mean)*inv*g1.x + b1.x,
                                              (v1.y-mean)*inv*g1.y + b1.y);
    __nv_bfloat162 o3 = __floats2bfloat162_rn((v1.z-mean)*inv*g1.z + b1.z,
                                              (v1.w-mean)*inv*g1.w + b1.w);
    uint4 pk = make_uint4(*reinterpret_cast<uint32_t*>(&o0),
                          *reinterpret_cast<uint32_t*>(&o1),
                          *reinterpret_cast<uint32_t*>(&o2),
                          *reinterpret_cast<uint32_t*>(&o3));
    *reinterpret_cast<uint4*>(out + (size_t)row * CC + lane * 8) = pk;
}

// ---------------- bf16 tensor-core GEMM: cp.async 3-stage pipeline ----------
// C[M,N] = A[M,K] @ W[K,N] (+ epilogue). A,W bf16 row-major. fp32 accum.
// BM_ in {128,64}, BN=64, BK=32, 8 warps. 3-stage cp.async; ldmatrix frags.
// TAIL FIX vs R10: iterations that don't issue a real group commit an EMPTY
// group, so wait_group(1) always covers the current tile's copy.
// EPI 0: +bias ; EPI 1: gelu(+bias) ; EPI 2: +bias + res ; EPI 3: qkv split
#define A_STR 20   // uint32 per A row (80B)
#define B_STR 36   // uint32 per B row (144B)
#define NSTG 3

__device__ __forceinline__ void store2(float* p, float v0, float v1) {
    *reinterpret_cast<float2*>(p) = make_float2(v0, v1);
}
__device__ __forceinline__ void store2(__nv_bfloat16* p, float v0, float v1) {
    *reinterpret_cast<__nv_bfloat162*>(p) = __floats2bfloat162_rn(v0, v1);
}

template<int EPI, typename OutT, int BM_>
__global__ void __launch_bounds__(256, 2)
bgemm_kernel(const __nv_bfloat16* __restrict__ A, const __nv_bfloat16* __restrict__ W,
             const float* __restrict__ bias, const float* __restrict__ res,
             OutT* __restrict__ C, __nv_bfloat16* __restrict__ kout,
             __nv_bfloat16* __restrict__ vout, int M, int N, int K)
{
    constexpr int WM = (BM_ == 128) ? 4 : 2;
    constexpr int WN = 8 / WM;
    constexpr int NF = 64 / (WN * 8);
    constexpr uint32_t A_STG = BM_ * A_STR * 4;   // bytes per A stage
    constexpr uint32_t B_STG = 32 * B_STR * 4;    // bytes per B stage

    __shared__ __align__(16) uint32_t As[NSTG][BM_ * A_STR];
    __shared__ __align__(16) uint32_t Bs[NSTG][32 * B_STR];

    const int tid  = threadIdx.x;
    const int lane = tid & 31, warp = tid >> 5;
    const int wm = warp % WM, wn = warp / WM;
    const int g = lane >> 2, c = lane & 3;
    const int bm = blockIdx.y * BM_, bn = blockIdx.x * 64;

    const int arow = (tid >> 1) % BM_, ahalf = (tid & 1);
    const bool aload = (BM_ == 128) || (tid < 128);
    const int bkrow = tid >> 3, bnch = (tid & 7) * 8;
    const __nv_bfloat16* Ag = A + (size_t)(bm + arow) * K + ahalf * 16;
    const __nv_bfloat16* Wg = W + (size_t)bkrow * N + bn + bnch;

    const uint32_t aBase = smem_u32(As);
    const uint32_t bBase = smem_u32(Bs);
    const uint32_t asto = (uint32_t)(arow * A_STR + ahalf * 8) * 4;
    const uint32_t bsto = (uint32_t)(bkrow * B_STR + (tid & 7) * 4) * 4;

    const uint32_t aoff = (uint32_t)(wm*32 + (lane & 15)) * 80 + (lane >> 4) * 16;
    const uint32_t boff = (uint32_t)(lane & 15) * 144 +
                          (uint32_t)(wn*(NF*8) + (lane >> 4)*8) * 2;

    float acc[2][NF][4];
    #pragma unroll
    for (int mf = 0; mf < 2; mf++)
        #pragma unroll
        for (int nf = 0; nf < NF; nf++)
            #pragma unroll
            for (int e = 0; e < 4; e++) acc[mf][nf][e] = 0.f;

    const int NT = K / 32;

    // issue loads for k-tile kt into stage s (one commit group per call)
    auto issue = [&](int kt, int s) {
        if (aload) {
            const __nv_bfloat16* ag = Ag + kt * 32;
            uint32_t d = aBase + (uint32_t)s * A_STG + asto;
            cpa16(d, ag);
            cpa16(d + 16, ag + 8);
        }
        cpa16(bBase + (uint32_t)s * B_STG + bsto, Wg + (size_t)kt * 32 * N);
        CP_COMMIT();
    };

    // prologue: stages 0..NSTG-2
    issue(0, 0);
    issue(1, 1);

    for (int kt = 0; kt < NT; kt++) {
        CP_WAIT(NSTG - 2);
        __syncthreads();
        const int s = kt % NSTG;
        if (kt + NSTG - 1 < NT) {
            issue(kt + NSTG - 1, (kt + NSTG - 1) % NSTG);
        } else {
            CP_COMMIT();   // empty group keeps wait_group invariant at the tail
        }

        const uint32_t ab = aBase + (uint32_t)s * A_STG;
        const uint32_t bb = bBase + (uint32_t)s * B_STG;
        #pragma unroll
        for (int ks = 0; ks < 32; ks += 16) {
            uint32_t af[2][4], bf[NF][2];
            #pragma unroll
            for (int mf = 0; mf < 2; mf++)
                ldsm_x4(af[mf], ab + aoff + (uint32_t)(mf * 16 * 80 + ks * 2));
            #pragma unroll
            for (int p = 0; p < NF/2; p++) {
                uint32_t br[4];
                ldsm_x4_t(br, bb + boff + (uint32_t)(ks * 144 + p * 32));
                bf[2*p][0]   = br[0]; bf[2*p][1]   = br[1];
                bf[2*p+1][0] = br[2]; bf[2*p+1][1] = br[3];
            }
            #pragma unroll
            for (int mf = 0; mf < 2; mf++)
                #pragma unroll
                for (int nf = 0; nf < NF; nf++)
                    mma_bf16(acc[mf][nf], af[mf], bf[nf]);
        }
        __syncthreads();
    }

    #pragma unroll
    for (int mf = 0; mf < 2; mf++) {
        #pragma unroll
        for (int nf = 0; nf < NF; nf++) {
            int row0 = bm + wm * 32 + mf * 16 + g;
            int col  = bn + wn * (NF*8) + nf * 8 + c * 2;
            float bx = bias[col], by = bias[col + 1];
            #pragma unroll
            for (int h = 0; h < 2; h++) {
                int row = row0 + h * 8;
                float v0 = acc[mf][nf][h * 2 + 0] + bx;
                float v1 = acc[mf][nf][h * 2 + 1] + by;
                if (EPI == 1) {
                    v0 *= normcdff(v0);
                    v1 *= normcdff(v1);
                } else if (EPI == 2) {
                    float2 r = *reinterpret_cast<const float2*>(res + (size_t)row * N + col);
                    v0 += r.x; v1 += r.y;
                }
                if (EPI == 3) {
                    if (col < 256) {
                        store2((float*)C + (size_t)row * 256 + col, v0 * SCALE, v1 * SCALE);
                    } else if (col < 512) {
                        store2(kout + (size_t)row * 256 + (col - 256), v0, v1);
                    } else {
                        store2(vout + (size_t)row * 256 + (col - 512), v0, v1);
                    }
                } else {
                    store2(C + (size_t)row * N + col, v0, v1);
                }
            }
        }
    }
}

// ---------------- dilated neighborhood attention: quad-token sharing --------
__global__ void __launch_bounds__(256)
attn_kernel(const float* __restrict__ q, const __nv_bfloat16* __restrict__ k,
            const __nv_bfloat16* __restrict__ v, const float* __restrict__ rpb,
            __nv_bfloat16* __restrict__ ctx)
{
    __shared__ float sc[HEADS][4][64];

    const int head = threadIdx.y;
    const int lane = threadIdx.x;
    const int gg = lane >> 2, e = lane & 3;

    const int b   = blockIdx.x;
    const int bi  = b & 15, bj = (b >> 4) & 15, par = b >> 8;
    const int ri  = par & 1, rj = par >> 1;
    const int gi0 = bi * 2, gj0 = bj * 2;

    int si0 = gi0 - 3; si0 = si0 < 0 ? 0 : (si0 > 25 ? 25 : si0);
    int si1 = gi0 - 2; si1 = si1 < 0 ? 0 : (si1 > 25 ? 25 : si1);
    int sj0 = gj0 - 3; sj0 = sj0 < 0 ? 0 : (sj0 > 25 ? 25 : sj0);
    int sj1 = gj0 - 2; sj1 = sj1 < 0 ? 0 : (sj1 > 25 ? 25 : sj1);
    const int dr1 = si1 - si0, dc1 = sj1 - sj0;

    int sjg = sj0 + gg; sjg = sjg > 31 ? 31 : sjg;
    const int kj = sjg * 2 + rj;
    const int choff = head * HD + e * 8;
    const int kcoff = kj * CC + choff;

    float2 qv[4][4];
    int toks[4];
    #pragma unroll
    for (int a = 0; a < 2; a++) {
        #pragma unroll
        for (int c = 0; c < 2; c++) {
            int tok = (2*(gi0 + a) + ri) * WW + 2*(gj0 + c) + rj;
            int qq_ = a*2 + c;
            toks[qq_] = tok;
            const float* qp = q + (size_t)tok * CC + choff;
            float4 qa = ld4(qp), qb = ld4(qp + 4);
            qv[qq_][0] = make_float2(qa.x, qa.y);
            qv[qq_][1] = make_float2(qa.z, qa.w);
            qv[qq_][2] = make_float2(qb.x, qb.y);
            qv[qq_][3] = make_float2(qb.z, qb.w);
        }
    }

    #pragma unroll
    for (int t = 0; t < 8; t++) {
        int sit = si0 + t; sit = sit > 31 ? 31 : sit;
        const int ki = sit * 2 + ri;
        uint4 u = *reinterpret_cast<const uint4*>(k + ki * (WW*CC) + kcoff);
        float2 k0 = bf2f(u.x), k1 = bf2f(u.y), k2 = bf2f(u.z), k3 = bf2f(u.w);
        #pragma unroll
        for (int qq_ = 0; qq_ < 4; qq_++) {
            float2 p2 = fmul2(qv[qq_][0], k0);
            p2 = ffma2(qv[qq_][1], k1, p2);
            p2 = ffma2(qv[qq_][2], k2, p2);
            p2 = ffma2(qv[qq_][3], k3, p2);
            float pt = p2.x + p2.y;
            pt += __shfl_xor_sync(0xffffffffu, pt, 1);
            pt += __shfl_xor_sync(0xffffffffu, pt, 2);
            if (e == 0) sc[head][qq_][t*8 + gg] = pt;
        }
    }
    __syncwarp();

    const float* br = rpb + head * 169;
    float inv[4];
    #pragma unroll
    for (int qq_ = 0; qq_ < 4; qq_++) {
        const int a = qq_ >> 1, c = qq_ & 1;
        const int dra = a ? dr1 : 0, dcc = c ? dc1 : 0;
        const int Bq = (si0 - gi0 - a + 6) * 13 + (sj0 - gj0 - c + 6);
        float s1, s2;
        {
            int p = lane, pr = p >> 3, pc = p & 7;
            bool val = (pr >= dra) && (pr < dra + 7) && (pc >= dcc) && (pc < dcc + 7);
            s1 = val ? sc[head][qq_][p] + br[Bq + pr*13 + pc] : -1e30f;
        }
        {
            int p = lane + 32, pr = p >> 3, pc = p & 7;
            bool val = (pr >= dra) && (pr < dra + 7) && (pc >= dcc) && (pc < dcc + 7);
            s2 = val ? sc[head][qq_][p] + br[Bq + pr*13 + pc] : -1e30f;
        }
        float m = fmaxf(s1, s2);
        #pragma unroll
        for (int o = 16; o; o >>= 1) m = fmaxf(m, __shfl_xor_sync(0xffffffffu, m, o));
        float e1 = __expf(s1 - m), e2 = __expf(s2 - m);
        float ss = e1 + e2;
        #pragma unroll
        for (int o = 16; o; o >>= 1) ss += __shfl_xor_sync(0xffffffffu, ss, o);
        sc[head][qq_][lane]      = e1;
        sc[head][qq_][lane + 32] = e2;
        inv[qq_] = 1.0f / ss;
    }
    __syncwarp();

    float2 acc[4][4];
    #pragma unroll
    for (int qq_ = 0; qq_ < 4; qq_++)
        #pragma unroll
        for (int i = 0; i < 4; i++) acc[qq_][i] = make_float2(0.f, 0.f);

    #pragma unroll
    for (int t = 0; t < 8; t++) {
        int sit = si0 + t; sit = sit > 31 ? 31 : sit;
        const int ki = sit * 2 + ri;
        uint4 u = *reinterpret_cast<const uint4*>(v + ki * (WW*CC) + kcoff);
        float2 v0 = bf2f(u.x), v1 = bf2f(u.y), v2 = bf2f(u.z), v3 = bf2f(u.w);
        #pragma unroll
        for (int qq_ = 0; qq_ < 4; qq_++) {
            float w = sc[head][qq_][t*8 + gg];
            float2 w2 = make_float2(w, w);
            acc[qq_][0] = ffma2(w2, v0, acc[qq_][0]);
            acc[qq_][1] = ffma2(w2, v1, acc[qq_][1]);
            acc[qq_][2] = ffma2(w2, v2, acc[qq_][2]);
            acc[qq_][3] = ffma2(w2, v3, acc[qq_][3]);
        }
    }

    #pragma unroll
    for (int o = 4; o <= 16; o <<= 1) {
        #pragma unroll
        for (int qq_ = 0; qq_ < 4; qq_++) {
            #pragma unroll
            for (int i = 0; i < 4; i++) {
                acc[qq_][i].x += __shfl_xor_sync(0xffffffffu, acc[qq_][i].x, o);
                acc[qq_][i].y += __shfl_xor_sync(0xffffffffu, acc[qq_][i].y, o);
            }
        }
    }
    if (gg == 0) {
        #pragma unroll
        for (int qq_ = 0; qq_ < 4; qq_++) {
            float iv = inv[qq_];
            __nv_bfloat162 o0 = __floats2bfloat162_rn(acc[qq_][0].x*iv, acc[qq_][0].y*iv);
            __nv_bfloat162 o1 = __floats2bfloat162_rn(acc[qq_][1].x*iv, acc[qq_][1].y*iv);
            __nv_bfloat162 o2 = __floats2bfloat162_rn(acc[qq_][2].x*iv, acc[qq_][2].y*iv);
            __nv_bfloat162 o3 = __floats2bfloat162_rn(acc[qq_][3].x*iv, acc[qq_][3].y*iv);
            uint4 pk = make_uint4(*reinterpret_cast<uint32_t*>(&o0),
                                  *reinterpret_cast<uint32_t*>(&o1),
                                  *reinterpret_cast<uint32_t*>(&o2),
                                  *reinterpret_cast<uint32_t*>(&o3));
            *reinterpret_cast<uint4*>(ctx + (size_t)toks[qq_]*CC + choff) = pk;
        }
    }
}

// ---------------- launch ----------------
extern "C" void kernel_launch(void* const* d_in, const int* in_sizes, int n_in,
                              void* d_out, int out_size)
{
    const float* x     = (const float*)d_in[0];
    const float* ln1_g = (const float*)d_in[1];
    const float* ln1_b = (const float*)d_in[2];
    const float* wq    = (const float*)d_in[3];
    const float* bq    = (const float*)d_in[4];
    const float* wk    = (const float*)d_in[5];
    const float* bk    = (const float*)d_in[6];
    const float* wv    = (const float*)d_in[7];
    const float* bv    = (const float*)d_in[8];
    const float* rpb   = (const float*)d_in[9];
    const float* wo    = (const float*)d_in[10];
    const float* bo    = (const float*)d_in[11];
    const float* ln2_g = (const float*)d_in[12];
    const float* ln2_b = (const float*)d_in[13];
    const float* w1    = (const float*)d_in[14];
    const float* b1    = (const float*)d_in[15];
    const float* w2    = (const float*)d_in[16];
    const float* b2    = (const float*)d_in[17];
    float* out = (float*)d_out;

    __nv_bfloat16 *hs, *kq, *vq, *ctxp, *y, *t;
    __nv_bfloat16 *wqkv_b, *wo_b, *w1_b, *w2_b;
    float *qq, *hs2, *bqkv;
    cudaGetSymbolAddress((void**)&hs,     g_hs);
    cudaGetSymbolAddress((void**)&qq,     g_q);
    cudaGetSymbolAddress((void**)&kq,     g_k);
    cudaGetSymbolAddress((void**)&vq,     g_v);
    cudaGetSymbolAddress((void**)&ctxp,   g_ctx);
    cudaGetSymbolAddress((void**)&hs2,    g_hs2);
    cudaGetSymbolAddress((void**)&y,      g_y);
    cudaGetSymbolAddress((void**)&t,      g_t);
    cudaGetSymbolAddress((void**)&wqkv_b, g_wqkv_b);
    cudaGetSymbolAddress((void**)&wo_b,   g_wo_b);
    cudaGetSymbolAddress((void**)&w1_b,   g_w1_b);
    cudaGetSymbolAddress((void**)&w2_b,   g_w2_b);
    cudaGetSymbolAddress((void**)&bqkv,   g_bqkv);

    // 1) pack weights to bf16
    pack_kernel<<<3072, 256>>>(wq, wk, wv, wo, w1, w2, bq, bk, bv);

    // 2) LN1 -> bf16
    ln_kernel<<<NTOK/8, 256>>>(x, ln1_g, ln1_b, hs);

    // 3) QKV GEMM: [4096,256] @ [256,768] -> q fp32(scaled) | k bf16 | v bf16
    {
        dim3 grid(768/64, NTOK/128);
        bgemm_kernel<3, float, 128><<<grid, 256>>>(hs, wqkv_b, bqkv, nullptr, qq,
                                                   kq, vq, NTOK, 768, CC);
    }

    // 4) attention -> bf16 ctx (quad-token blocks)
    {
        dim3 blk(32, HEADS);
        attn_kernel<<<1024, blk>>>(qq, kq, vq, rpb, ctxp);
    }

    // 5) wo GEMM + residual(x): hs2 = ctx@wo + bo + x  (fp32), BM=64
    {
        dim3 grid(CC/64, NTOK/64);
        bgemm_kernel<2, float, 64><<<grid, 256>>>(ctxp, wo_b, bo, x, hs2,
                                                  nullptr, nullptr, NTOK, CC, CC);
    }

    // 6) LN2 -> bf16
    ln_kernel<<<NTOK/8, 256>>>(hs2, ln2_g, ln2_b, y);

    // 7) w1 GEMM + exact GELU -> bf16 t
    {
        dim3 grid(FF/64, NTOK/128);
        bgemm_kernel<1, __nv_bfloat16, 128><<<grid, 256>>>(y, w1_b, b1, nullptr, t,
                                                           nullptr, nullptr, NTOK, FF, CC);
    }

    // 8) w2 GEMM + residual(hs2): out = t@w2 + b2 + hs2  (fp32), BM=64
    {
        dim3 grid(CC/64, NTOK/64);
        bgemm_kernel<2, float, 64><<<grid, 256>>>(t, w2_b, b2, hs2, out,
                                                  nullptr, nullptr, NTOK, CC, FF);
    }
}

// round 12
// speedup vs baseline: 3.9709x; 1.0461x over previous
#include <cuda_runtime.h>
#include <cuda_bf16.h>
#include <math.h>
#include <stdint.h>

// Problem constants
#define BB 1
#define HH 64
#define WW 64
#define CC 256
#define HEADS 8
#define HD 32
#define KK 7
#define DIL 2
#define FF 1024
#define NTOK (HH*WW)            // 4096
#define SCALE 0.17677669529663687f  // 1/sqrt(32)

// ---------------- scratch (device globals; no runtime alloc) ----------------
__device__ __nv_bfloat16 g_hs [NTOK*CC];     // LN1(x), bf16 (GEMM A)
__device__ float         g_q  [NTOK*CC];     // q fp32, pre-scaled
__device__ __nv_bfloat16 g_k  [NTOK*CC];     // k bf16
__device__ __nv_bfloat16 g_v  [NTOK*CC];     // v bf16
__device__ __nv_bfloat16 g_ctx[NTOK*CC];     // attention context, bf16
__device__ float         g_hs2[NTOK*CC];     // x + attn_out, fp32
__device__ __nv_bfloat16 g_y  [NTOK*CC];     // LN2(hs2), bf16
__device__ __nv_bfloat16 g_t  [NTOK*FF];     // gelu(y@w1+b1), bf16
// bf16 weights, plain [k][n] layout
__device__ __nv_bfloat16 g_wqkv_b[256*768];
__device__ __nv_bfloat16 g_wo_b  [256*256];
__device__ __nv_bfloat16 g_w1_b  [256*1024];
__device__ __nv_bfloat16 g_w2_b  [1024*256];
__device__ float         g_bqkv  [768];

__device__ __forceinline__ float4 ld4(const float* p) {
    return *reinterpret_cast<const float4*>(p);
}
__device__ __forceinline__ float2 bf2f(uint32_t u) {
    __nv_bfloat162 h = *reinterpret_cast<__nv_bfloat162*>(&u);
    return __bfloat1622float2(h);
}
__device__ __forceinline__ float2 ffma2(float2 a, float2 b, float2 c) {
    float2 d;
    asm("fma.rn.f32x2 %0, %1, %2, %3;"
        : "=l"(*reinterpret_cast<uint64_t*>(&d))
        : "l"(*reinterpret_cast<const uint64_t*>(&a)),
          "l"(*reinterpret_cast<const uint64_t*>(&b)),
          "l"(*reinterpret_cast<const uint64_t*>(&c)));
    return d;
}
__device__ __forceinline__ float2 fmul2(float2 a, float2 b) {
    float2 d;
    asm("mul.rn.f32x2 %0, %1, %2;"
        : "=l"(*reinterpret_cast<uint64_t*>(&d))
        : "l"(*reinterpret_cast<const uint64_t*>(&a)),
          "l"(*reinterpret_cast<const uint64_t*>(&b)));
    return d;
}
__device__ __forceinline__ uint32_t smem_u32(const void* p) {
    uint32_t a;
    asm("{ .reg .u64 t; cvta.to.shared.u64 t, %1; cvt.u32.u64 %0, t; }"
        : "=r"(a) : "l"(p));
    return a;
}
__device__ __forceinline__ void ldsm_x4(uint32_t (&r)[4], uint32_t addr) {
    asm volatile("ldmatrix.sync.aligned.m8n8.x4.shared.b16 {%0,%1,%2,%3}, [%4];"
        : "=r"(r[0]), "=r"(r[1]), "=r"(r[2]), "=r"(r[3]) : "r"(addr));
}
__device__ __forceinline__ void ldsm_x4_t(uint32_t (&r)[4], uint32_t addr) {
    asm volatile("ldmatrix.sync.aligned.m8n8.x4.trans.shared.b16 {%0,%1,%2,%3}, [%4];"
        : "=r"(r[0]), "=r"(r[1]), "=r"(r[2]), "=r"(r[3]) : "r"(addr));
}
__device__ __forceinline__ void mma_bf16(float (&d)[4], const uint32_t (&a)[4],
                                         const uint32_t (&b)[2]) {
    asm volatile(
        "mma.sync.aligned.m16n8k16.row.col.f32.bf16.bf16.f32 "
        "{%0,%1,%2,%3}, {%4,%5,%6,%7}, {%8,%9}, {%0,%1,%2,%3};\n"
        : "+f"(d[0]), "+f"(d[1]), "+f"(d[2]), "+f"(d[3])
        : "r"(a[0]), "r"(a[1]), "r"(a[2]), "r"(a[3]),
          "r"(b[0]), "r"(b[1]));
}
__device__ __forceinline__ void cpa16(uint32_t dst, const void* src) {
    asm volatile("cp.async.cg.shared.global [%0], [%1], 16;"
        :: "r"(dst), "l"(src) : "memory");
}
#define CP_COMMIT() asm volatile("cp.async.commit_group;" ::: "memory")
#define CP_WAIT(n)  asm volatile("cp.async.wait_group %0;" :: "n"(n) : "memory")

// ---------------- weight pack: fp32 -> bf16 plain [k][n], vectorized --------
__device__ __forceinline__ uint2 f4_to_bf4(float4 v) {
    __nv_bfloat162 h0 = __floats2bfloat162_rn(v.x, v.y);
    __nv_bfloat162 h1 = __floats2bfloat162_rn(v.z, v.w);
    return make_uint2(*reinterpret_cast<uint32_t*>(&h0),
                      *reinterpret_cast<uint32_t*>(&h1));
}

__global__ void pack_kernel(const float* __restrict__ wq, const float* __restrict__ wk,
                            const float* __restrict__ wv, const float* __restrict__ wo,
                            const float* __restrict__ w1, const float* __restrict__ w2,
                            const float* __restrict__ bq, const float* __restrict__ bk,
                            const float* __restrict__ bv)
{
    int i4 = blockIdx.x * 256 + threadIdx.x;     // vector (4-elem) index
    if (i4 < 49152) {                            // wqkv: 256x768
        int idx = i4 * 4;
        int k = idx / 768, n = idx % 768;
        const float* W; int nn;
        if      (n < 256) { W = wq; nn = n; }
        else if (n < 512) { W = wk; nn = n - 256; }
        else              { W = wv; nn = n - 512; }
        float4 v = ld4(W + (size_t)k * 256 + nn);
        *reinterpret_cast<uint2*>(g_wqkv_b + idx) = f4_to_bf4(v);
    } else if (i4 < 65536) {                     // wo: 65536 elems
        int t = (i4 - 49152) * 4;
        *reinterpret_cast<uint2*>(g_wo_b + t) = f4_to_bf4(ld4(wo + t));
    } else if (i4 < 131072) {                    // w1: 262144 elems
        int t = (i4 - 65536) * 4;
        *reinterpret_cast<uint2*>(g_w1_b + t) = f4_to_bf4(ld4(w1 + t));
    } else if (i4 < 196608) {                    // w2: 262144 elems
        int t = (i4 - 131072) * 4;
        *reinterpret_cast<uint2*>(g_w2_b + t) = f4_to_bf4(ld4(w2 + t));
    }
    if (i4 < 768) {
        float v;
        if      (i4 < 256) v = bq[i4];
        else if (i4 < 512) v = bk[i4 - 256];
        else               v = bv[i4 - 512];
        g_bqkv[i4] = v;
    }
}

// ---------------- LayerNorm: one warp per row, 8 rows/block ----------------
__global__ void ln_kernel(const float* __restrict__ x, const float* __restrict__ g,
                          const float* __restrict__ b, __nv_bfloat16* __restrict__ out)
{
    const int row  = blockIdx.x * 8 + (threadIdx.x >> 5);
    const int lane = threadIdx.x & 31;
    const float* xr = x + (size_t)row * CC + lane * 8;
    float4 v0 = ld4(xr), v1 = ld4(xr + 4);
    float s  = v0.x + v0.y + v0.z + v0.w + v1.x + v1.y + v1.z + v1.w;
    float sq = v0.x*v0.x + v0.y*v0.y + v0.z*v0.z + v0.w*v0.w
             + v1.x*v1.x + v1.y*v1.y + v1.z*v1.z + v1.w*v1.w;
    #pragma unroll
    for (int o = 16; o; o >>= 1) {
        s  += __shfl_xor_sync(0xffffffffu, s,  o);
        sq += __shfl_xor_sync(0xffffffffu, sq, o);
    }
    float mean = s * (1.0f/CC);
    float var  = sq * (1.0f/CC) - mean*mean;
    float inv  = rsqrtf(var + 1e-5f);
    float4 g0 = ld4(g + lane*8), g1 = ld4(g + lane*8 + 4);
    float4 b0 = ld4(b + lane*8), b1 = ld4(b + lane*8 + 4);
    __nv_bfloat162 o0 = __floats2bfloat162_rn((v0.x-mean)*inv*g0.x + b0.x,
                                              (v0.y-mean)*inv*g0.y + b0.y);
    __nv_bfloat162 o1 = __floats2bfloat162_rn((v0.z-mean)*inv*g0.z + b0.z,
                                              (v0.w-mean)*inv*g0.w + b0.w);
    __nv_bfloat162 o2 = __floats2bfloat162_rn((v1.x-mean)*inv*g1.x + b1.x,
                                              (v1.y-mean)*inv*g1.y + b1.y);
    __nv_bfloat162 o3 = __floats2bfloat162_rn((v1.z-mean)*inv*g1.z + b1.z,
                                              (v1.w-mean)*inv*g1.w + b1.w);
    uint4 pk = make_uint4(*reinterpret_cast<uint32_t*>(&o0),
                          *reinterpret_cast<uint32_t*>(&o1),
                          *reinterpret_cast<uint32_t*>(&o2),
                          *reinterpret_cast<uint32_t*>(&o3));
    *reinterpret_cast<uint4*>(out + (size_t)row * CC + lane * 8) = pk;
}

// ---------------- bf16 tensor-core GEMM: cp.async 3-stage pipeline ----------
// BM64 tiles everywhere: 2Mx4N warps, warp 32x16 (2x2 frags), minctas=3.
// One __syncthreads per k-tile (top barrier also orders stage reuse).
// Tail: empty commit groups keep the wait_group(1) invariant.
// EPI 1: gelu(+bias) ; EPI 2: +bias + res ; EPI 3: qkv split
#define A_STR 20   // uint32 per A row (80B)
#define B_STR 36   // uint32 per B row (144B)
#define NSTG 3
#define BMT 64

__device__ __forceinline__ void store2(float* p, float v0, float v1) {
    *reinterpret_cast<float2*>(p) = make_float2(v0, v1);
}
__device__ __forceinline__ void store2(__nv_bfloat16* p, float v0, float v1) {
    *reinterpret_cast<__nv_bfloat162*>(p) = __floats2bfloat162_rn(v0, v1);
}

template<int EPI, typename OutT>
__global__ void __launch_bounds__(256, 3)
bgemm_kernel(const __nv_bfloat16* __restrict__ A, const __nv_bfloat16* __restrict__ W,
             const float* __restrict__ bias, const float* __restrict__ res,
             OutT* __restrict__ C, __nv_bfloat16* __restrict__ kout,
             __nv_bfloat16* __restrict__ vout, int M, int N, int K)
{
    constexpr int WM = 2, WN = 4, NF = 2;
    constexpr uint32_t A_STG = BMT * A_STR * 4;
    constexpr uint32_t B_STG = 32 * B_STR * 4;

    __shared__ __align__(16) uint32_t As[NSTG][BMT * A_STR];
    __shared__ __align__(16) uint32_t Bs[NSTG][32 * B_STR];

    const int tid  = threadIdx.x;
    const int lane = tid & 31, warp = tid >> 5;
    const int wm = warp % WM, wn = warp / WM;
    const int g = lane >> 2, c = lane & 3;
    const int bm = blockIdx.y * BMT, bn = blockIdx.x * 64;

    const int arow = (tid >> 1) & 63, ahalf = (tid & 1);
    const bool aload = (tid < 128);
    const int bkrow = tid >> 3, bnch = (tid & 7) * 8;
    const __nv_bfloat16* Ag = A + (size_t)(bm + arow) * K + ahalf * 16;
    const __nv_bfloat16* Wg = W + (size_t)bkrow * N + bn + bnch;

    const uint32_t aBase = smem_u32(As);
    const uint32_t bBase = smem_u32(Bs);
    const uint32_t asto = (uint32_t)(arow * A_STR + ahalf * 8) * 4;
    const uint32_t bsto = (uint32_t)(bkrow * B_STR + (tid & 7) * 4) * 4;

    const uint32_t aoff = (uint32_t)(wm*32 + (lane & 15)) * 80 + (lane >> 4) * 16;
    const uint32_t boff = (uint32_t)(lane & 15) * 144 +
                          (uint32_t)(wn*(NF*8) + (lane >> 4)*8) * 2;

    float acc[2][NF][4];
    #pragma unroll
    for (int mf = 0; mf < 2; mf++)
        #pragma unroll
        for (int nf = 0; nf < NF; nf++)
            #pragma unroll
            for (int e = 0; e < 4; e++) acc[mf][nf][e] = 0.f;

    const int NT = K / 32;

    auto issue = [&](int kt, int s) {
        if (aload) {
            const __nv_bfloat16* ag = Ag + kt * 32;
            uint32_t d = aBase + (uint32_t)s * A_STG + asto;
            cpa16(d, ag);
            cpa16(d + 16, ag + 8);
        }
        cpa16(bBase + (uint32_t)s * B_STG + bsto, Wg + (size_t)kt * 32 * N);
        CP_COMMIT();
    };

    issue(0, 0);
    issue(1, 1);

    for (int kt = 0; kt < NT; kt++) {
        CP_WAIT(NSTG - 2);
        __syncthreads();
        const int s = kt % NSTG;
        if (kt + NSTG - 1 < NT) {
            issue(kt + NSTG - 1, (kt + NSTG - 1) % NSTG);
        } else {
            CP_COMMIT();   // empty group keeps wait_group invariant at the tail
        }

        const uint32_t ab = aBase + (uint32_t)s * A_STG;
        const uint32_t bb = bBase + (uint32_t)s * B_STG;
        #pragma unroll
        for (int ks = 0; ks < 32; ks += 16) {
            uint32_t af[2][4], bf[NF][2];
            #pragma unroll
            for (int mf = 0; mf < 2; mf++)
                ldsm_x4(af[mf], ab + aoff + (uint32_t)(mf * 16 * 80 + ks * 2));
            {
                uint32_t br[4];
                ldsm_x4_t(br, bb + boff + (uint32_t)(ks * 144));
                bf[0][0] = br[0]; bf[0][1] = br[1];
                bf[1][0] = br[2]; bf[1][1] = br[3];
            }
            #pragma unroll
            for (int mf = 0; mf < 2; mf++)
                #pragma unroll
                for (int nf = 0; nf < NF; nf++)
                    mma_bf16(acc[mf][nf], af[mf], bf[nf]);
        }
    }
    __syncthreads();   // all reads done before block exit (paranoia for reuse)

    #pragma unroll
    for (int mf = 0; mf < 2; mf++) {
        #pragma unroll
        for (int nf = 0; nf < NF; nf++) {
            int row0 = bm + wm * 32 + mf * 16 + g;
            int col  = bn + wn * (NF*8) + nf * 8 + c * 2;
            float bx = bias[col], by = bias[col + 1];
            #pragma unroll
            for (int h = 0; h < 2; h++) {
                int row = row0 + h * 8;
                float v0 = acc[mf][nf][h * 2 + 0] + bx;
                float v1 = acc[mf][nf][h * 2 + 1] + by;
                if (EPI == 1) {
                    v0 *= normcdff(v0);
                    v1 *= normcdff(v1);
                } else if (EPI == 2) {
                    float2 r = *reinterpret_cast<const float2*>(res + (size_t)row * N + col);
                    v0 += r.x; v1 += r.y;
                }
                if (EPI == 3) {
                    if (col < 256) {
                        store2((float*)C + (size_t)row * 256 + col, v0 * SCALE, v1 * SCALE);
                    } else if (col < 512) {
                        store2(kout + (size_t)row * 256 + (col - 256), v0, v1);
                    } else {
                        store2(vout + (size_t)row * 256 + (col - 512), v0, v1);
                    }
                } else {
                    store2(C + (size_t)row * N + col, v0, v1);
                }
            }
        }
    }
}

// ---------------- dilated neighborhood attention: quad-token sharing --------
__global__ void __launch_bounds__(256)
attn_kernel(const float* __restrict__ q, const __nv_bfloat16* __restrict__ k,
            const __nv_bfloat16* __restrict__ v, const float* __restrict__ rpb,
            __nv_bfloat16* __restrict__ ctx)
{
    __shared__ float sc[HEADS][4][64];

    const int head = threadIdx.y;
    const int lane = threadIdx.x;
    const int gg = lane >> 2, e = lane & 3;

    const int b   = blockIdx.x;
    const int bi  = b & 15, bj = (b >> 4) & 15, par = b >> 8;
    const int ri  = par & 1, rj = par >> 1;
    const int gi0 = bi * 2, gj0 = bj * 2;

    int si0 = gi0 - 3; si0 = si0 < 0 ? 0 : (si0 > 25 ? 25 : si0);
    int si1 = gi0 - 2; si1 = si1 < 0 ? 0 : (si1 > 25 ? 25 : si1);
    int sj0 = gj0 - 3; sj0 = sj0 < 0 ? 0 : (sj0 > 25 ? 25 : sj0);
    int sj1 = gj0 - 2; sj1 = sj1 < 0 ? 0 : (sj1 > 25 ? 25 : sj1);
    const int dr1 = si1 - si0, dc1 = sj1 - sj0;

    int sjg = sj0 + gg; sjg = sjg > 31 ? 31 : sjg;
    const int kj = sjg * 2 + rj;
    const int choff = head * HD + e * 8;
    const int kcoff = kj * CC + choff;

    float2 qv[4][4];
    int toks[4];
    #pragma unroll
    for (int a = 0; a < 2; a++) {
        #pragma unroll
        for (int c = 0; c < 2; c++) {
            int tok = (2*(gi0 + a) + ri) * WW + 2*(gj0 + c) + rj;
            int qq_ = a*2 + c;
            toks[qq_] = tok;
            const float* qp = q + (size_t)tok * CC + choff;
            float4 qa = ld4(qp), qb = ld4(qp + 4);
            qv[qq_][0] = make_float2(qa.x, qa.y);
            qv[qq_][1] = make_float2(qa.z, qa.w);
            qv[qq_][2] = make_float2(qb.x, qb.y);
            qv[qq_][3] = make_float2(qb.z, qb.w);
        }
    }

    #pragma unroll
    for (int t = 0; t < 8; t++) {
        int sit = si0 + t; sit = sit > 31 ? 31 : sit;
        const int ki = sit * 2 + ri;
        uint4 u = *reinterpret_cast<const uint4*>(k + ki * (WW*CC) + kcoff);
        float2 k0 = bf2f(u.x), k1 = bf2f(u.y), k2 = bf2f(u.z), k3 = bf2f(u.w);
        #pragma unroll
        for (int qq_ = 0; qq_ < 4; qq_++) {
            float2 p2 = fmul2(qv[qq_][0], k0);
            p2 = ffma2(qv[qq_][1], k1, p2);
            p2 = ffma2(qv[qq_][2], k2, p2);
            p2 = ffma2(qv[qq_][3], k3, p2);
            float pt = p2.x + p2.y;
            pt += __shfl_xor_sync(0xffffffffu, pt, 1);
            pt += __shfl_xor_sync(0xffffffffu, pt, 2);
            if (e == 0) sc[head][qq_][t*8 + gg] = pt;
        }
    }
    __syncwarp();

    const float* br = rpb + head * 169;
    float inv[4];
    #pragma unroll
    for (int qq_ = 0; qq_ < 4; qq_++) {
        const int a = qq_ >> 1, c = qq_ & 1;
        const int dra = a ? dr1 : 0, dcc = c ? dc1 : 0;
        const int Bq = (si0 - gi0 - a + 6) * 13 + (sj0 - gj0 - c + 6);
        float s1, s2;
        {
            int p = lane, pr = p >> 3, pc = p & 7;
            bool val = (pr >= dra) && (pr < dra + 7) && (pc >= dcc) && (pc < dcc + 7);
            s1 = val ? sc[head][qq_][p] + br[Bq + pr*13 + pc] : -1e30f;
        }
        {
            int p = lane + 32, pr = p >> 3, pc = p & 7;
            bool val = (pr >= dra) && (pr < dra + 7) && (pc >= dcc) && (pc < dcc + 7);
            s2 = val ? sc[head][qq_][p] + br[Bq + pr*13 + pc] : -1e30f;
        }
        float m = fmaxf(s1, s2);
        #pragma unroll
        for (int o = 16; o; o >>= 1) m = fmaxf(m, __shfl_xor_sync(0xffffffffu, m, o));
        float e1 = __expf(s1 - m), e2 = __expf(s2 - m);
        float ss = e1 + e2;
        #pragma unroll
        for (int o = 16; o; o >>= 1) ss += __shfl_xor_sync(0xffffffffu, ss, o);
        sc[head][qq_][lane]      = e1;
        sc[head][qq_][lane + 32] = e2;
        inv[qq_] = 1.0f / ss;
    }
    __syncwarp();

    float2 acc[4][4];
    #pragma unroll
    for (int qq_ = 0; qq_ < 4; qq_++)
        #pragma unroll
        for (int i = 0; i < 4; i++) acc[qq_][i] = make_float2(0.f, 0.f);

    #pragma unroll
    for (int t = 0; t < 8; t++) {
        int sit = si0 + t; sit = sit > 31 ? 31 : sit;
        const int ki = sit * 2 + ri;
        uint4 u = *reinterpret_cast<const uint4*>(v + ki * (WW*CC) + kcoff);
        float2 v0 = bf2f(u.x), v1 = bf2f(u.y), v2 = bf2f(u.z), v3 = bf2f(u.w);
        #pragma unroll
        for (int qq_ = 0; qq_ < 4; qq_++) {
            float w = sc[head][qq_][t*8 + gg];
            float2 w2 = make_float2(w, w);
            acc[qq_][0] = ffma2(w2, v0, acc[qq_][0]);
            acc[qq_][1] = ffma2(w2, v1, acc[qq_][1]);
            acc[qq_][2] = ffma2(w2, v2, acc[qq_][2]);
            acc[qq_][3] = ffma2(w2, v3, acc[qq_][3]);
        }
    }

    #pragma unroll
    for (int o = 4; o <= 16; o <<= 1) {
        #pragma unroll
        for (int qq_ = 0; qq_ < 4; qq_++) {
            #pragma unroll
            for (int i = 0; i < 4; i++) {
                acc[qq_][i].x += __shfl_xor_sync(0xffffffffu, acc[qq_][i].x, o);
                acc[qq_][i].y += __shfl_xor_sync(0xffffffffu, acc[qq_][i].y, o);
            }
        }
    }
    if (gg == 0) {
        #pragma unroll
        for (int qq_ = 0; qq_ < 4; qq_++) {
            float iv = inv[qq_];
            __nv_bfloat162 o0 = __floats2bfloat162_rn(acc[qq_][0].x*iv, acc[qq_][0].y*iv);
            __nv_bfloat162 o1 = __floats2bfloat162_rn(acc[qq_][1].x*iv, acc[qq_][1].y*iv);
            __nv_bfloat162 o2 = __floats2bfloat162_rn(acc[qq_][2].x*iv, acc[qq_][2].y*iv);
            __nv_bfloat162 o3 = __floats2bfloat162_rn(acc[qq_][3].x*iv, acc[qq_][3].y*iv);
            uint4 pk = make_uint4(*reinterpret_cast<uint32_t*>(&o0),
                                  *reinterpret_cast<uint32_t*>(&o1),
                                  *reinterpret_cast<uint32_t*>(&o2),
                                  *reinterpret_cast<uint32_t*>(&o3));
            *reinterpret_cast<uint4*>(ctx + (size_t)toks[qq_]*CC + choff) = pk;
        }
    }
}

// ---------------- launch ----------------
extern "C" void kernel_launch(void* const* d_in, const int* in_sizes, int n_in,
                              void* d_out, int out_size)
{
    const float* x     = (const float*)d_in[0];
    const float* ln1_g = (const float*)d_in[1];
    const float* ln1_b = (const float*)d_in[2];
    const float* wq    = (const float*)d_in[3];
    const float* bq    = (const float*)d_in[4];
    const float* wk    = (const float*)d_in[5];
    const float* bk    = (const float*)d_in[6];
    const float* wv    = (const float*)d_in[7];
    const float* bv    = (const float*)d_in[8];
    const float* rpb   = (const float*)d_in[9];
    const float* wo    = (const float*)d_in[10];
    const float* bo    = (const float*)d_in[11];
    const float* ln2_g = (const float*)d_in[12];
    const float* ln2_b = (const float*)d_in[13];
    const float* w1    = (const float*)d_in[14];
    const float* b1    = (const float*)d_in[15];
    const float* w2    = (const float*)d_in[16];
    const float* b2    = (const float*)d_in[17];
    float* out = (float*)d_out;

    __nv_bfloat16 *hs, *kq, *vq, *ctxp, *y, *t;
    __nv_bfloat16 *wqkv_b, *wo_b, *w1_b, *w2_b;
    float *qq, *hs2, *bqkv;
    cudaGetSymbolAddress((void**)&hs,     g_hs);
    cudaGetSymbolAddress((void**)&qq,     g_q);
    cudaGetSymbolAddress((void**)&kq,     g_k);
    cudaGetSymbolAddress((void**)&vq,     g_v);
    cudaGetSymbolAddress((void**)&ctxp,   g_ctx);
    cudaGetSymbolAddress((void**)&hs2,    g_hs2);
    cudaGetSymbolAddress((void**)&y,      g_y);
    cudaGetSymbolAddress((void**)&t,      g_t);
    cudaGetSymbolAddress((void**)&wqkv_b, g_wqkv_b);
    cudaGetSymbolAddress((void**)&wo_b,   g_wo_b);
    cudaGetSymbolAddress((void**)&w1_b,   g_w1_b);
    cudaGetSymbolAddress((void**)&w2_b,   g_w2_b);
    cudaGetSymbolAddress((void**)&bqkv,   g_bqkv);

    // 1) pack weights to bf16 (vectorized)
    pack_kernel<<<768, 256>>>(wq, wk, wv, wo, w1, w2, bq, bk, bv);

    // 2) LN1 -> bf16
    ln_kernel<<<NTOK/8, 256>>>(x, ln1_g, ln1_b, hs);

    // 3) QKV GEMM: [4096,256] @ [256,768] -> q fp32(scaled) | k bf16 | v bf16
    {
        dim3 grid(768/64, NTOK/64);
        bgemm_kernel<3, float><<<grid, 256>>>(hs, wqkv_b, bqkv, nullptr, qq,
                                              kq, vq, NTOK, 768, CC);
    }

    // 4) attention -> bf16 ctx (quad-token blocks)
    {
        dim3 blk(32, HEADS);
        attn_kernel<<<1024, blk>>>(qq, kq, vq, rpb, ctxp);
    }

    // 5) wo GEMM + residual(x): hs2 = ctx@wo + bo + x  (fp32)
    {
        dim3 grid(CC/64, NTOK/64);
        bgemm_kernel<2, float><<<grid, 256>>>(ctxp, wo_b, bo, x, hs2,
                                              nullptr, nullptr, NTOK, CC, CC);
    }

    // 6) LN2 -> bf16
    ln_kernel<<<NTOK/8, 256>>>(hs2, ln2_g, ln2_b, y);

    // 7) w1 GEMM + exact GELU -> bf16 t
    {
        dim3 grid(FF/64, NTOK/64);
        bgemm_kernel<1, __nv_bfloat16><<<grid, 256>>>(y, w1_b, b1, nullptr, t,
                                                      nullptr, nullptr, NTOK, FF, CC);
    }

    // 8) w2 GEMM + residual(hs2): out = t@w2 + b2 + hs2  (fp32)
    {
        dim3 grid(CC/64, NTOK/64);
        bgemm_kernel<2, float><<<grid, 256>>>(t, w2_b, b2, hs2, out,
                                              nullptr, nullptr, NTOK, CC, FF);
    }
}